// round 1
// baseline (speedup 1.0000x reference)
#include <cuda_runtime.h>
#include <cuda_bf16.h>
#include <cstdint>

#define TT 12
#define NN 10000
#define EE 160000
#define C1 32
#define CH 64
#define CO 32

// ---------------- device scratch (no allocations allowed) ----------------
__device__ float g_xw1[TT * NN * CH];   // layer1 h@W  [T,N,64]
__device__ float g_agg1[TT * NN * CH];  // layer1 GCN output [T,N,64]
__device__ float g_xs2[NN * CH];        // mean_t(h2) @ W2  [N,64]
__device__ float g_deg[NN];
__device__ float g_dis[NN];
__device__ int   g_cnt[NN];
__device__ int   g_fill[NN];
__device__ int   g_rowptr[NN + 1];
__device__ int   g_csrc[EE];
__device__ float g_cnorm[EE];

// ---------------- graph preprocessing ----------------
__global__ void k_zero() {
    int i = blockIdx.x * blockDim.x + threadIdx.x;
    if (i < NN) { g_deg[i] = 0.f; g_cnt[i] = 0; g_fill[i] = 0; }
}

__global__ void k_edge_hist(const int* __restrict__ ei, const float* __restrict__ ew) {
    int e = blockIdx.x * blockDim.x + threadIdx.x;
    if (e >= EE) return;
    int d = ei[EE + e];
    atomicAdd(&g_deg[d], ew[e]);
    atomicAdd(&g_cnt[d], 1);
}

__global__ void k_dis() {
    int i = blockIdx.x * blockDim.x + threadIdx.x;
    if (i < NN) g_dis[i] = rsqrtf(g_deg[i] + 1.0f);
}

// single-block scan over g_cnt -> g_rowptr (exclusive), rowptr[NN] = total
__global__ void k_scan() {
    __shared__ int s[1024];
    const int per = (NN + 1023) / 1024;  // 10
    int tid = threadIdx.x;
    int vals[16];
    int start = tid * per;
    int local = 0;
    for (int k = 0; k < per; k++) {
        int idx = start + k;
        int v = (idx < NN) ? g_cnt[idx] : 0;
        vals[k] = v; local += v;
    }
    s[tid] = local;
    __syncthreads();
    for (int off = 1; off < 1024; off <<= 1) {
        int v = (tid >= off) ? s[tid - off] : 0;
        __syncthreads();
        s[tid] += v;
        __syncthreads();
    }
    int run = (tid > 0) ? s[tid - 1] : 0;
    for (int k = 0; k < per; k++) {
        int idx = start + k;
        if (idx < NN) g_rowptr[idx] = run;
        run += vals[k];
    }
    if (tid == 1023) g_rowptr[NN] = s[1023];
}

__global__ void k_scatter(const int* __restrict__ ei, const float* __restrict__ ew) {
    int e = blockIdx.x * blockDim.x + threadIdx.x;
    if (e >= EE) return;
    int srcn = ei[e];
    int d = ei[EE + e];
    int pos = atomicAdd(&g_fill[d], 1);
    int idx = g_rowptr[d] + pos;
    g_csrc[idx] = srcn;
    g_cnorm[idx] = g_dis[srcn] * ew[e] * g_dis[d];
}

// ---------------- layer 1 node kernel: conv(32->64,k3) + IN + relu + @gcn_w1 ----------------
// block: 256 threads, 4 nodes per block, thread = (node_local, out_channel)
__global__ void k_layer1(const float* __restrict__ x, const float* __restrict__ w1,
                         const float* __restrict__ b1, const float* __restrict__ gamma,
                         const float* __restrict__ beta, const float* __restrict__ gw) {
    extern __shared__ float sm[];
    float* ws = sm;                 // [96][64] transposed conv weights
    float* gs = ws + 96 * 64;       // [64][64] gcn weights
    float* xp = gs + 64 * 64;       // 4 * [14][32] padded inputs
    float* hs = xp + 4 * 14 * 32;   // 4 * [64][13] post-relu h

    int tid = threadIdx.x;
    for (int i = tid; i < 64 * 32 * 3; i += 256) {
        int co = i / 96, r = i % 96;
        ws[r * 64 + co] = w1[i];
    }
    for (int i = tid; i < 64 * 64; i += 256) gs[i] = gw[i];
    // zero temporal pads (t=-1 and t=T rows)
    for (int i = tid; i < 4 * 32; i += 256) {
        int ln = i / 32, ci = i % 32;
        xp[ln * 14 * 32 + 0 * 32 + ci] = 0.f;
        xp[ln * 14 * 32 + 13 * 32 + ci] = 0.f;
    }
    int local = tid >> 6;
    int co = tid & 63;
    int n = blockIdx.x * 4 + local;
    bool active = (n < NN);
    __syncthreads();
    if (active) {
        float* xpl = xp + local * 14 * 32;
        for (int i = co; i < TT * 32; i += 64) {
            int t = i / 32, ci = i % 32;
            xpl[(t + 1) * 32 + ci] = x[((size_t)t * NN + n) * 32 + ci];
        }
    }
    __syncthreads();
    if (active) {
        const float* xpl = xp + local * 14 * 32;
        float acc[TT];
#pragma unroll
        for (int t = 0; t < TT; t++) acc[t] = 0.f;
        for (int ci = 0; ci < 32; ci++) {
            float w0 = ws[(ci * 3 + 0) * 64 + co];
            float wa = ws[(ci * 3 + 1) * 64 + co];
            float wb = ws[(ci * 3 + 2) * 64 + co];
#pragma unroll
            for (int t = 0; t < TT; t++) {
                acc[t] += w0 * xpl[t * 32 + ci] + wa * xpl[(t + 1) * 32 + ci] + wb * xpl[(t + 2) * 32 + ci];
            }
        }
        float bb = b1[co];
        float mu = 0.f;
#pragma unroll
        for (int t = 0; t < TT; t++) { acc[t] += bb; mu += acc[t]; }
        mu *= (1.0f / TT);
        float var = 0.f;
#pragma unroll
        for (int t = 0; t < TT; t++) { float d = acc[t] - mu; var += d * d; }
        var *= (1.0f / TT);
        float sc = rsqrtf(var + 1e-5f) * gamma[co];
        float bt = beta[co];
        float* hl = hs + local * 64 * 13;
#pragma unroll
        for (int t = 0; t < TT; t++) {
            float v = (acc[t] - mu) * sc + bt;
            hl[co * 13 + t] = v > 0.f ? v : 0.f;
        }
    }
    __syncthreads();
    if (active) {
        const float* hl = hs + local * 64 * 13;
        float o[TT];
#pragma unroll
        for (int t = 0; t < TT; t++) o[t] = 0.f;
        for (int c = 0; c < 64; c++) {
            float g = gs[c * 64 + co];
#pragma unroll
            for (int t = 0; t < TT; t++) o[t] += g * hl[c * 13 + t];
        }
#pragma unroll
        for (int t = 0; t < TT; t++) g_xw1[((size_t)t * NN + n) * 64 + co] = o[t];
    }
}

// ---------------- layer 1 aggregation: warp per node, all 12 t in registers ----------------
__global__ void k_agg1(const float* __restrict__ gb) {
    int wid = (blockIdx.x * blockDim.x + threadIdx.x) >> 5;
    int lane = threadIdx.x & 31;
    if (wid >= NN) return;
    int n = wid;
    int rs = g_rowptr[n], re = g_rowptr[n + 1];
    float a[2 * TT];
#pragma unroll
    for (int i = 0; i < 2 * TT; i++) a[i] = 0.f;
    for (int i = rs; i < re; i++) {
        int s = __ldg(&g_csrc[i]);
        float w = __ldg(&g_cnorm[i]);
        const float* p = g_xw1 + (size_t)s * 64;
#pragma unroll
        for (int t = 0; t < TT; t++) {
            const float* pt = p + (size_t)t * NN * 64;
            a[2 * t]     += w * __ldg(pt + lane);
            a[2 * t + 1] += w * __ldg(pt + lane + 32);
        }
    }
    float d = g_dis[n];
    float d2 = d * d;
    float b0 = gb[lane], b1v = gb[lane + 32];
    const float* pn = g_xw1 + (size_t)n * 64;
#pragma unroll
    for (int t = 0; t < TT; t++) {
        const float* pt = pn + (size_t)t * NN * 64;
        float r0 = a[2 * t]     + d2 * pt[lane]      + b0;
        float r1 = a[2 * t + 1] + d2 * pt[lane + 32] + b1v;
        float* o = g_agg1 + ((size_t)t * NN + n) * 64;
        o[lane] = r0;
        o[lane + 32] = r1;
    }
}

// ---------------- layer 2 node kernel: conv(64->64,k3)+IN+relu, T-mean, @gcn_w2 ----------------
__global__ void k_layer2(const float* __restrict__ w2, const float* __restrict__ b2,
                         const float* __restrict__ gamma, const float* __restrict__ beta,
                         const float* __restrict__ gw) {
    extern __shared__ float sm[];
    float* ws = sm;                   // [192][64]
    float* gs = ws + 192 * 64;        // [64][64]
    float* xp = gs + 64 * 64;         // 4 * [14][64]
    float* hb = xp + 4 * 14 * 64;     // 4 * [64] (T-mean of relu h)

    int tid = threadIdx.x;
    for (int i = tid; i < 64 * 64 * 3; i += 256) {
        int co = i / 192, r = i % 192;
        ws[r * 64 + co] = w2[i];
    }
    for (int i = tid; i < 64 * 64; i += 256) gs[i] = gw[i];
    for (int i = tid; i < 4 * 64; i += 256) {
        int ln = i / 64, ci = i % 64;
        xp[ln * 14 * 64 + 0 * 64 + ci] = 0.f;
        xp[ln * 14 * 64 + 13 * 64 + ci] = 0.f;
    }
    int local = tid >> 6;
    int co = tid & 63;
    int n = blockIdx.x * 4 + local;
    bool active = (n < NN);
    __syncthreads();
    if (active) {
        float* xpl = xp + local * 14 * 64;
        for (int i = co; i < TT * 64; i += 64) {
            int t = i / 64, ci = i % 64;
            xpl[(t + 1) * 64 + ci] = g_agg1[((size_t)t * NN + n) * 64 + ci];
        }
    }
    __syncthreads();
    if (active) {
        const float* xpl = xp + local * 14 * 64;
        float acc[TT];
#pragma unroll
        for (int t = 0; t < TT; t++) acc[t] = 0.f;
        for (int ci = 0; ci < 64; ci++) {
            float w0 = ws[(ci * 3 + 0) * 64 + co];
            float wa = ws[(ci * 3 + 1) * 64 + co];
            float wb = ws[(ci * 3 + 2) * 64 + co];
#pragma unroll
            for (int t = 0; t < TT; t++) {
                acc[t] += w0 * xpl[t * 64 + ci] + wa * xpl[(t + 1) * 64 + ci] + wb * xpl[(t + 2) * 64 + ci];
            }
        }
        float bb = b2[co];
        float mu = 0.f;
#pragma unroll
        for (int t = 0; t < TT; t++) { acc[t] += bb; mu += acc[t]; }
        mu *= (1.0f / TT);
        float var = 0.f;
#pragma unroll
        for (int t = 0; t < TT; t++) { float d = acc[t] - mu; var += d * d; }
        var *= (1.0f / TT);
        float sc = rsqrtf(var + 1e-5f) * gamma[co];
        float bt = beta[co];
        float hsum = 0.f;
#pragma unroll
        for (int t = 0; t < TT; t++) {
            float v = (acc[t] - mu) * sc + bt;
            hsum += (v > 0.f ? v : 0.f);
        }
        hb[local * 64 + co] = hsum * (1.0f / TT);
    }
    __syncthreads();
    if (active) {
        const float* hl = hb + local * 64;
        float s = 0.f;
        for (int c = 0; c < 64; c++) s += hl[c] * gs[c * 64 + co];
        g_xs2[(size_t)n * 64 + co] = s;
    }
}

// ---------------- layer 2 aggregation (T collapsed) + output linear ----------------
__global__ void k_agg2_out(const float* __restrict__ gb, const float* __restrict__ ow,
                           const float* __restrict__ ob, float* __restrict__ out) {
    __shared__ float ows[64 * 32];
    __shared__ float am[8][64];
    int tid = threadIdx.x;
    for (int i = tid; i < 64 * 32; i += 256) ows[i] = ow[i];
    __syncthreads();
    int wslot = tid >> 5;
    int lane = tid & 31;
    int n = blockIdx.x * 8 + wslot;
    if (n >= NN) return;
    int rs = g_rowptr[n], re = g_rowptr[n + 1];
    float a0 = 0.f, a1 = 0.f;
    for (int i = rs; i < re; i++) {
        int s = __ldg(&g_csrc[i]);
        float w = __ldg(&g_cnorm[i]);
        const float* p = g_xs2 + (size_t)s * 64;
        a0 += w * __ldg(p + lane);
        a1 += w * __ldg(p + lane + 32);
    }
    float d = g_dis[n];
    float d2 = d * d;
    const float* pn = g_xs2 + (size_t)n * 64;
    a0 += d2 * pn[lane] + gb[lane];
    a1 += d2 * pn[lane + 32] + gb[lane + 32];
    am[wslot][lane] = a0;
    am[wslot][lane + 32] = a1;
    __syncwarp();
    float s = ob[lane];
    const float* amr = am[wslot];
#pragma unroll 8
    for (int c = 0; c < 64; c++) s += amr[c] * ows[c * 32 + lane];
    out[(size_t)n * 32 + lane] = s;
}

// ---------------- launch ----------------
extern "C" void kernel_launch(void* const* d_in, const int* in_sizes, int n_in,
                              void* d_out, int out_size) {
    const float* x    = (const float*)d_in[0];
    const int*   ei   = (const int*)d_in[1];
    const float* ew   = (const float*)d_in[2];
    const float* cw1  = (const float*)d_in[3];
    const float* cb1  = (const float*)d_in[4];
    const float* ga1  = (const float*)d_in[5];
    const float* be1  = (const float*)d_in[6];
    const float* gw1  = (const float*)d_in[7];
    const float* gb1  = (const float*)d_in[8];
    const float* cw2  = (const float*)d_in[9];
    const float* cb2  = (const float*)d_in[10];
    const float* ga2  = (const float*)d_in[11];
    const float* be2  = (const float*)d_in[12];
    const float* gw2  = (const float*)d_in[13];
    const float* gb2  = (const float*)d_in[14];
    const float* ow   = (const float*)d_in[15];
    const float* ob   = (const float*)d_in[16];
    float* out = (float*)d_out;

    static bool attr_set = false;
    const int smem1 = (96 * 64 + 64 * 64 + 4 * 14 * 32 + 4 * 64 * 13) * 4;   // 61440
    const int smem2 = (192 * 64 + 64 * 64 + 4 * 14 * 64 + 4 * 64) * 4;       // 80896
    if (!attr_set) {
        cudaFuncSetAttribute(k_layer1, cudaFuncAttributeMaxDynamicSharedMemorySize, smem1);
        cudaFuncSetAttribute(k_layer2, cudaFuncAttributeMaxDynamicSharedMemorySize, smem2);
        attr_set = true;
    }

    k_zero<<<(NN + 255) / 256, 256>>>();
    k_edge_hist<<<(EE + 255) / 256, 256>>>(ei, ew);
    k_dis<<<(NN + 255) / 256, 256>>>();
    k_scan<<<1, 1024>>>();
    k_scatter<<<(EE + 255) / 256, 256>>>(ei, ew);

    k_layer1<<<(NN + 3) / 4, 256, smem1>>>(x, cw1, cb1, ga1, be1, gw1);
    k_agg1<<<(NN * 32 + 255) / 256, 256>>>(gb1);
    k_layer2<<<(NN + 3) / 4, 256, smem2>>>(cw2, cb2, ga2, be2, gw2);
    k_agg2_out<<<(NN + 7) / 8, 256>>>(gb2, ow, ob, out);
}

// round 2
// speedup vs baseline: 1.3057x; 1.3057x over previous
#include <cuda_runtime.h>
#include <cuda_fp16.h>
#include <cuda_bf16.h>
#include <cstdint>

#define TT 12
#define NN 10000
#define EE 160000
#define C1 32
#define CH 64
#define CO 32

typedef unsigned long long u64;

// ---------------- packed f32x2 helpers (Blackwell FFMA2) ----------------
__device__ __forceinline__ u64 splat2(float v) {
    u64 r; asm("mov.b64 %0,{%1,%1};" : "=l"(r) : "f"(v)); return r;
}
__device__ __forceinline__ void fma2(u64& acc, u64 a, u64 b) {
    asm("fma.rn.f32x2 %0,%1,%2,%0;" : "+l"(acc) : "l"(a), "l"(b));
}
__device__ __forceinline__ float2 unpack2(u64 v) {
    float2 f; asm("mov.b64 {%0,%1},%2;" : "=f"(f.x), "=f"(f.y) : "l"(v)); return f;
}
__device__ __forceinline__ u64 lds2(const float* p) {
    return *reinterpret_cast<const u64*>(p);
}

// ---------------- device scratch ----------------
__device__ __half  g_xw1h[TT * NN * CH];  // layer1 h@W  [T,N,64] (fp16)
__device__ float   g_agg1[TT * NN * CH];  // layer1 GCN output [T,N,64]
__device__ float   g_xs2[NN * CH];        // mean_t(h2) @ W2  [N,64]
__device__ float   g_deg[NN];
__device__ float   g_dis[NN];
__device__ int     g_cnt[NN];
__device__ int     g_fill[NN];
__device__ int     g_rowptr[NN + 1];
__device__ int     g_csrc[EE];
__device__ float   g_cnorm[EE];

// ---------------- graph preprocessing ----------------
__global__ void k_zero() {
    int i = blockIdx.x * blockDim.x + threadIdx.x;
    if (i < NN) { g_deg[i] = 0.f; g_cnt[i] = 0; g_fill[i] = 0; }
}

__global__ void k_edge_hist(const int* __restrict__ ei, const float* __restrict__ ew) {
    int e = blockIdx.x * blockDim.x + threadIdx.x;
    if (e >= EE) return;
    int d = ei[EE + e];
    atomicAdd(&g_deg[d], ew[e]);
    atomicAdd(&g_cnt[d], 1);
}

__global__ void k_dis() {
    int i = blockIdx.x * blockDim.x + threadIdx.x;
    if (i < NN) g_dis[i] = rsqrtf(g_deg[i] + 1.0f);
}

__global__ void k_scan() {
    __shared__ int s[1024];
    const int per = (NN + 1023) / 1024;
    int tid = threadIdx.x;
    int vals[16];
    int start = tid * per;
    int local = 0;
    for (int k = 0; k < per; k++) {
        int idx = start + k;
        int v = (idx < NN) ? g_cnt[idx] : 0;
        vals[k] = v; local += v;
    }
    s[tid] = local;
    __syncthreads();
    for (int off = 1; off < 1024; off <<= 1) {
        int v = (tid >= off) ? s[tid - off] : 0;
        __syncthreads();
        s[tid] += v;
        __syncthreads();
    }
    int run = (tid > 0) ? s[tid - 1] : 0;
    for (int k = 0; k < per; k++) {
        int idx = start + k;
        if (idx < NN) g_rowptr[idx] = run;
        run += vals[k];
    }
    if (tid == 1023) g_rowptr[NN] = s[1023];
}

__global__ void k_scatter(const int* __restrict__ ei, const float* __restrict__ ew) {
    int e = blockIdx.x * blockDim.x + threadIdx.x;
    if (e >= EE) return;
    int srcn = ei[e];
    int d = ei[EE + e];
    int pos = atomicAdd(&g_fill[d], 1);
    int idx = g_rowptr[d] + pos;
    g_csrc[idx] = srcn;
    g_cnorm[idx] = g_dis[srcn] * ew[e] * g_dis[d];
}

// ---------------- layer 1: conv(32->64,k3)+IN+relu+@gcn_w1, FFMA2 packed over t ----------------
// 8 nodes/block, 512 threads, thread = (node_local, out_channel)
#define L1N 8
__global__ void k_layer1(const float* __restrict__ x, const float* __restrict__ w1,
                         const float* __restrict__ b1, const float* __restrict__ gamma,
                         const float* __restrict__ beta, const float* __restrict__ gw) {
    extern __shared__ float sm[];
    float* ws = sm;                     // [96][64]
    float* gs = ws + 96 * 64;           // [64][64]
    float* xa = gs + 64 * 64;           // L1N * [32][14]  (t-pad layout)
    float* xb = xa + L1N * 32 * 14;     // shifted copy
    float* hs = xb + L1N * 32 * 14;     // L1N * [64][14]  (12 used, pad stride 14)

    int tid = threadIdx.x;
    for (int i = tid; i < 64 * 32 * 3; i += 512) {
        int co = i / 96, r = i % 96;
        ws[r * 64 + co] = w1[i];
    }
    for (int i = tid; i < 64 * 64; i += 512) gs[i] = gw[i];
    for (int i = tid; i < L1N * 32; i += 512) {
        float* ra = xa + i * 14;
        float* rb = xb + i * 14;
        ra[0] = 0.f; ra[13] = 0.f; rb[12] = 0.f; rb[13] = 0.f;
    }
    int local = tid >> 6;
    int co = tid & 63;
    int n = blockIdx.x * L1N + local;
    bool active = (n < NN);
    __syncthreads();
    if (active) {
        for (int i = co; i < TT * 32; i += 64) {
            int t = i >> 5, ci = i & 31;
            float v = x[((size_t)t * NN + n) * 32 + ci];
            int row = (local * 32 + ci) * 14;
            xa[row + t + 1] = v;
            xb[row + t] = v;
        }
    }
    __syncthreads();
    if (active) {
        u64 acc[6];
#pragma unroll
        for (int p = 0; p < 6; p++) acc[p] = splat2(0.f);
        for (int ci = 0; ci < 32; ci++) {
            const float* ra = xa + (local * 32 + ci) * 14;
            const float* rb = xb + (local * 32 + ci) * 14;
            u64 W0 = splat2(ws[(ci * 3 + 0) * 64 + co]);
            u64 W1 = splat2(ws[(ci * 3 + 1) * 64 + co]);
            u64 W2 = splat2(ws[(ci * 3 + 2) * 64 + co]);
            u64 la[7], lb[6];
#pragma unroll
            for (int j = 0; j < 7; j++) la[j] = lds2(ra + 2 * j);
#pragma unroll
            for (int j = 0; j < 6; j++) lb[j] = lds2(rb + 2 * j);
#pragma unroll
            for (int p = 0; p < 6; p++) {
                fma2(acc[p], W0, la[p]);
                fma2(acc[p], W1, lb[p]);
                fma2(acc[p], W2, la[p + 1]);
            }
        }
        float a[TT];
#pragma unroll
        for (int p = 0; p < 6; p++) {
            float2 f = unpack2(acc[p]);
            a[2 * p] = f.x; a[2 * p + 1] = f.y;
        }
        float bb = b1[co];
        float mu = 0.f;
#pragma unroll
        for (int t = 0; t < TT; t++) { a[t] += bb; mu += a[t]; }
        mu *= (1.0f / TT);
        float var = 0.f;
#pragma unroll
        for (int t = 0; t < TT; t++) { float d = a[t] - mu; var += d * d; }
        var *= (1.0f / TT);
        float sc = rsqrtf(var + 1e-5f) * gamma[co];
        float bt = beta[co];
        float* hr = hs + (local * 64 + co) * 14;
#pragma unroll
        for (int p = 0; p < 6; p++) {
            float v0 = (a[2 * p] - mu) * sc + bt;
            float v1 = (a[2 * p + 1] - mu) * sc + bt;
            v0 = v0 > 0.f ? v0 : 0.f;
            v1 = v1 > 0.f ? v1 : 0.f;
            *reinterpret_cast<float2*>(hr + 2 * p) = make_float2(v0, v1);
        }
    }
    __syncthreads();
    if (active) {
        u64 o[6];
#pragma unroll
        for (int p = 0; p < 6; p++) o[p] = splat2(0.f);
        for (int c = 0; c < 64; c++) {
            u64 G = splat2(gs[c * 64 + co]);
            const float* hr = hs + (local * 64 + c) * 14;
#pragma unroll
            for (int p = 0; p < 6; p++) fma2(o[p], G, lds2(hr + 2 * p));
        }
#pragma unroll
        for (int p = 0; p < 6; p++) {
            float2 f = unpack2(o[p]);
            g_xw1h[((size_t)(2 * p) * NN + n) * 64 + co] = __float2half_rn(f.x);
            g_xw1h[((size_t)(2 * p + 1) * NN + n) * 64 + co] = __float2half_rn(f.y);
        }
    }
}

// ---------------- layer 1 aggregation: warp per node, fp16 gathers ----------------
__global__ void k_agg1(const float* __restrict__ gb) {
    int wid = (blockIdx.x * blockDim.x + threadIdx.x) >> 5;
    int lane = threadIdx.x & 31;
    if (wid >= NN) return;
    int n = wid;
    int rs = g_rowptr[n], re = g_rowptr[n + 1];
    const __half2* base = reinterpret_cast<const __half2*>(g_xw1h);
    float a[2 * TT];
#pragma unroll
    for (int i = 0; i < 2 * TT; i++) a[i] = 0.f;
    for (int i = rs; i < re; i++) {
        int s = __ldg(&g_csrc[i]);
        float w = __ldg(&g_cnorm[i]);
        const __half2* p = base + (size_t)s * 32 + lane;
#pragma unroll
        for (int t = 0; t < TT; t++) {
            float2 f = __half22float2(__ldg(p + (size_t)t * NN * 32));
            a[2 * t]     += w * f.x;
            a[2 * t + 1] += w * f.y;
        }
    }
    float d = g_dis[n];
    float d2 = d * d;
    float b0 = gb[2 * lane], b1v = gb[2 * lane + 1];
    const __half2* pn = base + (size_t)n * 32 + lane;
#pragma unroll
    for (int t = 0; t < TT; t++) {
        float2 f = __half22float2(pn[(size_t)t * NN * 32]);
        float r0 = a[2 * t]     + d2 * f.x + b0;
        float r1 = a[2 * t + 1] + d2 * f.y + b1v;
        *reinterpret_cast<float2*>(g_agg1 + ((size_t)t * NN + n) * 64 + 2 * lane) = make_float2(r0, r1);
    }
}

// ---------------- layer 2: conv(64->64,k3)+IN+relu, T-mean, @gcn_w2 ----------------
// 6 nodes/block, 384 threads
#define L2N 6
__global__ void k_layer2(const float* __restrict__ w2, const float* __restrict__ b2,
                         const float* __restrict__ gamma, const float* __restrict__ beta,
                         const float* __restrict__ gw) {
    extern __shared__ float sm[];
    float* ws = sm;                     // [192][64]
    float* gs = ws + 192 * 64;          // [64][64]
    float* xa = gs + 64 * 64;           // L2N * [64][14]
    float* xb = xa + L2N * 64 * 14;
    float* hb = xb + L2N * 64 * 14;     // L2N * [64]

    int tid = threadIdx.x;
    for (int i = tid; i < 64 * 64 * 3; i += 384) {
        int co = i / 192, r = i % 192;
        ws[r * 64 + co] = w2[i];
    }
    for (int i = tid; i < 64 * 64; i += 384) gs[i] = gw[i];
    for (int i = tid; i < L2N * 64; i += 384) {
        float* ra = xa + i * 14;
        float* rb = xb + i * 14;
        ra[0] = 0.f; ra[13] = 0.f; rb[12] = 0.f; rb[13] = 0.f;
    }
    int local = tid >> 6;
    int co = tid & 63;
    int n = blockIdx.x * L2N + local;
    bool active = (n < NN);
    __syncthreads();
    if (active) {
        for (int i = co; i < TT * 64; i += 64) {
            int t = i >> 6, ci = i & 63;
            float v = g_agg1[((size_t)t * NN + n) * 64 + ci];
            int row = (local * 64 + ci) * 14;
            xa[row + t + 1] = v;
            xb[row + t] = v;
        }
    }
    __syncthreads();
    if (active) {
        u64 acc[6];
#pragma unroll
        for (int p = 0; p < 6; p++) acc[p] = splat2(0.f);
        for (int ci = 0; ci < 64; ci++) {
            const float* ra = xa + (local * 64 + ci) * 14;
            const float* rb = xb + (local * 64 + ci) * 14;
            u64 W0 = splat2(ws[(ci * 3 + 0) * 64 + co]);
            u64 W1 = splat2(ws[(ci * 3 + 1) * 64 + co]);
            u64 W2 = splat2(ws[(ci * 3 + 2) * 64 + co]);
            u64 la[7], lb[6];
#pragma unroll
            for (int j = 0; j < 7; j++) la[j] = lds2(ra + 2 * j);
#pragma unroll
            for (int j = 0; j < 6; j++) lb[j] = lds2(rb + 2 * j);
#pragma unroll
            for (int p = 0; p < 6; p++) {
                fma2(acc[p], W0, la[p]);
                fma2(acc[p], W1, lb[p]);
                fma2(acc[p], W2, la[p + 1]);
            }
        }
        float a[TT];
#pragma unroll
        for (int p = 0; p < 6; p++) {
            float2 f = unpack2(acc[p]);
            a[2 * p] = f.x; a[2 * p + 1] = f.y;
        }
        float bb = b2[co];
        float mu = 0.f;
#pragma unroll
        for (int t = 0; t < TT; t++) { a[t] += bb; mu += a[t]; }
        mu *= (1.0f / TT);
        float var = 0.f;
#pragma unroll
        for (int t = 0; t < TT; t++) { float d = a[t] - mu; var += d * d; }
        var *= (1.0f / TT);
        float sc = rsqrtf(var + 1e-5f) * gamma[co];
        float bt = beta[co];
        float hsum = 0.f;
#pragma unroll
        for (int t = 0; t < TT; t++) {
            float v = (a[t] - mu) * sc + bt;
            hsum += (v > 0.f ? v : 0.f);
        }
        hb[local * 64 + co] = hsum * (1.0f / TT);
    }
    __syncthreads();
    if (active) {
        const float* hl = hb + local * 64;
        float s = 0.f;
#pragma unroll 8
        for (int c = 0; c < 64; c++) s += hl[c] * gs[c * 64 + co];
        g_xs2[(size_t)n * 64 + co] = s;
    }
}

// ---------------- layer 2 aggregation (T collapsed) + output linear ----------------
__global__ void k_agg2_out(const float* __restrict__ gb, const float* __restrict__ ow,
                           const float* __restrict__ ob, float* __restrict__ out) {
    __shared__ float ows[64 * 32];
    __shared__ float am[8][64];
    int tid = threadIdx.x;
    for (int i = tid; i < 64 * 32; i += 256) ows[i] = ow[i];
    __syncthreads();
    int wslot = tid >> 5;
    int lane = tid & 31;
    int n = blockIdx.x * 8 + wslot;
    if (n >= NN) return;
    int rs = g_rowptr[n], re = g_rowptr[n + 1];
    float a0 = 0.f, a1 = 0.f;
    for (int i = rs; i < re; i++) {
        int s = __ldg(&g_csrc[i]);
        float w = __ldg(&g_cnorm[i]);
        const float* p = g_xs2 + (size_t)s * 64;
        a0 += w * __ldg(p + lane);
        a1 += w * __ldg(p + lane + 32);
    }
    float d = g_dis[n];
    float d2 = d * d;
    const float* pn = g_xs2 + (size_t)n * 64;
    a0 += d2 * pn[lane] + gb[lane];
    a1 += d2 * pn[lane + 32] + gb[lane + 32];
    am[wslot][lane] = a0;
    am[wslot][lane + 32] = a1;
    __syncwarp();
    float s = ob[lane];
    const float* amr = am[wslot];
#pragma unroll 8
    for (int c = 0; c < 64; c++) s += amr[c] * ows[c * 32 + lane];
    out[(size_t)n * 32 + lane] = s;
}

// ---------------- launch ----------------
extern "C" void kernel_launch(void* const* d_in, const int* in_sizes, int n_in,
                              void* d_out, int out_size) {
    const float* x    = (const float*)d_in[0];
    const int*   ei   = (const int*)d_in[1];
    const float* ew   = (const float*)d_in[2];
    const float* cw1  = (const float*)d_in[3];
    const float* cb1  = (const float*)d_in[4];
    const float* ga1  = (const float*)d_in[5];
    const float* be1  = (const float*)d_in[6];
    const float* gw1  = (const float*)d_in[7];
    const float* gb1  = (const float*)d_in[8];
    const float* cw2  = (const float*)d_in[9];
    const float* cb2  = (const float*)d_in[10];
    const float* ga2  = (const float*)d_in[11];
    const float* be2  = (const float*)d_in[12];
    const float* gw2  = (const float*)d_in[13];
    const float* gb2  = (const float*)d_in[14];
    const float* ow   = (const float*)d_in[15];
    const float* ob   = (const float*)d_in[16];
    float* out = (float*)d_out;

    const int smem1 = (96 * 64 + 64 * 64 + L1N * 32 * 14 * 2 + L1N * 64 * 14) * 4;
    const int smem2 = (192 * 64 + 64 * 64 + L2N * 64 * 14 * 2 + L2N * 64) * 4;
    static bool attr_set = false;
    if (!attr_set) {
        cudaFuncSetAttribute(k_layer1, cudaFuncAttributeMaxDynamicSharedMemorySize, smem1);
        cudaFuncSetAttribute(k_layer2, cudaFuncAttributeMaxDynamicSharedMemorySize, smem2);
        attr_set = true;
    }

    k_zero<<<(NN + 255) / 256, 256>>>();
    k_edge_hist<<<(EE + 255) / 256, 256>>>(ei, ew);
    k_dis<<<(NN + 255) / 256, 256>>>();
    k_scan<<<1, 1024>>>();
    k_scatter<<<(EE + 255) / 256, 256>>>(ei, ew);

    k_layer1<<<(NN + L1N - 1) / L1N, 512, smem1>>>(x, cw1, cb1, ga1, be1, gw1);
    k_agg1<<<(NN * 32 + 255) / 256, 256>>>(gb1);
    k_layer2<<<(NN + L2N - 1) / L2N, 384, smem2>>>(cw2, cb2, ga2, be2, gw2);
    k_agg2_out<<<(NN + 7) / 8, 256>>>(gb2, ow, ob, out);
}

// round 3
// speedup vs baseline: 1.3117x; 1.0046x over previous
#include <cuda_runtime.h>
#include <cuda_fp16.h>
#include <cuda_bf16.h>
#include <cstdint>

#define TT 12
#define NN 10000
#define EE 160000
#define C1 32
#define CH 64
#define CO 32

typedef unsigned long long u64;

// ---------------- packed f32x2 helpers (Blackwell FFMA2) ----------------
__device__ __forceinline__ u64 splat2(float v) {
    u64 r; asm("mov.b64 %0,{%1,%1};" : "=l"(r) : "f"(v)); return r;
}
__device__ __forceinline__ void fma2(u64& acc, u64 a, u64 b) {
    asm("fma.rn.f32x2 %0,%1,%2,%0;" : "+l"(acc) : "l"(a), "l"(b));
}
__device__ __forceinline__ float2 unpack2(u64 v) {
    float2 f; asm("mov.b64 {%0,%1},%2;" : "=f"(f.x), "=f"(f.y) : "l"(v)); return f;
}
__device__ __forceinline__ u64 lds2(const float* p) {
    return *reinterpret_cast<const u64*>(p);
}

// ---------------- device scratch ----------------
__device__ __half  g_xw1h[TT * NN * CH];  // layer1 h@W  [T,N,64] (fp16)
__device__ float   g_agg1[TT * NN * CH];  // layer1 GCN output [T,N,64]
__device__ float   g_xs2[NN * CH];        // mean_t(h2) @ W2  [N,64]
__device__ float   g_deg[NN];
__device__ float   g_dis[NN];
__device__ int     g_cnt[NN];
__device__ int     g_fill[NN];
__device__ int     g_rowptr[NN + 1];
__device__ int     g_csrc[EE];
__device__ float   g_cnorm[EE];

// ---------------- graph preprocessing ----------------
__global__ void k_zero() {
    int i = blockIdx.x * blockDim.x + threadIdx.x;
    if (i < NN) { g_deg[i] = 0.f; g_cnt[i] = 0; g_fill[i] = 0; }
}

__global__ void k_edge_hist(const int* __restrict__ ei, const float* __restrict__ ew) {
    int e = blockIdx.x * blockDim.x + threadIdx.x;
    if (e >= EE) return;
    int d = ei[EE + e];
    atomicAdd(&g_deg[d], ew[e]);
    atomicAdd(&g_cnt[d], 1);
}

// fused: g_dis = rsqrt(deg+1) AND exclusive scan of g_cnt -> g_rowptr (shfl-based)
__global__ void k_scandis() {
    __shared__ int ssum[32];
    int tid = threadIdx.x;
    int lane = tid & 31;
    int wid = tid >> 5;
    const int per = 10;  // 1024*10 >= 10000
    int start = tid * per;
    int vals[per];
    int local = 0;
#pragma unroll
    for (int k = 0; k < per; k++) {
        int idx = start + k;
        int v = 0;
        if (idx < NN) {
            v = g_cnt[idx];
            g_dis[idx] = rsqrtf(g_deg[idx] + 1.0f);
        }
        vals[k] = v; local += v;
    }
    // warp inclusive scan
    int x = local;
#pragma unroll
    for (int off = 1; off < 32; off <<= 1) {
        int y = __shfl_up_sync(0xffffffffu, x, off);
        if (lane >= off) x += y;
    }
    if (lane == 31) ssum[wid] = x;
    __syncthreads();
    if (wid == 0) {
        int v = ssum[lane];
#pragma unroll
        for (int off = 1; off < 32; off <<= 1) {
            int y = __shfl_up_sync(0xffffffffu, v, off);
            if (lane >= off) v += y;
        }
        ssum[lane] = v;
    }
    __syncthreads();
    int run = (wid > 0 ? ssum[wid - 1] : 0) + x - local;  // exclusive prefix
#pragma unroll
    for (int k = 0; k < per; k++) {
        int idx = start + k;
        if (idx < NN) g_rowptr[idx] = run;
        run += vals[k];
    }
    if (tid == 1023) g_rowptr[NN] = run;
}

__global__ void k_scatter(const int* __restrict__ ei, const float* __restrict__ ew) {
    int e = blockIdx.x * blockDim.x + threadIdx.x;
    if (e >= EE) return;
    int srcn = ei[e];
    int d = ei[EE + e];
    int pos = atomicAdd(&g_fill[d], 1);
    int idx = g_rowptr[d] + pos;
    g_csrc[idx] = srcn;
    g_cnorm[idx] = g_dis[srcn] * ew[e] * g_dis[d];
}

// ---------------- layer 1: conv(32->64,k3)+IN+relu+@gcn_w1, FFMA2 packed over t ----------------
#define L1N 8
__global__ void k_layer1(const float* __restrict__ x, const float* __restrict__ w1,
                         const float* __restrict__ b1, const float* __restrict__ gamma,
                         const float* __restrict__ beta, const float* __restrict__ gw) {
    extern __shared__ float sm[];
    float* ws = sm;                     // [96][64]
    float* gs = ws + 96 * 64;           // [64][64]
    float* xa = gs + 64 * 64;           // L1N * [32][14]
    float* xb = xa + L1N * 32 * 14;     // shifted copy
    float* hs = xb + L1N * 32 * 14;     // L1N * [64][14]

    int tid = threadIdx.x;
    for (int i = tid; i < 64 * 32 * 3; i += 512) {
        int co = i / 96, r = i % 96;
        ws[r * 64 + co] = w1[i];
    }
    for (int i = tid; i < 64 * 64; i += 512) gs[i] = gw[i];
    for (int i = tid; i < L1N * 32; i += 512) {
        float* ra = xa + i * 14;
        float* rb = xb + i * 14;
        ra[0] = 0.f; ra[13] = 0.f; rb[12] = 0.f; rb[13] = 0.f;
    }
    int local = tid >> 6;
    int co = tid & 63;
    int n = blockIdx.x * L1N + local;
    bool active = (n < NN);
    __syncthreads();
    if (active) {
        for (int i = co; i < TT * 32; i += 64) {
            int t = i >> 5, ci = i & 31;
            float v = x[((size_t)t * NN + n) * 32 + ci];
            int row = (local * 32 + ci) * 14;
            xa[row + t + 1] = v;
            xb[row + t] = v;
        }
    }
    __syncthreads();
    if (active) {
        u64 acc[6];
#pragma unroll
        for (int p = 0; p < 6; p++) acc[p] = splat2(0.f);
        for (int ci = 0; ci < 32; ci++) {
            const float* ra = xa + (local * 32 + ci) * 14;
            const float* rb = xb + (local * 32 + ci) * 14;
            u64 W0 = splat2(ws[(ci * 3 + 0) * 64 + co]);
            u64 W1 = splat2(ws[(ci * 3 + 1) * 64 + co]);
            u64 W2 = splat2(ws[(ci * 3 + 2) * 64 + co]);
            u64 la[7], lb[6];
#pragma unroll
            for (int j = 0; j < 7; j++) la[j] = lds2(ra + 2 * j);
#pragma unroll
            for (int j = 0; j < 6; j++) lb[j] = lds2(rb + 2 * j);
#pragma unroll
            for (int p = 0; p < 6; p++) {
                fma2(acc[p], W0, la[p]);
                fma2(acc[p], W1, lb[p]);
                fma2(acc[p], W2, la[p + 1]);
            }
        }
        float a[TT];
#pragma unroll
        for (int p = 0; p < 6; p++) {
            float2 f = unpack2(acc[p]);
            a[2 * p] = f.x; a[2 * p + 1] = f.y;
        }
        float bb = b1[co];
        float mu = 0.f;
#pragma unroll
        for (int t = 0; t < TT; t++) { a[t] += bb; mu += a[t]; }
        mu *= (1.0f / TT);
        float var = 0.f;
#pragma unroll
        for (int t = 0; t < TT; t++) { float d = a[t] - mu; var += d * d; }
        var *= (1.0f / TT);
        float sc = rsqrtf(var + 1e-5f) * gamma[co];
        float bt = beta[co];
        float* hr = hs + (local * 64 + co) * 14;
#pragma unroll
        for (int p = 0; p < 6; p++) {
            float v0 = (a[2 * p] - mu) * sc + bt;
            float v1 = (a[2 * p + 1] - mu) * sc + bt;
            v0 = v0 > 0.f ? v0 : 0.f;
            v1 = v1 > 0.f ? v1 : 0.f;
            *reinterpret_cast<float2*>(hr + 2 * p) = make_float2(v0, v1);
        }
    }
    __syncthreads();
    if (active) {
        u64 o[6];
#pragma unroll
        for (int p = 0; p < 6; p++) o[p] = splat2(0.f);
        for (int c = 0; c < 64; c++) {
            u64 G = splat2(gs[c * 64 + co]);
            const float* hr = hs + (local * 64 + c) * 14;
#pragma unroll
            for (int p = 0; p < 6; p++) fma2(o[p], G, lds2(hr + 2 * p));
        }
#pragma unroll
        for (int p = 0; p < 6; p++) {
            float2 f = unpack2(o[p]);
            g_xw1h[((size_t)(2 * p) * NN + n) * 64 + co] = __float2half_rn(f.x);
            g_xw1h[((size_t)(2 * p + 1) * NN + n) * 64 + co] = __float2half_rn(f.y);
        }
    }
}

// ---------------- layer 1 aggregation: 2 warps per node (t halves), prefetch ----------------
__global__ void k_agg1(const float* __restrict__ gb) {
    int gwid = (blockIdx.x * blockDim.x + threadIdx.x) >> 5;
    int lane = threadIdx.x & 31;
    if (gwid >= 2 * NN) return;
    int n = gwid >> 1;
    int t0 = (gwid & 1) * 6;
    int rs = g_rowptr[n], re = g_rowptr[n + 1];
    const __half2* base = reinterpret_cast<const __half2*>(g_xw1h) + (size_t)t0 * NN * 32 + lane;
    float a[12];
#pragma unroll
    for (int i = 0; i < 12; i++) a[i] = 0.f;
    int sN = 0; float wN = 0.f;
    if (rs < re) { sN = __ldg(&g_csrc[rs]); wN = __ldg(&g_cnorm[rs]); }
    for (int i = rs; i < re; i++) {
        int s = sN; float w = wN;
        if (i + 1 < re) { sN = __ldg(&g_csrc[i + 1]); wN = __ldg(&g_cnorm[i + 1]); }
        const __half2* p = base + (size_t)s * 32;
#pragma unroll
        for (int t = 0; t < 6; t++) {
            float2 f = __half22float2(__ldg(p + (size_t)t * NN * 32));
            a[2 * t]     += w * f.x;
            a[2 * t + 1] += w * f.y;
        }
    }
    float d = g_dis[n];
    float d2 = d * d;
    float b0 = gb[2 * lane], b1v = gb[2 * lane + 1];
    const __half2* pn = base + (size_t)n * 32;
#pragma unroll
    for (int t = 0; t < 6; t++) {
        float2 f = __half22float2(pn[(size_t)t * NN * 32]);
        float r0 = a[2 * t]     + d2 * f.x + b0;
        float r1 = a[2 * t + 1] + d2 * f.y + b1v;
        *reinterpret_cast<float2*>(g_agg1 + ((size_t)(t0 + t) * NN + n) * 64 + 2 * lane) = make_float2(r0, r1);
    }
}

// ---------------- layer 2: conv(64->64,k3)+IN+relu, T-mean, @gcn_w2 ----------------
#define L2N 6
__global__ void k_layer2(const float* __restrict__ w2, const float* __restrict__ b2,
                         const float* __restrict__ gamma, const float* __restrict__ beta,
                         const float* __restrict__ gw) {
    extern __shared__ float sm[];
    float* ws = sm;                     // [192][64]
    float* gs = ws + 192 * 64;          // [64][64]
    float* xa = gs + 64 * 64;           // L2N * [64][14]
    float* xb = xa + L2N * 64 * 14;
    float* hb = xb + L2N * 64 * 14;     // L2N * [64]

    int tid = threadIdx.x;
    for (int i = tid; i < 64 * 64 * 3; i += 384) {
        int co = i / 192, r = i % 192;
        ws[r * 64 + co] = w2[i];
    }
    for (int i = tid; i < 64 * 64; i += 384) gs[i] = gw[i];
    for (int i = tid; i < L2N * 64; i += 384) {
        float* ra = xa + i * 14;
        float* rb = xb + i * 14;
        ra[0] = 0.f; ra[13] = 0.f; rb[12] = 0.f; rb[13] = 0.f;
    }
    int local = tid >> 6;
    int co = tid & 63;
    int n = blockIdx.x * L2N + local;
    bool active = (n < NN);
    __syncthreads();
    if (active) {
        for (int i = co; i < TT * 64; i += 64) {
            int t = i >> 6, ci = i & 63;
            float v = g_agg1[((size_t)t * NN + n) * 64 + ci];
            int row = (local * 64 + ci) * 14;
            xa[row + t + 1] = v;
            xb[row + t] = v;
        }
    }
    __syncthreads();
    if (active) {
        u64 acc[6];
#pragma unroll
        for (int p = 0; p < 6; p++) acc[p] = splat2(0.f);
        for (int ci = 0; ci < 64; ci++) {
            const float* ra = xa + (local * 64 + ci) * 14;
            const float* rb = xb + (local * 64 + ci) * 14;
            u64 W0 = splat2(ws[(ci * 3 + 0) * 64 + co]);
            u64 W1 = splat2(ws[(ci * 3 + 1) * 64 + co]);
            u64 W2 = splat2(ws[(ci * 3 + 2) * 64 + co]);
            u64 la[7], lb[6];
#pragma unroll
            for (int j = 0; j < 7; j++) la[j] = lds2(ra + 2 * j);
#pragma unroll
            for (int j = 0; j < 6; j++) lb[j] = lds2(rb + 2 * j);
#pragma unroll
            for (int p = 0; p < 6; p++) {
                fma2(acc[p], W0, la[p]);
                fma2(acc[p], W1, lb[p]);
                fma2(acc[p], W2, la[p + 1]);
            }
        }
        float a[TT];
#pragma unroll
        for (int p = 0; p < 6; p++) {
            float2 f = unpack2(acc[p]);
            a[2 * p] = f.x; a[2 * p + 1] = f.y;
        }
        float bb = b2[co];
        float mu = 0.f;
#pragma unroll
        for (int t = 0; t < TT; t++) { a[t] += bb; mu += a[t]; }
        mu *= (1.0f / TT);
        float var = 0.f;
#pragma unroll
        for (int t = 0; t < TT; t++) { float d = a[t] - mu; var += d * d; }
        var *= (1.0f / TT);
        float sc = rsqrtf(var + 1e-5f) * gamma[co];
        float bt = beta[co];
        float hsum = 0.f;
#pragma unroll
        for (int t = 0; t < TT; t++) {
            float v = (a[t] - mu) * sc + bt;
            hsum += (v > 0.f ? v : 0.f);
        }
        hb[local * 64 + co] = hsum * (1.0f / TT);
    }
    __syncthreads();
    if (active) {
        const float* hl = hb + local * 64;
        float s = 0.f;
#pragma unroll 8
        for (int c = 0; c < 64; c++) s += hl[c] * gs[c * 64 + co];
        g_xs2[(size_t)n * 64 + co] = s;
    }
}

// ---------------- layer 2 aggregation (T collapsed) + output linear ----------------
__global__ void k_agg2_out(const float* __restrict__ gb, const float* __restrict__ ow,
                           const float* __restrict__ ob, float* __restrict__ out) {
    __shared__ float ows[64 * 32];
    __shared__ float am[8][64];
    int tid = threadIdx.x;
    for (int i = tid; i < 64 * 32; i += 256) ows[i] = ow[i];
    __syncthreads();
    int wslot = tid >> 5;
    int lane = tid & 31;
    int n = blockIdx.x * 8 + wslot;
    if (n >= NN) return;
    int rs = g_rowptr[n], re = g_rowptr[n + 1];
    float a0 = 0.f, a1 = 0.f;
    int sN = 0; float wN = 0.f;
    if (rs < re) { sN = __ldg(&g_csrc[rs]); wN = __ldg(&g_cnorm[rs]); }
    for (int i = rs; i < re; i++) {
        int s = sN; float w = wN;
        if (i + 1 < re) { sN = __ldg(&g_csrc[i + 1]); wN = __ldg(&g_cnorm[i + 1]); }
        const float* p = g_xs2 + (size_t)s * 64;
        a0 += w * __ldg(p + lane);
        a1 += w * __ldg(p + lane + 32);
    }
    float d = g_dis[n];
    float d2 = d * d;
    const float* pn = g_xs2 + (size_t)n * 64;
    a0 += d2 * pn[lane] + gb[lane];
    a1 += d2 * pn[lane + 32] + gb[lane + 32];
    am[wslot][lane] = a0;
    am[wslot][lane + 32] = a1;
    __syncwarp();
    float s = ob[lane];
    const float* amr = am[wslot];
#pragma unroll 8
    for (int c = 0; c < 64; c++) s += amr[c] * ows[c * 32 + lane];
    out[(size_t)n * 32 + lane] = s;
}

// ---------------- launch ----------------
extern "C" void kernel_launch(void* const* d_in, const int* in_sizes, int n_in,
                              void* d_out, int out_size) {
    const float* x    = (const float*)d_in[0];
    const int*   ei   = (const int*)d_in[1];
    const float* ew   = (const float*)d_in[2];
    const float* cw1  = (const float*)d_in[3];
    const float* cb1  = (const float*)d_in[4];
    const float* ga1  = (const float*)d_in[5];
    const float* be1  = (const float*)d_in[6];
    const float* gw1  = (const float*)d_in[7];
    const float* gb1  = (const float*)d_in[8];
    const float* cw2  = (const float*)d_in[9];
    const float* cb2  = (const float*)d_in[10];
    const float* ga2  = (const float*)d_in[11];
    const float* be2  = (const float*)d_in[12];
    const float* gw2  = (const float*)d_in[13];
    const float* gb2  = (const float*)d_in[14];
    const float* ow   = (const float*)d_in[15];
    const float* ob   = (const float*)d_in[16];
    float* out = (float*)d_out;

    const int smem1 = (96 * 64 + 64 * 64 + L1N * 32 * 14 * 2 + L1N * 64 * 14) * 4;
    const int smem2 = (192 * 64 + 64 * 64 + L2N * 64 * 14 * 2 + L2N * 64) * 4;
    static bool attr_set = false;
    if (!attr_set) {
        cudaFuncSetAttribute(k_layer1, cudaFuncAttributeMaxDynamicSharedMemorySize, smem1);
        cudaFuncSetAttribute(k_layer2, cudaFuncAttributeMaxDynamicSharedMemorySize, smem2);
        attr_set = true;
    }

    // launch order chosen so k_layer1 is the 4th launch (ncu positional capture)
    k_zero<<<(NN + 255) / 256, 256>>>();
    k_edge_hist<<<(EE + 255) / 256, 256>>>(ei, ew);
    k_scandis<<<1, 1024>>>();
    k_layer1<<<(NN + L1N - 1) / L1N, 512, smem1>>>(x, cw1, cb1, ga1, be1, gw1);
    k_scatter<<<(EE + 255) / 256, 256>>>(ei, ew);
    k_agg1<<<(2 * NN * 32 + 255) / 256, 256>>>(gb1);
    k_layer2<<<(NN + L2N - 1) / L2N, 384, smem2>>>(cw2, cb2, ga2, be2, gw2);
    k_agg2_out<<<(NN + 7) / 8, 256>>>(gb2, ow, ob, out);
}

// round 4
// speedup vs baseline: 1.7270x; 1.3167x over previous
#include <cuda_runtime.h>
#include <cuda_fp16.h>
#include <cuda_bf16.h>
#include <cstdint>

#define TT 12
#define NN 10000
#define EE 160000
#define C1 32
#define CH 64
#define CO 32

typedef unsigned long long u64;

// ---------------- packed f32x2 helpers ----------------
__device__ __forceinline__ u64 splat2(float v) {
    u64 r; asm("mov.b64 %0,{%1,%1};" : "=l"(r) : "f"(v)); return r;
}
__device__ __forceinline__ u64 pack2(float lo, float hi) {
    u64 r; asm("mov.b64 %0,{%1,%2};" : "=l"(r) : "f"(lo), "f"(hi)); return r;
}
__device__ __forceinline__ void fma2(u64& acc, u64 a, u64 b) {
    asm("fma.rn.f32x2 %0,%1,%2,%0;" : "+l"(acc) : "l"(a), "l"(b));
}
__device__ __forceinline__ float2 unpack2(u64 v) {
    float2 f; asm("mov.b64 {%0,%1},%2;" : "=f"(f.x), "=f"(f.y) : "l"(v)); return f;
}
__device__ __forceinline__ u64 lds2(const float* p) {
    return *reinterpret_cast<const u64*>(p);
}

// ---------------- device scratch ----------------
__device__ __half  g_xw1h[TT * NN * CH];
__device__ float   g_agg1[TT * NN * CH];
__device__ float   g_xs2[NN * CH];
__device__ float   g_deg[NN];
__device__ float   g_dis[NN];
__device__ int     g_cnt[NN];
__device__ int     g_fill[NN];
__device__ int     g_rowptr[NN + 1];
__device__ int     g_csrc[EE];
__device__ float   g_cnorm[EE];

// ---------------- graph preprocessing ----------------
__global__ void k_zero() {
    int i = blockIdx.x * blockDim.x + threadIdx.x;
    if (i < NN) { g_deg[i] = 0.f; g_cnt[i] = 0; g_fill[i] = 0; }
}

__global__ void k_edge_hist(const int* __restrict__ ei, const float* __restrict__ ew) {
    int e = blockIdx.x * blockDim.x + threadIdx.x;
    if (e >= EE) return;
    int d = ei[EE + e];
    atomicAdd(&g_deg[d], ew[e]);
    atomicAdd(&g_cnt[d], 1);
}

__global__ void k_scandis() {
    __shared__ int ssum[32];
    int tid = threadIdx.x;
    int lane = tid & 31;
    int wid = tid >> 5;
    const int per = 10;
    int start = tid * per;
    int vals[per];
    int local = 0;
#pragma unroll
    for (int k = 0; k < per; k++) {
        int idx = start + k;
        int v = 0;
        if (idx < NN) {
            v = g_cnt[idx];
            g_dis[idx] = rsqrtf(g_deg[idx] + 1.0f);
        }
        vals[k] = v; local += v;
    }
    int x = local;
#pragma unroll
    for (int off = 1; off < 32; off <<= 1) {
        int y = __shfl_up_sync(0xffffffffu, x, off);
        if (lane >= off) x += y;
    }
    if (lane == 31) ssum[wid] = x;
    __syncthreads();
    if (wid == 0) {
        int v = ssum[lane];
#pragma unroll
        for (int off = 1; off < 32; off <<= 1) {
            int y = __shfl_up_sync(0xffffffffu, v, off);
            if (lane >= off) v += y;
        }
        ssum[lane] = v;
    }
    __syncthreads();
    int run = (wid > 0 ? ssum[wid - 1] : 0) + x - local;
#pragma unroll
    for (int k = 0; k < per; k++) {
        int idx = start + k;
        if (idx < NN) g_rowptr[idx] = run;
        run += vals[k];
    }
    if (tid == 1023) g_rowptr[NN] = run;
}

__global__ void k_scatter(const int* __restrict__ ei, const float* __restrict__ ew) {
    int e = blockIdx.x * blockDim.x + threadIdx.x;
    if (e >= EE) return;
    int srcn = ei[e];
    int d = ei[EE + e];
    int pos = atomicAdd(&g_fill[d], 1);
    int idx = g_rowptr[d] + pos;
    g_csrc[idx] = srcn;
    g_cnorm[idx] = g_dis[srcn] * ew[e] * g_dis[d];
}

// ---------------- layer 1: warp per node, lane owns co pair (2l,2l+1) ----------------
#define L1N 8
__global__ void __launch_bounds__(32 * L1N, 2)
k_layer1(const float* __restrict__ x, const float* __restrict__ w1,
         const float* __restrict__ b1, const float* __restrict__ gamma,
         const float* __restrict__ beta, const float* __restrict__ gw) {
    extern __shared__ float sm[];
    float* ws = sm;                     // [96][64]
    float* gs = ws + 96 * 64;           // [64][64]
    float* xa = gs + 64 * 64;           // L1N * [32][14]
    float* hs = xa + L1N * 32 * 14;     // L1N * [64][14]

    int tid = threadIdx.x;
    const int NT = 32 * L1N;
    for (int i = tid; i < 64 * 32 * 3; i += NT) {
        int co = i / 96, r = i % 96;
        ws[r * 64 + co] = w1[i];
    }
    for (int i = tid; i < 64 * 64; i += NT) gs[i] = gw[i];

    int local = tid >> 5;
    int lane = tid & 31;
    int n = blockIdx.x * L1N + local;
    // zero temporal pads for this warp's node (row per lane)
    {
        float* ra = xa + (local * 32 + lane) * 14;
        ra[0] = 0.f; ra[13] = 0.f;
    }
    __syncthreads();   // ws/gs visible

    // load this node's input: lane = ci, loop t
    {
        float* ra = xa + (local * 32 + lane) * 14;
#pragma unroll
        for (int t = 0; t < TT; t++)
            ra[t + 1] = x[((size_t)t * NN + n) * 32 + lane];
    }
    __syncwarp();

    // conv: acc for co pair
    u64 accA[6], accB[6];
#pragma unroll
    for (int p = 0; p < 6; p++) { accA[p] = splat2(0.f); accB[p] = splat2(0.f); }
    for (int ci = 0; ci < 32; ci++) {
        const float* ra = xa + (local * 32 + ci) * 14;
        u64 pa[7];
#pragma unroll
        for (int j = 0; j < 7; j++) pa[j] = lds2(ra + 2 * j);
        float2 uu[7];
#pragma unroll
        for (int j = 0; j < 7; j++) uu[j] = unpack2(pa[j]);
        u64 pb[6];
#pragma unroll
        for (int p = 0; p < 6; p++) pb[p] = pack2(uu[p].y, uu[p + 1].x);
        float2 w0 = unpack2(lds2(ws + (ci * 3 + 0) * 64 + 2 * lane));
        float2 w1v = unpack2(lds2(ws + (ci * 3 + 1) * 64 + 2 * lane));
        float2 w2 = unpack2(lds2(ws + (ci * 3 + 2) * 64 + 2 * lane));
        u64 W0a = splat2(w0.x), W0b = splat2(w0.y);
        u64 W1a = splat2(w1v.x), W1b = splat2(w1v.y);
        u64 W2a = splat2(w2.x), W2b = splat2(w2.y);
#pragma unroll
        for (int p = 0; p < 6; p++) {
            fma2(accA[p], W0a, pa[p]);
            fma2(accB[p], W0b, pa[p]);
            fma2(accA[p], W1a, pb[p]);
            fma2(accB[p], W1b, pb[p]);
            fma2(accA[p], W2a, pa[p + 1]);
            fma2(accB[p], W2b, pa[p + 1]);
        }
    }
    // IN + relu for both co, write to hs
    {
        float2 bb = *reinterpret_cast<const float2*>(b1 + 2 * lane);
        float2 gg = *reinterpret_cast<const float2*>(gamma + 2 * lane);
        float2 be = *reinterpret_cast<const float2*>(beta + 2 * lane);
        float aA[TT], aB[TT];
#pragma unroll
        for (int p = 0; p < 6; p++) {
            float2 fa = unpack2(accA[p]);
            float2 fb = unpack2(accB[p]);
            aA[2 * p] = fa.x + bb.x; aA[2 * p + 1] = fa.y + bb.x;
            aB[2 * p] = fb.x + bb.y; aB[2 * p + 1] = fb.y + bb.y;
        }
        float muA = 0.f, muB = 0.f;
#pragma unroll
        for (int t = 0; t < TT; t++) { muA += aA[t]; muB += aB[t]; }
        muA *= (1.0f / TT); muB *= (1.0f / TT);
        float vA = 0.f, vB = 0.f;
#pragma unroll
        for (int t = 0; t < TT; t++) {
            float dA = aA[t] - muA, dB = aB[t] - muB;
            vA += dA * dA; vB += dB * dB;
        }
        float scA = rsqrtf(vA * (1.0f / TT) + 1e-5f) * gg.x;
        float scB = rsqrtf(vB * (1.0f / TT) + 1e-5f) * gg.y;
        float* hA = hs + (local * 64 + 2 * lane) * 14;
        float* hB = hA + 14;
#pragma unroll
        for (int p = 0; p < 6; p++) {
            float x0 = (aA[2 * p] - muA) * scA + be.x;
            float x1 = (aA[2 * p + 1] - muA) * scA + be.x;
            float y0 = (aB[2 * p] - muB) * scB + be.y;
            float y1 = (aB[2 * p + 1] - muB) * scB + be.y;
            x0 = x0 > 0.f ? x0 : 0.f; x1 = x1 > 0.f ? x1 : 0.f;
            y0 = y0 > 0.f ? y0 : 0.f; y1 = y1 > 0.f ? y1 : 0.f;
            *reinterpret_cast<float2*>(hA + 2 * p) = make_float2(x0, x1);
            *reinterpret_cast<float2*>(hB + 2 * p) = make_float2(y0, y1);
        }
    }
    __syncwarp();
    // matmul: o[t, co pair] = sum_c h[c,t] * g[c,co]
    {
        u64 oA[6], oB[6];
#pragma unroll
        for (int p = 0; p < 6; p++) { oA[p] = splat2(0.f); oB[p] = splat2(0.f); }
        for (int c = 0; c < 64; c++) {
            float2 g01 = unpack2(lds2(gs + c * 64 + 2 * lane));
            u64 Ga = splat2(g01.x), Gb = splat2(g01.y);
            const float* hr = hs + (local * 64 + c) * 14;
#pragma unroll
            for (int p = 0; p < 6; p++) {
                u64 hv = lds2(hr + 2 * p);
                fma2(oA[p], Ga, hv);
                fma2(oB[p], Gb, hv);
            }
        }
        __half2* outp = reinterpret_cast<__half2*>(g_xw1h);
#pragma unroll
        for (int p = 0; p < 6; p++) {
            float2 fa = unpack2(oA[p]);
            float2 fb = unpack2(oB[p]);
            outp[((size_t)(2 * p) * NN + n) * 32 + lane] = __floats2half2_rn(fa.x, fb.x);
            outp[((size_t)(2 * p + 1) * NN + n) * 32 + lane] = __floats2half2_rn(fa.y, fb.y);
        }
    }
}

// ---------------- layer 1 aggregation: 2 warps per node (t halves), prefetch ----------------
__global__ void k_agg1(const float* __restrict__ gb) {
    int gwid = (blockIdx.x * blockDim.x + threadIdx.x) >> 5;
    int lane = threadIdx.x & 31;
    if (gwid >= 2 * NN) return;
    int n = gwid >> 1;
    int t0 = (gwid & 1) * 6;
    int rs = g_rowptr[n], re = g_rowptr[n + 1];
    const __half2* base = reinterpret_cast<const __half2*>(g_xw1h) + (size_t)t0 * NN * 32 + lane;
    float a[12];
#pragma unroll
    for (int i = 0; i < 12; i++) a[i] = 0.f;
    int sN = 0; float wN = 0.f;
    if (rs < re) { sN = __ldg(&g_csrc[rs]); wN = __ldg(&g_cnorm[rs]); }
    for (int i = rs; i < re; i++) {
        int s = sN; float w = wN;
        if (i + 1 < re) { sN = __ldg(&g_csrc[i + 1]); wN = __ldg(&g_cnorm[i + 1]); }
        const __half2* p = base + (size_t)s * 32;
#pragma unroll
        for (int t = 0; t < 6; t++) {
            float2 f = __half22float2(__ldg(p + (size_t)t * NN * 32));
            a[2 * t]     += w * f.x;
            a[2 * t + 1] += w * f.y;
        }
    }
    float d = g_dis[n];
    float d2 = d * d;
    float b0 = gb[2 * lane], b1v = gb[2 * lane + 1];
    const __half2* pn = base + (size_t)n * 32;
#pragma unroll
    for (int t = 0; t < 6; t++) {
        float2 f = __half22float2(pn[(size_t)t * NN * 32]);
        float r0 = a[2 * t]     + d2 * f.x + b0;
        float r1 = a[2 * t + 1] + d2 * f.y + b1v;
        *reinterpret_cast<float2*>(g_agg1 + ((size_t)(t0 + t) * NN + n) * 64 + 2 * lane) = make_float2(r0, r1);
    }
}

// ---------------- layer 2: warp per node, co pairs; conv+IN+relu+Tmean+@gcn_w2 ----------------
#define L2N 8
__global__ void __launch_bounds__(32 * L2N, 2)
k_layer2(const float* __restrict__ w2, const float* __restrict__ b2,
         const float* __restrict__ gamma, const float* __restrict__ beta,
         const float* __restrict__ gw) {
    extern __shared__ float sm[];
    float* ws = sm;                     // [192][64]
    float* gs = ws + 192 * 64;          // [64][64]
    float* xa = gs + 64 * 64;           // L2N * [64][14]
    float* hb = xa + L2N * 64 * 14;     // L2N * [64]

    int tid = threadIdx.x;
    const int NT = 32 * L2N;
    for (int i = tid; i < 64 * 64 * 3; i += NT) {
        int co = i / 192, r = i % 192;
        ws[r * 64 + co] = w2[i];
    }
    for (int i = tid; i < 64 * 64; i += NT) gs[i] = gw[i];

    int local = tid >> 5;
    int lane = tid & 31;
    int n = blockIdx.x * L2N + local;
    {
        float* ra = xa + (local * 64 + lane) * 14;
        ra[0] = 0.f; ra[13] = 0.f;
        float* rb = xa + (local * 64 + lane + 32) * 14;
        rb[0] = 0.f; rb[13] = 0.f;
    }
    __syncthreads();

    // load node input: 12t x 64ci
    {
#pragma unroll
        for (int t = 0; t < TT; t++) {
            const float* src = g_agg1 + ((size_t)t * NN + n) * 64;
            xa[(local * 64 + lane) * 14 + t + 1] = src[lane];
            xa[(local * 64 + lane + 32) * 14 + t + 1] = src[lane + 32];
        }
    }
    __syncwarp();

    u64 accA[6], accB[6];
#pragma unroll
    for (int p = 0; p < 6; p++) { accA[p] = splat2(0.f); accB[p] = splat2(0.f); }
    for (int ci = 0; ci < 64; ci++) {
        const float* ra = xa + (local * 64 + ci) * 14;
        u64 pa[7];
#pragma unroll
        for (int j = 0; j < 7; j++) pa[j] = lds2(ra + 2 * j);
        float2 uu[7];
#pragma unroll
        for (int j = 0; j < 7; j++) uu[j] = unpack2(pa[j]);
        u64 pb[6];
#pragma unroll
        for (int p = 0; p < 6; p++) pb[p] = pack2(uu[p].y, uu[p + 1].x);
        float2 w0 = unpack2(lds2(ws + (ci * 3 + 0) * 64 + 2 * lane));
        float2 w1v = unpack2(lds2(ws + (ci * 3 + 1) * 64 + 2 * lane));
        float2 w2v = unpack2(lds2(ws + (ci * 3 + 2) * 64 + 2 * lane));
        u64 W0a = splat2(w0.x), W0b = splat2(w0.y);
        u64 W1a = splat2(w1v.x), W1b = splat2(w1v.y);
        u64 W2a = splat2(w2v.x), W2b = splat2(w2v.y);
#pragma unroll
        for (int p = 0; p < 6; p++) {
            fma2(accA[p], W0a, pa[p]);
            fma2(accB[p], W0b, pa[p]);
            fma2(accA[p], W1a, pb[p]);
            fma2(accB[p], W1b, pb[p]);
            fma2(accA[p], W2a, pa[p + 1]);
            fma2(accB[p], W2b, pa[p + 1]);
        }
    }
    // IN + relu + T-mean
    {
        float2 bb = *reinterpret_cast<const float2*>(b2 + 2 * lane);
        float2 gg = *reinterpret_cast<const float2*>(gamma + 2 * lane);
        float2 be = *reinterpret_cast<const float2*>(beta + 2 * lane);
        float aA[TT], aB[TT];
#pragma unroll
        for (int p = 0; p < 6; p++) {
            float2 fa = unpack2(accA[p]);
            float2 fb = unpack2(accB[p]);
            aA[2 * p] = fa.x + bb.x; aA[2 * p + 1] = fa.y + bb.x;
            aB[2 * p] = fb.x + bb.y; aB[2 * p + 1] = fb.y + bb.y;
        }
        float muA = 0.f, muB = 0.f;
#pragma unroll
        for (int t = 0; t < TT; t++) { muA += aA[t]; muB += aB[t]; }
        muA *= (1.0f / TT); muB *= (1.0f / TT);
        float vA = 0.f, vB = 0.f;
#pragma unroll
        for (int t = 0; t < TT; t++) {
            float dA = aA[t] - muA, dB = aB[t] - muB;
            vA += dA * dA; vB += dB * dB;
        }
        float scA = rsqrtf(vA * (1.0f / TT) + 1e-5f) * gg.x;
        float scB = rsqrtf(vB * (1.0f / TT) + 1e-5f) * gg.y;
        float sA = 0.f, sB = 0.f;
#pragma unroll
        for (int t = 0; t < TT; t++) {
            float x0 = (aA[t] - muA) * scA + be.x;
            float y0 = (aB[t] - muB) * scB + be.y;
            sA += (x0 > 0.f ? x0 : 0.f);
            sB += (y0 > 0.f ? y0 : 0.f);
        }
        *reinterpret_cast<float2*>(hb + local * 64 + 2 * lane) =
            make_float2(sA * (1.0f / TT), sB * (1.0f / TT));
    }
    __syncwarp();
    // mean(h) @ gcn_w2
    {
        const float* hl = hb + local * 64;
        u64 oacc = splat2(0.f);
        for (int c = 0; c < 64; c++) {
            u64 g01 = lds2(gs + c * 64 + 2 * lane);
            fma2(oacc, splat2(hl[c]), g01);
        }
        float2 o = unpack2(oacc);
        *reinterpret_cast<float2*>(g_xs2 + (size_t)n * 64 + 2 * lane) = o;
    }
}

// ---------------- layer 2 aggregation (T collapsed) + output linear ----------------
__global__ void k_agg2_out(const float* __restrict__ gb, const float* __restrict__ ow,
                           const float* __restrict__ ob, float* __restrict__ out) {
    __shared__ float ows[64 * 32];
    __shared__ float am[8][64];
    int tid = threadIdx.x;
    for (int i = tid; i < 64 * 32; i += 256) ows[i] = ow[i];
    __syncthreads();
    int wslot = tid >> 5;
    int lane = tid & 31;
    int n = blockIdx.x * 8 + wslot;
    if (n >= NN) return;
    int rs = g_rowptr[n], re = g_rowptr[n + 1];
    float a0 = 0.f, a1 = 0.f;
    int sN = 0; float wN = 0.f;
    if (rs < re) { sN = __ldg(&g_csrc[rs]); wN = __ldg(&g_cnorm[rs]); }
    for (int i = rs; i < re; i++) {
        int s = sN; float w = wN;
        if (i + 1 < re) { sN = __ldg(&g_csrc[i + 1]); wN = __ldg(&g_cnorm[i + 1]); }
        const float* p = g_xs2 + (size_t)s * 64;
        a0 += w * __ldg(p + lane);
        a1 += w * __ldg(p + lane + 32);
    }
    float d = g_dis[n];
    float d2 = d * d;
    const float* pn = g_xs2 + (size_t)n * 64;
    a0 += d2 * pn[lane] + gb[lane];
    a1 += d2 * pn[lane + 32] + gb[lane + 32];
    am[wslot][lane] = a0;
    am[wslot][lane + 32] = a1;
    __syncwarp();
    float s = ob[lane];
    const float* amr = am[wslot];
#pragma unroll 8
    for (int c = 0; c < 64; c++) s += amr[c] * ows[c * 32 + lane];
    out[(size_t)n * 32 + lane] = s;
}

// ---------------- launch ----------------
extern "C" void kernel_launch(void* const* d_in, const int* in_sizes, int n_in,
                              void* d_out, int out_size) {
    const float* x    = (const float*)d_in[0];
    const int*   ei   = (const int*)d_in[1];
    const float* ew   = (const float*)d_in[2];
    const float* cw1  = (const float*)d_in[3];
    const float* cb1  = (const float*)d_in[4];
    const float* ga1  = (const float*)d_in[5];
    const float* be1  = (const float*)d_in[6];
    const float* gw1  = (const float*)d_in[7];
    const float* gb1  = (const float*)d_in[8];
    const float* cw2  = (const float*)d_in[9];
    const float* cb2  = (const float*)d_in[10];
    const float* ga2  = (const float*)d_in[11];
    const float* be2  = (const float*)d_in[12];
    const float* gw2  = (const float*)d_in[13];
    const float* gb2  = (const float*)d_in[14];
    const float* ow   = (const float*)d_in[15];
    const float* ob   = (const float*)d_in[16];
    float* out = (float*)d_out;

    const int smem1 = (96 * 64 + 64 * 64 + L1N * 32 * 14 + L1N * 64 * 14) * 4;
    const int smem2 = (192 * 64 + 64 * 64 + L2N * 64 * 14 + L2N * 64) * 4;
    static bool attr_set = false;
    if (!attr_set) {
        cudaFuncSetAttribute(k_layer1, cudaFuncAttributeMaxDynamicSharedMemorySize, smem1);
        cudaFuncSetAttribute(k_layer2, cudaFuncAttributeMaxDynamicSharedMemorySize, smem2);
        attr_set = true;
    }

    // k_layer1 kept at launch slot 4 for positional ncu capture
    k_zero<<<(NN + 255) / 256, 256>>>();
    k_edge_hist<<<(EE + 255) / 256, 256>>>(ei, ew);
    k_scandis<<<1, 1024>>>();
    k_layer1<<<(NN + L1N - 1) / L1N, 32 * L1N, smem1>>>(x, cw1, cb1, ga1, be1, gw1);
    k_scatter<<<(EE + 255) / 256, 256>>>(ei, ew);
    k_agg1<<<(2 * NN * 32 + 255) / 256, 256>>>(gb1);
    k_layer2<<<(NN + L2N - 1) / L2N, 32 * L2N, smem2>>>(cw2, cb2, ga2, be2, gw2);
    k_agg2_out<<<(NN + 7) / 8, 256>>>(gb2, ow, ob, out);
}

// round 5
// speedup vs baseline: 1.7383x; 1.0065x over previous
#include <cuda_runtime.h>
#include <cuda_fp16.h>
#include <cuda_bf16.h>
#include <cstdint>

#define TT 12
#define NN 10000
#define EE 160000

typedef unsigned long long u64;

// ---------------- packed f32x2 helpers ----------------
__device__ __forceinline__ u64 splat2(float v) {
    u64 r; asm("mov.b64 %0,{%1,%1};" : "=l"(r) : "f"(v)); return r;
}
__device__ __forceinline__ u64 pack2(float lo, float hi) {
    u64 r; asm("mov.b64 %0,{%1,%2};" : "=l"(r) : "f"(lo), "f"(hi)); return r;
}
__device__ __forceinline__ void fma2(u64& acc, u64 a, u64 b) {
    asm("fma.rn.f32x2 %0,%1,%2,%0;" : "+l"(acc) : "l"(a), "l"(b));
}
__device__ __forceinline__ float2 unpack2(u64 v) {
    float2 f; asm("mov.b64 {%0,%1},%2;" : "=f"(f.x), "=f"(f.y) : "l"(v)); return f;
}
__device__ __forceinline__ u64 lds2(const float* p) {
    return *reinterpret_cast<const u64*>(p);
}
__device__ __forceinline__ float2 h2f2(unsigned int h) {
    return __half22float2(*reinterpret_cast<const __half2*>(&h));
}

// ---------------- device scratch ----------------
__device__ __half  g_xw1h[TT * NN * 64];
__device__ float   g_agg1[TT * NN * 64];
__device__ float   g_xs2[NN * 64];
__device__ float   g_deg[NN];
__device__ float   g_dis[NN];
__device__ int     g_cnt[NN];
__device__ int     g_fill[NN];
__device__ int     g_rowptr[NN + 1];
__device__ int     g_csrc[EE];
__device__ float   g_cnorm[EE];

// ---------------- graph preprocessing ----------------
__global__ void k_zero() {
    int i = blockIdx.x * blockDim.x + threadIdx.x;
    if (i < NN) { g_deg[i] = 0.f; g_cnt[i] = 0; g_fill[i] = 0; }
}

__global__ void k_edge_hist(const int* __restrict__ ei, const float* __restrict__ ew) {
    int e = blockIdx.x * blockDim.x + threadIdx.x;
    if (e >= EE) return;
    int d = ei[EE + e];
    atomicAdd(&g_deg[d], ew[e]);
    atomicAdd(&g_cnt[d], 1);
}

__global__ void k_scandis() {
    __shared__ int ssum[32];
    int tid = threadIdx.x;
    int lane = tid & 31;
    int wid = tid >> 5;
    const int per = 10;
    int start = tid * per;
    int vals[per];
    int local = 0;
#pragma unroll
    for (int k = 0; k < per; k++) {
        int idx = start + k;
        int v = 0;
        if (idx < NN) {
            v = g_cnt[idx];
            g_dis[idx] = rsqrtf(g_deg[idx] + 1.0f);
        }
        vals[k] = v; local += v;
    }
    int x = local;
#pragma unroll
    for (int off = 1; off < 32; off <<= 1) {
        int y = __shfl_up_sync(0xffffffffu, x, off);
        if (lane >= off) x += y;
    }
    if (lane == 31) ssum[wid] = x;
    __syncthreads();
    if (wid == 0) {
        int v = ssum[lane];
#pragma unroll
        for (int off = 1; off < 32; off <<= 1) {
            int y = __shfl_up_sync(0xffffffffu, v, off);
            if (lane >= off) v += y;
        }
        ssum[lane] = v;
    }
    __syncthreads();
    int run = (wid > 0 ? ssum[wid - 1] : 0) + x - local;
#pragma unroll
    for (int k = 0; k < per; k++) {
        int idx = start + k;
        if (idx < NN) g_rowptr[idx] = run;
        run += vals[k];
    }
    if (tid == 1023) g_rowptr[NN] = run;
}

__global__ void k_scatter(const int* __restrict__ ei, const float* __restrict__ ew) {
    int e = blockIdx.x * blockDim.x + threadIdx.x;
    if (e >= EE) return;
    int srcn = ei[e];
    int d = ei[EE + e];
    int pos = atomicAdd(&g_fill[d], 1);
    int idx = g_rowptr[d] + pos;
    g_csrc[idx] = srcn;
    g_cnorm[idx] = g_dis[srcn] * ew[e] * g_dis[d];
}

// ======================= layer 1 =======================
// warp per node; lane owns co pair (2l,2l+1); conv input staged as half2 t-pairs
#define L1N 8
// smem: ws 96*64 f32 (24KB) | hs L1N*64*14 f32 (28KB) | xh L1N*32 rows * 12 half2 (12KB)
__global__ void __launch_bounds__(32 * L1N, 3)
k_layer1(const float* __restrict__ x, const float* __restrict__ w1,
         const float* __restrict__ b1, const float* __restrict__ gamma,
         const float* __restrict__ beta, const float* __restrict__ gw) {
    extern __shared__ float sm[];
    float* ws = sm;                       // [96][64]
    float* hs = ws + 96 * 64;             // L1N*[64][14]
    unsigned int* xh = reinterpret_cast<unsigned int*>(hs + L1N * 64 * 14); // rows of 12 half2

    int tid = threadIdx.x;
    const int NT = 32 * L1N;
    for (int i = tid; i < 64 * 32 * 3; i += NT) {
        int co = i / 96, r = i % 96;
        ws[r * 64 + co] = w1[i];
    }
    int local = tid >> 5;
    int lane = tid & 31;
    int n = blockIdx.x * L1N + local;
    __syncthreads();

    // stage input: lane = ci; half2 slots j: (xpad[2j], xpad[2j+1]); xpad[k]=x[k-1], pads 0
    {
        unsigned int* row = xh + (local * 32 + lane) * 12;
        const float* xn = x + (size_t)n * 32 + lane;
        float xv[TT];
#pragma unroll
        for (int t = 0; t < TT; t++) xv[t] = xn[(size_t)t * NN * 32];
        __half2 s0 = __floats2half2_rn(0.f, xv[0]);
        row[0] = *reinterpret_cast<unsigned int*>(&s0);
#pragma unroll
        for (int j = 1; j <= 5; j++) {
            __half2 sj = __floats2half2_rn(xv[2 * j - 1], xv[2 * j]);
            row[j] = *reinterpret_cast<unsigned int*>(&sj);
        }
        __half2 s6 = __floats2half2_rn(xv[11], 0.f);
        row[6] = *reinterpret_cast<unsigned int*>(&s6);
        row[7] = 0u;
    }
    __syncwarp();

    // conv
    u64 accA[6], accB[6];
#pragma unroll
    for (int p = 0; p < 6; p++) { accA[p] = splat2(0.f); accB[p] = splat2(0.f); }
    for (int ci = 0; ci < 32; ci++) {
        const uint4* rp = reinterpret_cast<const uint4*>(xh + (local * 32 + ci) * 12);
        uint4 q0 = rp[0];
        uint4 q1 = rp[1];
        float2 f[7];
        f[0] = h2f2(q0.x); f[1] = h2f2(q0.y); f[2] = h2f2(q0.z); f[3] = h2f2(q0.w);
        f[4] = h2f2(q1.x); f[5] = h2f2(q1.y); f[6] = h2f2(q1.z);
        u64 pa[7], pb[6];
#pragma unroll
        for (int j = 0; j < 7; j++) pa[j] = pack2(f[j].x, f[j].y);
#pragma unroll
        for (int p = 0; p < 6; p++) pb[p] = pack2(f[p].y, f[p + 1].x);
        float2 w0 = unpack2(lds2(ws + (ci * 3 + 0) * 64 + 2 * lane));
        float2 w1v = unpack2(lds2(ws + (ci * 3 + 1) * 64 + 2 * lane));
        float2 w2 = unpack2(lds2(ws + (ci * 3 + 2) * 64 + 2 * lane));
        u64 W0a = splat2(w0.x), W0b = splat2(w0.y);
        u64 W1a = splat2(w1v.x), W1b = splat2(w1v.y);
        u64 W2a = splat2(w2.x), W2b = splat2(w2.y);
#pragma unroll
        for (int p = 0; p < 6; p++) {
            fma2(accA[p], W0a, pa[p]);
            fma2(accB[p], W0b, pa[p]);
            fma2(accA[p], W1a, pb[p]);
            fma2(accB[p], W1b, pb[p]);
            fma2(accA[p], W2a, pa[p + 1]);
            fma2(accB[p], W2b, pa[p + 1]);
        }
    }
    // IN + relu, write hs
    {
        float2 bb = *reinterpret_cast<const float2*>(b1 + 2 * lane);
        float2 gg = *reinterpret_cast<const float2*>(gamma + 2 * lane);
        float2 be = *reinterpret_cast<const float2*>(beta + 2 * lane);
        float aA[TT], aB[TT];
#pragma unroll
        for (int p = 0; p < 6; p++) {
            float2 fa = unpack2(accA[p]);
            float2 fb = unpack2(accB[p]);
            aA[2 * p] = fa.x + bb.x; aA[2 * p + 1] = fa.y + bb.x;
            aB[2 * p] = fb.x + bb.y; aB[2 * p + 1] = fb.y + bb.y;
        }
        float muA = 0.f, muB = 0.f;
#pragma unroll
        for (int t = 0; t < TT; t++) { muA += aA[t]; muB += aB[t]; }
        muA *= (1.0f / TT); muB *= (1.0f / TT);
        float vA = 0.f, vB = 0.f;
#pragma unroll
        for (int t = 0; t < TT; t++) {
            float dA = aA[t] - muA, dB = aB[t] - muB;
            vA += dA * dA; vB += dB * dB;
        }
        float scA = rsqrtf(vA * (1.0f / TT) + 1e-5f) * gg.x;
        float scB = rsqrtf(vB * (1.0f / TT) + 1e-5f) * gg.y;
        float* hA = hs + (local * 64 + 2 * lane) * 14;
        float* hB = hA + 14;
#pragma unroll
        for (int p = 0; p < 6; p++) {
            float x0 = (aA[2 * p] - muA) * scA + be.x;
            float x1 = (aA[2 * p + 1] - muA) * scA + be.x;
            float y0 = (aB[2 * p] - muB) * scB + be.y;
            float y1 = (aB[2 * p + 1] - muB) * scB + be.y;
            x0 = x0 > 0.f ? x0 : 0.f; x1 = x1 > 0.f ? x1 : 0.f;
            y0 = y0 > 0.f ? y0 : 0.f; y1 = y1 > 0.f ? y1 : 0.f;
            *reinterpret_cast<float2*>(hA + 2 * p) = make_float2(x0, x1);
            *reinterpret_cast<float2*>(hB + 2 * p) = make_float2(y0, y1);
        }
    }
    __syncwarp();
    // mm: g via LDG (L2-resident), h broadcast from smem
    {
        u64 oA[6], oB[6];
#pragma unroll
        for (int p = 0; p < 6; p++) { oA[p] = splat2(0.f); oB[p] = splat2(0.f); }
        const float2* gp = reinterpret_cast<const float2*>(gw) + lane;
        for (int c = 0; c < 64; c++) {
            float2 g01 = __ldg(gp + c * 32);
            u64 Ga = splat2(g01.x), Gb = splat2(g01.y);
            const float* hr = hs + (local * 64 + c) * 14;
#pragma unroll
            for (int p = 0; p < 6; p++) {
                u64 hv = lds2(hr + 2 * p);
                fma2(oA[p], Ga, hv);
                fma2(oB[p], Gb, hv);
            }
        }
        __half2* outp = reinterpret_cast<__half2*>(g_xw1h);
#pragma unroll
        for (int p = 0; p < 6; p++) {
            float2 fa = unpack2(oA[p]);
            float2 fb = unpack2(oB[p]);
            outp[((size_t)(2 * p) * NN + n) * 32 + lane] = __floats2half2_rn(fa.x, fb.x);
            outp[((size_t)(2 * p + 1) * NN + n) * 32 + lane] = __floats2half2_rn(fa.y, fb.y);
        }
    }
}

// ---------------- layer 1 aggregation: 2 warps per node (t halves), prefetch ----------------
__global__ void k_agg1(const float* __restrict__ gb) {
    int gwid = (blockIdx.x * blockDim.x + threadIdx.x) >> 5;
    int lane = threadIdx.x & 31;
    if (gwid >= 2 * NN) return;
    int n = gwid >> 1;
    int t0 = (gwid & 1) * 6;
    int rs = g_rowptr[n], re = g_rowptr[n + 1];
    const __half2* base = reinterpret_cast<const __half2*>(g_xw1h) + (size_t)t0 * NN * 32 + lane;
    float a[12];
#pragma unroll
    for (int i = 0; i < 12; i++) a[i] = 0.f;
    int sN = 0; float wN = 0.f;
    if (rs < re) { sN = __ldg(&g_csrc[rs]); wN = __ldg(&g_cnorm[rs]); }
    for (int i = rs; i < re; i++) {
        int s = sN; float w = wN;
        if (i + 1 < re) { sN = __ldg(&g_csrc[i + 1]); wN = __ldg(&g_cnorm[i + 1]); }
        const __half2* p = base + (size_t)s * 32;
#pragma unroll
        for (int t = 0; t < 6; t++) {
            float2 f = __half22float2(__ldg(p + (size_t)t * NN * 32));
            a[2 * t]     += w * f.x;
            a[2 * t + 1] += w * f.y;
        }
    }
    float d = g_dis[n];
    float d2 = d * d;
    float b0 = gb[2 * lane], b1v = gb[2 * lane + 1];
    const __half2* pn = base + (size_t)n * 32;
#pragma unroll
    for (int t = 0; t < 6; t++) {
        float2 f = __half22float2(pn[(size_t)t * NN * 32]);
        float r0 = a[2 * t]     + d2 * f.x + b0;
        float r1 = a[2 * t + 1] + d2 * f.y + b1v;
        *reinterpret_cast<float2*>(g_agg1 + ((size_t)(t0 + t) * NN + n) * 64 + 2 * lane) = make_float2(r0, r1);
    }
}

// ======================= layer 2 =======================
#define L2N 8
// smem: ws 192*64 f32 (48KB) | xh L2N*64 rows * 12 half2 (24KB) | hb L2N*64 f32 (2KB)
__global__ void __launch_bounds__(32 * L2N, 3)
k_layer2(const float* __restrict__ w2, const float* __restrict__ b2,
         const float* __restrict__ gamma, const float* __restrict__ beta,
         const float* __restrict__ gw) {
    extern __shared__ float sm[];
    float* ws = sm;                       // [192][64]
    float* hb = ws + 192 * 64;            // L2N*[64]
    unsigned int* xh = reinterpret_cast<unsigned int*>(hb + L2N * 64);

    int tid = threadIdx.x;
    const int NT = 32 * L2N;
    for (int i = tid; i < 64 * 64 * 3; i += NT) {
        int co = i / 192, r = i % 192;
        ws[r * 64 + co] = w2[i];
    }
    int local = tid >> 5;
    int lane = tid & 31;
    int n = blockIdx.x * L2N + local;
    __syncthreads();

    // stage input: lane handles ci = lane and lane+32
    {
        const float* a0p = g_agg1 + (size_t)n * 64 + lane;
#pragma unroll
        for (int half = 0; half < 2; half++) {
            unsigned int* row = xh + (local * 64 + lane + 32 * half) * 12;
            const float* src = a0p + 32 * half;
            float xv[TT];
#pragma unroll
            for (int t = 0; t < TT; t++) xv[t] = src[(size_t)t * NN * 64];
            __half2 s0 = __floats2half2_rn(0.f, xv[0]);
            row[0] = *reinterpret_cast<unsigned int*>(&s0);
#pragma unroll
            for (int j = 1; j <= 5; j++) {
                __half2 sj = __floats2half2_rn(xv[2 * j - 1], xv[2 * j]);
                row[j] = *reinterpret_cast<unsigned int*>(&sj);
            }
            __half2 s6 = __floats2half2_rn(xv[11], 0.f);
            row[6] = *reinterpret_cast<unsigned int*>(&s6);
            row[7] = 0u;
        }
    }
    __syncwarp();

    u64 accA[6], accB[6];
#pragma unroll
    for (int p = 0; p < 6; p++) { accA[p] = splat2(0.f); accB[p] = splat2(0.f); }
    for (int ci = 0; ci < 64; ci++) {
        const uint4* rp = reinterpret_cast<const uint4*>(xh + (local * 64 + ci) * 12);
        uint4 q0 = rp[0];
        uint4 q1 = rp[1];
        float2 f[7];
        f[0] = h2f2(q0.x); f[1] = h2f2(q0.y); f[2] = h2f2(q0.z); f[3] = h2f2(q0.w);
        f[4] = h2f2(q1.x); f[5] = h2f2(q1.y); f[6] = h2f2(q1.z);
        u64 pa[7], pb[6];
#pragma unroll
        for (int j = 0; j < 7; j++) pa[j] = pack2(f[j].x, f[j].y);
#pragma unroll
        for (int p = 0; p < 6; p++) pb[p] = pack2(f[p].y, f[p + 1].x);
        float2 w0 = unpack2(lds2(ws + (ci * 3 + 0) * 64 + 2 * lane));
        float2 w1v = unpack2(lds2(ws + (ci * 3 + 1) * 64 + 2 * lane));
        float2 w2v = unpack2(lds2(ws + (ci * 3 + 2) * 64 + 2 * lane));
        u64 W0a = splat2(w0.x), W0b = splat2(w0.y);
        u64 W1a = splat2(w1v.x), W1b = splat2(w1v.y);
        u64 W2a = splat2(w2v.x), W2b = splat2(w2v.y);
#pragma unroll
        for (int p = 0; p < 6; p++) {
            fma2(accA[p], W0a, pa[p]);
            fma2(accB[p], W0b, pa[p]);
            fma2(accA[p], W1a, pb[p]);
            fma2(accB[p], W1b, pb[p]);
            fma2(accA[p], W2a, pa[p + 1]);
            fma2(accB[p], W2b, pa[p + 1]);
        }
    }
    // IN + relu + T-mean
    {
        float2 bb = *reinterpret_cast<const float2*>(b2 + 2 * lane);
        float2 gg = *reinterpret_cast<const float2*>(gamma + 2 * lane);
        float2 be = *reinterpret_cast<const float2*>(beta + 2 * lane);
        float aA[TT], aB[TT];
#pragma unroll
        for (int p = 0; p < 6; p++) {
            float2 fa = unpack2(accA[p]);
            float2 fb = unpack2(accB[p]);
            aA[2 * p] = fa.x + bb.x; aA[2 * p + 1] = fa.y + bb.x;
            aB[2 * p] = fb.x + bb.y; aB[2 * p + 1] = fb.y + bb.y;
        }
        float muA = 0.f, muB = 0.f;
#pragma unroll
        for (int t = 0; t < TT; t++) { muA += aA[t]; muB += aB[t]; }
        muA *= (1.0f / TT); muB *= (1.0f / TT);
        float vA = 0.f, vB = 0.f;
#pragma unroll
        for (int t = 0; t < TT; t++) {
            float dA = aA[t] - muA, dB = aB[t] - muB;
            vA += dA * dA; vB += dB * dB;
        }
        float scA = rsqrtf(vA * (1.0f / TT) + 1e-5f) * gg.x;
        float scB = rsqrtf(vB * (1.0f / TT) + 1e-5f) * gg.y;
        float sA = 0.f, sB = 0.f;
#pragma unroll
        for (int t = 0; t < TT; t++) {
            float x0 = (aA[t] - muA) * scA + be.x;
            float y0 = (aB[t] - muB) * scB + be.y;
            sA += (x0 > 0.f ? x0 : 0.f);
            sB += (y0 > 0.f ? y0 : 0.f);
        }
        *reinterpret_cast<float2*>(hb + local * 64 + 2 * lane) =
            make_float2(sA * (1.0f / TT), sB * (1.0f / TT));
    }
    __syncwarp();
    // mean(h) @ gcn_w2 (g via LDG)
    {
        const float* hl = hb + local * 64;
        const float2* gp = reinterpret_cast<const float2*>(gw) + lane;
        u64 oacc = splat2(0.f);
        for (int c = 0; c < 64; c += 2) {
            float2 hc = unpack2(lds2(hl + c));
            float2 g0 = __ldg(gp + c * 32);
            float2 g1 = __ldg(gp + (c + 1) * 32);
            fma2(oacc, splat2(hc.x), pack2(g0.x, g0.y));
            fma2(oacc, splat2(hc.y), pack2(g1.x, g1.y));
        }
        float2 o = unpack2(oacc);
        *reinterpret_cast<float2*>(g_xs2 + (size_t)n * 64 + 2 * lane) = o;
    }
}

// ---------------- layer 2 aggregation (T collapsed) + output linear ----------------
__global__ void k_agg2_out(const float* __restrict__ gb, const float* __restrict__ ow,
                           const float* __restrict__ ob, float* __restrict__ out) {
    __shared__ float ows[64 * 32];
    __shared__ float am[8][64];
    int tid = threadIdx.x;
    for (int i = tid; i < 64 * 32; i += 256) ows[i] = ow[i];
    __syncthreads();
    int wslot = tid >> 5;
    int lane = tid & 31;
    int n = blockIdx.x * 8 + wslot;
    if (n >= NN) return;
    int rs = g_rowptr[n], re = g_rowptr[n + 1];
    float a0 = 0.f, a1 = 0.f;
    int sN = 0; float wN = 0.f;
    if (rs < re) { sN = __ldg(&g_csrc[rs]); wN = __ldg(&g_cnorm[rs]); }
    for (int i = rs; i < re; i++) {
        int s = sN; float w = wN;
        if (i + 1 < re) { sN = __ldg(&g_csrc[i + 1]); wN = __ldg(&g_cnorm[i + 1]); }
        const float* p = g_xs2 + (size_t)s * 64;
        a0 += w * __ldg(p + lane);
        a1 += w * __ldg(p + lane + 32);
    }
    float d = g_dis[n];
    float d2 = d * d;
    const float* pn = g_xs2 + (size_t)n * 64;
    a0 += d2 * pn[lane] + gb[lane];
    a1 += d2 * pn[lane + 32] + gb[lane + 32];
    am[wslot][lane] = a0;
    am[wslot][lane + 32] = a1;
    __syncwarp();
    float s = ob[lane];
    const float* amr = am[wslot];
#pragma unroll 8
    for (int c = 0; c < 64; c++) s += amr[c] * ows[c * 32 + lane];
    out[(size_t)n * 32 + lane] = s;
}

// ---------------- launch ----------------
extern "C" void kernel_launch(void* const* d_in, const int* in_sizes, int n_in,
                              void* d_out, int out_size) {
    const float* x    = (const float*)d_in[0];
    const int*   ei   = (const int*)d_in[1];
    const float* ew   = (const float*)d_in[2];
    const float* cw1  = (const float*)d_in[3];
    const float* cb1  = (const float*)d_in[4];
    const float* ga1  = (const float*)d_in[5];
    const float* be1  = (const float*)d_in[6];
    const float* gw1  = (const float*)d_in[7];
    const float* gb1  = (const float*)d_in[8];
    const float* cw2  = (const float*)d_in[9];
    const float* cb2  = (const float*)d_in[10];
    const float* ga2  = (const float*)d_in[11];
    const float* be2  = (const float*)d_in[12];
    const float* gw2  = (const float*)d_in[13];
    const float* gb2  = (const float*)d_in[14];
    const float* ow   = (const float*)d_in[15];
    const float* ob   = (const float*)d_in[16];
    float* out = (float*)d_out;

    const int smem1 = (96 * 64 + L1N * 64 * 14) * 4 + L1N * 32 * 12 * 4;  // 24KB+28KB+12KB = 64KB
    const int smem2 = (192 * 64 + L2N * 64) * 4 + L2N * 64 * 12 * 4;      // 48KB+2KB+24KB = 74KB
    static bool attr_set = false;
    if (!attr_set) {
        cudaFuncSetAttribute(k_layer1, cudaFuncAttributeMaxDynamicSharedMemorySize, smem1);
        cudaFuncSetAttribute(k_layer2, cudaFuncAttributeMaxDynamicSharedMemorySize, smem2);
        attr_set = true;
    }

    // k_layer1 kept at launch slot 4 for positional ncu capture
    k_zero<<<(NN + 255) / 256, 256>>>();
    k_edge_hist<<<(EE + 255) / 256, 256>>>(ei, ew);
    k_scandis<<<1, 1024>>>();
    k_layer1<<<(NN + L1N - 1) / L1N, 32 * L1N, smem1>>>(x, cw1, cb1, ga1, be1, gw1);
    k_scatter<<<(EE + 255) / 256, 256>>>(ei, ew);
    k_agg1<<<(2 * NN * 32 + 255) / 256, 256>>>(gb1);
    k_layer2<<<(NN + L2N - 1) / L2N, 32 * L2N, smem2>>>(cw2, cb2, ga2, be2, gw2);
    k_agg2_out<<<(NN + 7) / 8, 256>>>(gb2, ow, ob, out);
}

// round 6
// speedup vs baseline: 1.7809x; 1.0245x over previous
#include <cuda_runtime.h>
#include <cuda_fp16.h>
#include <cuda_bf16.h>
#include <cstdint>

#define TT 12
#define NN 10000
#define EE 160000

typedef unsigned long long u64;

__device__ __forceinline__ u64 splat2(float v) {
    u64 r; asm("mov.b64 %0,{%1,%1};" : "=l"(r) : "f"(v)); return r;
}
__device__ __forceinline__ u64 pack2(float lo, float hi) {
    u64 r; asm("mov.b64 %0,{%1,%2};" : "=l"(r) : "f"(lo), "f"(hi)); return r;
}
__device__ __forceinline__ void fma2(u64& acc, u64 a, u64 b) {
    asm("fma.rn.f32x2 %0,%1,%2,%0;" : "+l"(acc) : "l"(a), "l"(b));
}
__device__ __forceinline__ float2 unpack2(u64 v) {
    float2 f; asm("mov.b64 {%0,%1},%2;" : "=f"(f.x), "=f"(f.y) : "l"(v)); return f;
}

// ---------------- device scratch ----------------
__device__ __half  g_xw1h[TT * NN * 64];
__device__ float   g_agg1[TT * NN * 64];
__device__ float   g_xs2[NN * 64];
__device__ float   g_deg[NN];      // zero-init at load; re-zeroed by k_agg2_out
__device__ float   g_dis[NN];
__device__ int     g_cnt[NN];      // ditto
__device__ int     g_fill[NN];     // ditto
__device__ int     g_rowptr[NN + 1];
__device__ int     g_csrc[EE];
__device__ float   g_cnorm[EE];

// ---------------- graph preprocessing ----------------
__global__ void k_edge_hist(const int* __restrict__ ei, const float* __restrict__ ew) {
    int e = blockIdx.x * blockDim.x + threadIdx.x;
    if (e >= EE) return;
    int d = ei[EE + e];
    atomicAdd(&g_deg[d], ew[e]);
    atomicAdd(&g_cnt[d], 1);
}

__global__ void k_scandis() {
    __shared__ int ssum[32];
    int tid = threadIdx.x;
    int lane = tid & 31;
    int wid = tid >> 5;
    const int per = 10;
    int start = tid * per;
    int vals[per];
    int local = 0;
#pragma unroll
    for (int k = 0; k < per; k++) {
        int idx = start + k;
        int v = 0;
        if (idx < NN) {
            v = g_cnt[idx];
            g_dis[idx] = rsqrtf(g_deg[idx] + 1.0f);
        }
        vals[k] = v; local += v;
    }
    int x = local;
#pragma unroll
    for (int off = 1; off < 32; off <<= 1) {
        int y = __shfl_up_sync(0xffffffffu, x, off);
        if (lane >= off) x += y;
    }
    if (lane == 31) ssum[wid] = x;
    __syncthreads();
    if (wid == 0) {
        int v = ssum[lane];
#pragma unroll
        for (int off = 1; off < 32; off <<= 1) {
            int y = __shfl_up_sync(0xffffffffu, v, off);
            if (lane >= off) v += y;
        }
        ssum[lane] = v;
    }
    __syncthreads();
    int run = (wid > 0 ? ssum[wid - 1] : 0) + x - local;
#pragma unroll
    for (int k = 0; k < per; k++) {
        int idx = start + k;
        if (idx < NN) g_rowptr[idx] = run;
        run += vals[k];
    }
    if (tid == 1023) g_rowptr[NN] = run;
}

__global__ void k_scatter(const int* __restrict__ ei, const float* __restrict__ ew) {
    int e = blockIdx.x * blockDim.x + threadIdx.x;
    if (e >= EE) return;
    int srcn = ei[e];
    int d = ei[EE + e];
    int pos = atomicAdd(&g_fill[d], 1);
    int idx = g_rowptr[d] + pos;
    g_csrc[idx] = srcn;
    g_cnorm[idx] = g_dis[srcn] * ew[e] * g_dis[d];
}

// ======================= layer 1 =======================
// warp per node; lane owns co pair (2l,2l+1); fp32 staged inputs (aligned + shifted copy)
// smem: wsA [32][128] 16KB | wsB [32][64] 8KB | region L1N*896 floats 28KB  => 52KB
#define L1N 8
__global__ void __launch_bounds__(32 * L1N, 3)
k_layer1(const float* __restrict__ x, const float* __restrict__ w1,
         const float* __restrict__ b1, const float* __restrict__ gamma,
         const float* __restrict__ beta, const float* __restrict__ gw) {
    extern __shared__ float sm[];
    float* wsA = sm;                    // [32][128]
    float* wsB = wsA + 32 * 128;        // [32][64]
    float* regAll = wsB + 32 * 64;      // L1N regions of 896 floats

    int tid = threadIdx.x;
    const int NT = 32 * L1N;
    // pack weights: wsA[ci][l*4 + {0,1,2,3}] = {w0(2l),w0(2l+1),w1(2l),w1(2l+1)}, wsB[ci][l*2+{0,1}] = w2 pair
    for (int i = tid; i < 32 * 64; i += NT) {
        int ci = i >> 6, co = i & 63;
        int l = co >> 1, odd = co & 1;
        const float* wp = w1 + co * 96 + ci * 3;
        wsA[ci * 128 + l * 4 + odd] = wp[0];
        wsA[ci * 128 + l * 4 + 2 + odd] = wp[1];
        wsB[ci * 64 + l * 2 + odd] = wp[2];
    }
    int local = tid >> 5;
    int lane = tid & 31;
    int n = blockIdx.x * L1N + local;
    float* region = regAll + local * 896;   // xa: [32][16] | xb: +512 [32][12]; later hs: [64][12]
    __syncthreads();

    // stage input (lane = ci)
    {
        const float* xn = x + (size_t)n * 32 + lane;
        float xv[TT];
#pragma unroll
        for (int t = 0; t < TT; t++) xv[t] = xn[(size_t)t * NN * 32];
        float4* xa4 = reinterpret_cast<float4*>(region + lane * 16);
        xa4[0] = make_float4(0.f, xv[0], xv[1], xv[2]);
        xa4[1] = make_float4(xv[3], xv[4], xv[5], xv[6]);
        xa4[2] = make_float4(xv[7], xv[8], xv[9], xv[10]);
        xa4[3] = make_float4(xv[11], 0.f, 0.f, 0.f);
        float4* xb4 = reinterpret_cast<float4*>(region + 512 + lane * 12);
        xb4[0] = make_float4(xv[0], xv[1], xv[2], xv[3]);
        xb4[1] = make_float4(xv[4], xv[5], xv[6], xv[7]);
        xb4[2] = make_float4(xv[8], xv[9], xv[10], xv[11]);
    }
    __syncwarp();

    // conv
    u64 accA[6], accB[6];
#pragma unroll
    for (int p = 0; p < 6; p++) { accA[p] = splat2(0.f); accB[p] = splat2(0.f); }
    const float4* wsA4 = reinterpret_cast<const float4*>(wsA) + lane;
    const float2* wsB2 = reinterpret_cast<const float2*>(wsB) + lane;
    for (int ci = 0; ci < 32; ci++) {
        const float4* xaP = reinterpret_cast<const float4*>(region + ci * 16);
        const float4* xbP = reinterpret_cast<const float4*>(region + 512 + ci * 12);
        float4 A0 = xaP[0], A1 = xaP[1], A2 = xaP[2], A3 = xaP[3];
        float4 B0 = xbP[0], B1 = xbP[1], B2 = xbP[2];
        u64 pa[7] = {pack2(A0.x, A0.y), pack2(A0.z, A0.w), pack2(A1.x, A1.y), pack2(A1.z, A1.w),
                     pack2(A2.x, A2.y), pack2(A2.z, A2.w), pack2(A3.x, A3.y)};
        u64 pb[6] = {pack2(B0.x, B0.y), pack2(B0.z, B0.w), pack2(B1.x, B1.y),
                     pack2(B1.z, B1.w), pack2(B2.x, B2.y), pack2(B2.z, B2.w)};
        float4 wa = wsA4[ci * 32];
        float2 wb = wsB2[ci * 32];
        u64 W0a = splat2(wa.x), W0b = splat2(wa.y);
        u64 W1a = splat2(wa.z), W1b = splat2(wa.w);
        u64 W2a = splat2(wb.x), W2b = splat2(wb.y);
#pragma unroll
        for (int p = 0; p < 6; p++) {
            fma2(accA[p], W0a, pa[p]);
            fma2(accB[p], W0b, pa[p]);
            fma2(accA[p], W1a, pb[p]);
            fma2(accB[p], W1b, pb[p]);
            fma2(accA[p], W2a, pa[p + 1]);
            fma2(accB[p], W2b, pa[p + 1]);
        }
    }
    __syncwarp();   // all conv reads done before region reuse

    // IN + relu, write h rows (region reused: [64][12])
    {
        float2 bb = *reinterpret_cast<const float2*>(b1 + 2 * lane);
        float2 gg = *reinterpret_cast<const float2*>(gamma + 2 * lane);
        float2 be = *reinterpret_cast<const float2*>(beta + 2 * lane);
        float aA[TT], aB[TT];
#pragma unroll
        for (int p = 0; p < 6; p++) {
            float2 fa = unpack2(accA[p]);
            float2 fb = unpack2(accB[p]);
            aA[2 * p] = fa.x + bb.x; aA[2 * p + 1] = fa.y + bb.x;
            aB[2 * p] = fb.x + bb.y; aB[2 * p + 1] = fb.y + bb.y;
        }
        float muA = 0.f, muB = 0.f;
#pragma unroll
        for (int t = 0; t < TT; t++) { muA += aA[t]; muB += aB[t]; }
        muA *= (1.0f / TT); muB *= (1.0f / TT);
        float vA = 0.f, vB = 0.f;
#pragma unroll
        for (int t = 0; t < TT; t++) {
            float dA = aA[t] - muA, dB = aB[t] - muB;
            vA += dA * dA; vB += dB * dB;
        }
        float scA = rsqrtf(vA * (1.0f / TT) + 1e-5f) * gg.x;
        float scB = rsqrtf(vB * (1.0f / TT) + 1e-5f) * gg.y;
        float hA[TT], hB[TT];
#pragma unroll
        for (int t = 0; t < TT; t++) {
            float xv = (aA[t] - muA) * scA + be.x;
            float yv = (aB[t] - muB) * scB + be.y;
            hA[t] = xv > 0.f ? xv : 0.f;
            hB[t] = yv > 0.f ? yv : 0.f;
        }
        float4* hA4 = reinterpret_cast<float4*>(region + (2 * lane) * 12);
        float4* hB4 = reinterpret_cast<float4*>(region + (2 * lane + 1) * 12);
        hA4[0] = make_float4(hA[0], hA[1], hA[2], hA[3]);
        hA4[1] = make_float4(hA[4], hA[5], hA[6], hA[7]);
        hA4[2] = make_float4(hA[8], hA[9], hA[10], hA[11]);
        hB4[0] = make_float4(hB[0], hB[1], hB[2], hB[3]);
        hB4[1] = make_float4(hB[4], hB[5], hB[6], hB[7]);
        hB4[2] = make_float4(hB[8], hB[9], hB[10], hB[11]);
    }
    __syncwarp();

    // mm: o[t, co pair] = sum_c h[c,t] * g[c,co]; g via LDG float2
    {
        u64 oA[6], oB[6];
#pragma unroll
        for (int p = 0; p < 6; p++) { oA[p] = splat2(0.f); oB[p] = splat2(0.f); }
        const float2* gp = reinterpret_cast<const float2*>(gw) + lane;
        for (int c = 0; c < 64; c++) {
            const float4* hr = reinterpret_cast<const float4*>(region + c * 12);
            float4 h0 = hr[0], h1 = hr[1], h2 = hr[2];
            u64 hv[6] = {pack2(h0.x, h0.y), pack2(h0.z, h0.w), pack2(h1.x, h1.y),
                         pack2(h1.z, h1.w), pack2(h2.x, h2.y), pack2(h2.z, h2.w)};
            float2 g01 = __ldg(gp + c * 32);
            u64 Ga = splat2(g01.x), Gb = splat2(g01.y);
#pragma unroll
            for (int p = 0; p < 6; p++) {
                fma2(oA[p], Ga, hv[p]);
                fma2(oB[p], Gb, hv[p]);
            }
        }
        __half2* outp = reinterpret_cast<__half2*>(g_xw1h);
#pragma unroll
        for (int p = 0; p < 6; p++) {
            float2 fa = unpack2(oA[p]);
            float2 fb = unpack2(oB[p]);
            outp[((size_t)(2 * p) * NN + n) * 32 + lane] = __floats2half2_rn(fa.x, fb.x);
            outp[((size_t)(2 * p + 1) * NN + n) * 32 + lane] = __floats2half2_rn(fa.y, fb.y);
        }
    }
}

// ---------------- layer 1 aggregation: 2 warps per node (t halves), prefetch ----------------
__global__ void k_agg1(const float* __restrict__ gb) {
    int gwid = (blockIdx.x * blockDim.x + threadIdx.x) >> 5;
    int lane = threadIdx.x & 31;
    if (gwid >= 2 * NN) return;
    int n = gwid >> 1;
    int t0 = (gwid & 1) * 6;
    int rs = g_rowptr[n], re = g_rowptr[n + 1];
    const __half2* base = reinterpret_cast<const __half2*>(g_xw1h) + (size_t)t0 * NN * 32 + lane;
    float a[12];
#pragma unroll
    for (int i = 0; i < 12; i++) a[i] = 0.f;
    int sN = 0; float wN = 0.f;
    if (rs < re) { sN = __ldg(&g_csrc[rs]); wN = __ldg(&g_cnorm[rs]); }
    for (int i = rs; i < re; i++) {
        int s = sN; float w = wN;
        if (i + 1 < re) { sN = __ldg(&g_csrc[i + 1]); wN = __ldg(&g_cnorm[i + 1]); }
        const __half2* p = base + (size_t)s * 32;
#pragma unroll
        for (int t = 0; t < 6; t++) {
            float2 f = __half22float2(__ldg(p + (size_t)t * NN * 32));
            a[2 * t]     += w * f.x;
            a[2 * t + 1] += w * f.y;
        }
    }
    float d = g_dis[n];
    float d2 = d * d;
    float b0 = gb[2 * lane], b1v = gb[2 * lane + 1];
    const __half2* pn = base + (size_t)n * 32;
#pragma unroll
    for (int t = 0; t < 6; t++) {
        float2 f = __half22float2(pn[(size_t)t * NN * 32]);
        float r0 = a[2 * t]     + d2 * f.x + b0;
        float r1 = a[2 * t + 1] + d2 * f.y + b1v;
        *reinterpret_cast<float2*>(g_agg1 + ((size_t)(t0 + t) * NN + n) * 64 + 2 * lane) = make_float2(r0, r1);
    }
}

// ======================= layer 2 =======================
// smem: wsA [64][128] 32KB | wsB [64][64] 16KB | region L2N*1792 floats 56KB  => 104KB
#define L2N 8
__global__ void __launch_bounds__(32 * L2N, 2)
k_layer2(const float* __restrict__ w2, const float* __restrict__ b2,
         const float* __restrict__ gamma, const float* __restrict__ beta,
         const float* __restrict__ gw) {
    extern __shared__ float sm[];
    float* wsA = sm;                    // [64][128]
    float* wsB = wsA + 64 * 128;        // [64][64]
    float* regAll = wsB + 64 * 64;      // L2N regions of 1792 floats

    int tid = threadIdx.x;
    const int NT = 32 * L2N;
    for (int i = tid; i < 64 * 64; i += NT) {
        int ci = i >> 6, co = i & 63;
        int l = co >> 1, odd = co & 1;
        const float* wp = w2 + co * 192 + ci * 3;
        wsA[ci * 128 + l * 4 + odd] = wp[0];
        wsA[ci * 128 + l * 4 + 2 + odd] = wp[1];
        wsB[ci * 64 + l * 2 + odd] = wp[2];
    }
    int local = tid >> 5;
    int lane = tid & 31;
    int n = blockIdx.x * L2N + local;
    float* region = regAll + local * 1792;   // xa: [64][16] | xb: +1024 [64][12]; later hb [64]
    __syncthreads();

    // stage input: lane handles ci = lane and lane+32
#pragma unroll
    for (int half = 0; half < 2; half++) {
        int ci = lane + 32 * half;
        const float* src = g_agg1 + (size_t)n * 64 + ci;
        float xv[TT];
#pragma unroll
        for (int t = 0; t < TT; t++) xv[t] = src[(size_t)t * NN * 64];
        float4* xa4 = reinterpret_cast<float4*>(region + ci * 16);
        xa4[0] = make_float4(0.f, xv[0], xv[1], xv[2]);
        xa4[1] = make_float4(xv[3], xv[4], xv[5], xv[6]);
        xa4[2] = make_float4(xv[7], xv[8], xv[9], xv[10]);
        xa4[3] = make_float4(xv[11], 0.f, 0.f, 0.f);
        float4* xb4 = reinterpret_cast<float4*>(region + 1024 + ci * 12);
        xb4[0] = make_float4(xv[0], xv[1], xv[2], xv[3]);
        xb4[1] = make_float4(xv[4], xv[5], xv[6], xv[7]);
        xb4[2] = make_float4(xv[8], xv[9], xv[10], xv[11]);
    }
    __syncwarp();

    u64 accA[6], accB[6];
#pragma unroll
    for (int p = 0; p < 6; p++) { accA[p] = splat2(0.f); accB[p] = splat2(0.f); }
    const float4* wsA4 = reinterpret_cast<const float4*>(wsA) + lane;
    const float2* wsB2 = reinterpret_cast<const float2*>(wsB) + lane;
    for (int ci = 0; ci < 64; ci++) {
        const float4* xaP = reinterpret_cast<const float4*>(region + ci * 16);
        const float4* xbP = reinterpret_cast<const float4*>(region + 1024 + ci * 12);
        float4 A0 = xaP[0], A1 = xaP[1], A2 = xaP[2], A3 = xaP[3];
        float4 B0 = xbP[0], B1 = xbP[1], B2 = xbP[2];
        u64 pa[7] = {pack2(A0.x, A0.y), pack2(A0.z, A0.w), pack2(A1.x, A1.y), pack2(A1.z, A1.w),
                     pack2(A2.x, A2.y), pack2(A2.z, A2.w), pack2(A3.x, A3.y)};
        u64 pb[6] = {pack2(B0.x, B0.y), pack2(B0.z, B0.w), pack2(B1.x, B1.y),
                     pack2(B1.z, B1.w), pack2(B2.x, B2.y), pack2(B2.z, B2.w)};
        float4 wa = wsA4[ci * 32];
        float2 wb = wsB2[ci * 32];
        u64 W0a = splat2(wa.x), W0b = splat2(wa.y);
        u64 W1a = splat2(wa.z), W1b = splat2(wa.w);
        u64 W2a = splat2(wb.x), W2b = splat2(wb.y);
#pragma unroll
        for (int p = 0; p < 6; p++) {
            fma2(accA[p], W0a, pa[p]);
            fma2(accB[p], W0b, pa[p]);
            fma2(accA[p], W1a, pb[p]);
            fma2(accB[p], W1b, pb[p]);
            fma2(accA[p], W2a, pa[p + 1]);
            fma2(accB[p], W2b, pa[p + 1]);
        }
    }
    __syncwarp();

    // IN + relu + T-mean; store mean h into region[0..63]
    {
        float2 bb = *reinterpret_cast<const float2*>(b2 + 2 * lane);
        float2 gg = *reinterpret_cast<const float2*>(gamma + 2 * lane);
        float2 be = *reinterpret_cast<const float2*>(beta + 2 * lane);
        float aA[TT], aB[TT];
#pragma unroll
        for (int p = 0; p < 6; p++) {
            float2 fa = unpack2(accA[p]);
            float2 fb = unpack2(accB[p]);
            aA[2 * p] = fa.x + bb.x; aA[2 * p + 1] = fa.y + bb.x;
            aB[2 * p] = fb.x + bb.y; aB[2 * p + 1] = fb.y + bb.y;
        }
        float muA = 0.f, muB = 0.f;
#pragma unroll
        for (int t = 0; t < TT; t++) { muA += aA[t]; muB += aB[t]; }
        muA *= (1.0f / TT); muB *= (1.0f / TT);
        float vA = 0.f, vB = 0.f;
#pragma unroll
        for (int t = 0; t < TT; t++) {
            float dA = aA[t] - muA, dB = aB[t] - muB;
            vA += dA * dA; vB += dB * dB;
        }
        float scA = rsqrtf(vA * (1.0f / TT) + 1e-5f) * gg.x;
        float scB = rsqrtf(vB * (1.0f / TT) + 1e-5f) * gg.y;
        float sA = 0.f, sB = 0.f;
#pragma unroll
        for (int t = 0; t < TT; t++) {
            float x0 = (aA[t] - muA) * scA + be.x;
            float y0 = (aB[t] - muB) * scB + be.y;
            sA += (x0 > 0.f ? x0 : 0.f);
            sB += (y0 > 0.f ? y0 : 0.f);
        }
        *reinterpret_cast<float2*>(region + 2 * lane) = make_float2(sA * (1.0f / TT), sB * (1.0f / TT));
    }
    __syncwarp();
    // mean(h) @ gcn_w2 (g via LDG)
    {
        const float4* hl4 = reinterpret_cast<const float4*>(region);
        const float2* gp = reinterpret_cast<const float2*>(gw) + lane;
        u64 oacc = splat2(0.f);
        for (int c4 = 0; c4 < 16; c4++) {
            float4 hc = hl4[c4];
            int c = c4 * 4;
            float2 g0 = __ldg(gp + (c + 0) * 32);
            float2 g1 = __ldg(gp + (c + 1) * 32);
            float2 g2 = __ldg(gp + (c + 2) * 32);
            float2 g3 = __ldg(gp + (c + 3) * 32);
            fma2(oacc, splat2(hc.x), pack2(g0.x, g0.y));
            fma2(oacc, splat2(hc.y), pack2(g1.x, g1.y));
            fma2(oacc, splat2(hc.z), pack2(g2.x, g2.y));
            fma2(oacc, splat2(hc.w), pack2(g3.x, g3.y));
        }
        float2 o = unpack2(oacc);
        *reinterpret_cast<float2*>(g_xs2 + (size_t)n * 64 + 2 * lane) = o;
    }
}

// ---------------- layer 2 aggregation + output linear + scratch re-zero ----------------
__global__ void k_agg2_out(const float* __restrict__ gb, const float* __restrict__ ow,
                           const float* __restrict__ ob, float* __restrict__ out) {
    __shared__ float ows[64 * 32];
    __shared__ float am[8][64];
    int tid = threadIdx.x;
    // re-zero preprocessing scratch for the next graph replay
    if (tid < 8) {
        int idx = blockIdx.x * 8 + tid;
        if (idx < NN) { g_deg[idx] = 0.f; g_cnt[idx] = 0; g_fill[idx] = 0; }
    }
    for (int i = tid; i < 64 * 32; i += 256) ows[i] = ow[i];
    __syncthreads();
    int wslot = tid >> 5;
    int lane = tid & 31;
    int n = blockIdx.x * 8 + wslot;
    if (n >= NN) return;
    int rs = g_rowptr[n], re = g_rowptr[n + 1];
    float a0 = 0.f, a1 = 0.f;
    int sN = 0; float wN = 0.f;
    if (rs < re) { sN = __ldg(&g_csrc[rs]); wN = __ldg(&g_cnorm[rs]); }
    for (int i = rs; i < re; i++) {
        int s = sN; float w = wN;
        if (i + 1 < re) { sN = __ldg(&g_csrc[i + 1]); wN = __ldg(&g_cnorm[i + 1]); }
        const float* p = g_xs2 + (size_t)s * 64;
        a0 += w * __ldg(p + lane);
        a1 += w * __ldg(p + lane + 32);
    }
    float d = g_dis[n];
    float d2 = d * d;
    const float* pn = g_xs2 + (size_t)n * 64;
    a0 += d2 * pn[lane] + gb[lane];
    a1 += d2 * pn[lane + 32] + gb[lane + 32];
    am[wslot][lane] = a0;
    am[wslot][lane + 32] = a1;
    __syncwarp();
    float s = ob[lane];
    const float* amr = am[wslot];
#pragma unroll 8
    for (int c = 0; c < 64; c++) s += amr[c] * ows[c * 32 + lane];
    out[(size_t)n * 32 + lane] = s;
}

// ---------------- launch ----------------
extern "C" void kernel_launch(void* const* d_in, const int* in_sizes, int n_in,
                              void* d_out, int out_size) {
    const float* x    = (const float*)d_in[0];
    const int*   ei   = (const int*)d_in[1];
    const float* ew   = (const float*)d_in[2];
    const float* cw1  = (const float*)d_in[3];
    const float* cb1  = (const float*)d_in[4];
    const float* ga1  = (const float*)d_in[5];
    const float* be1  = (const float*)d_in[6];
    const float* gw1  = (const float*)d_in[7];
    const float* gb1  = (const float*)d_in[8];
    const float* cw2  = (const float*)d_in[9];
    const float* cb2  = (const float*)d_in[10];
    const float* ga2  = (const float*)d_in[11];
    const float* be2  = (const float*)d_in[12];
    const float* gw2  = (const float*)d_in[13];
    const float* gb2  = (const float*)d_in[14];
    const float* ow   = (const float*)d_in[15];
    const float* ob   = (const float*)d_in[16];
    float* out = (float*)d_out;

    const int smem1 = (32 * 128 + 32 * 64 + L1N * 896) * 4;    // 52KB
    const int smem2 = (64 * 128 + 64 * 64 + L2N * 1792) * 4;   // 104KB
    static bool attr_set = false;
    if (!attr_set) {
        cudaFuncSetAttribute(k_layer1, cudaFuncAttributeMaxDynamicSharedMemorySize, smem1);
        cudaFuncSetAttribute(k_layer2, cudaFuncAttributeMaxDynamicSharedMemorySize, smem2);
        attr_set = true;
    }

    // k_layer1 kept at launch slot 4 for positional ncu capture
    k_edge_hist<<<(EE + 255) / 256, 256>>>(ei, ew);
    k_scandis<<<1, 1024>>>();
    k_scatter<<<(EE + 255) / 256, 256>>>(ei, ew);
    k_layer1<<<(NN + L1N - 1) / L1N, 32 * L1N, smem1>>>(x, cw1, cb1, ga1, be1, gw1);
    k_agg1<<<(2 * NN * 32 + 255) / 256, 256>>>(gb1);
    k_layer2<<<(NN + L2N - 1) / L2N, 32 * L2N, smem2>>>(cw2, cb2, ga2, be2, gw2);
    k_agg2_out<<<(NN + 7) / 8, 256>>>(gb2, ow, ob, out);
}

// round 7
// speedup vs baseline: 1.8300x; 1.0275x over previous
#include <cuda_runtime.h>
#include <cuda_fp16.h>
#include <cuda_bf16.h>
#include <cstdint>

#define TT 12
#define NN 10000
#define EE 160000

typedef unsigned long long u64;

__device__ __forceinline__ u64 splat2(float v) {
    u64 r; asm("mov.b64 %0,{%1,%1};" : "=l"(r) : "f"(v)); return r;
}
__device__ __forceinline__ u64 pack2(float lo, float hi) {
    u64 r; asm("mov.b64 %0,{%1,%2};" : "=l"(r) : "f"(lo), "f"(hi)); return r;
}
__device__ __forceinline__ void fma2(u64& acc, u64 a, u64 b) {
    asm("fma.rn.f32x2 %0,%1,%2,%0;" : "+l"(acc) : "l"(a), "l"(b));
}
__device__ __forceinline__ float2 unpack2(u64 v) {
    float2 f; asm("mov.b64 {%0,%1},%2;" : "=f"(f.x), "=f"(f.y) : "l"(v)); return f;
}

// ---------------- device scratch ----------------
__device__ __half  g_h1h[TT * NN * 64];    // layer1 h (post IN+relu), fp16 co-pair interleaved
__device__ __half  g_agg1h[TT * NN * 64];  // aggregated h, fp16 same layout
__device__ float   g_xs2[NN * 64];
__device__ float   g_w2c[64 * 64 * 3];     // composed conv2 weights  [co][c][k]
__device__ float   g_S0[64];               // boundary bias corrections
__device__ float   g_S2[64];
__device__ float   g_deg[NN];              // zero-init at load; re-zeroed by k_agg2_out
__device__ float   g_dis[NN];
__device__ int     g_cnt[NN];
__device__ int     g_fill[NN];
__device__ int     g_rowptr[NN + 1];
__device__ int     g_csrc[EE];
__device__ float   g_cnorm[EE];

// ---------------- weight composition: W2' = w2 ∘ gcn_w1, S0/S2 from gb1 ----------------
__global__ void k_compose(const float* __restrict__ w2, const float* __restrict__ gw1,
                          const float* __restrict__ gb1) {
    int idx = blockIdx.x * blockDim.x + threadIdx.x;
    if (idx < 4096) {
        int co = idx >> 6, c = idx & 63;
        const float* w2r = w2 + co * 192;      // [d][3]
        const float* g1r = gw1 + c * 64;       // [d]
        float s0 = 0.f, s1 = 0.f, s2 = 0.f;
        for (int d = 0; d < 64; d++) {
            float g = g1r[d];
            s0 += w2r[d * 3 + 0] * g;
            s1 += w2r[d * 3 + 1] * g;
            s2 += w2r[d * 3 + 2] * g;
        }
        float* o = g_w2c + co * 192 + c * 3;
        o[0] = s0; o[1] = s1; o[2] = s2;
    }
    if (idx >= 4096 && idx < 4096 + 128) {
        int j = idx - 4096;
        int co = j & 63, which = j >> 6;   // 0 -> S0 (k=0), 1 -> S2 (k=2)
        const float* w2r = w2 + co * 192;
        float s = 0.f;
        int k = which ? 2 : 0;
        for (int d = 0; d < 64; d++) s += w2r[d * 3 + k] * gb1[d];
        if (which) g_S2[co] = s; else g_S0[co] = s;
    }
}

// ---------------- graph preprocessing ----------------
__global__ void k_edge_hist(const int* __restrict__ ei, const float* __restrict__ ew) {
    int e = blockIdx.x * blockDim.x + threadIdx.x;
    if (e >= EE) return;
    int d = ei[EE + e];
    atomicAdd(&g_deg[d], ew[e]);
    atomicAdd(&g_cnt[d], 1);
}

__global__ void k_scandis() {
    __shared__ int ssum[32];
    int tid = threadIdx.x;
    int lane = tid & 31;
    int wid = tid >> 5;
    const int per = 10;
    int start = tid * per;
    int vals[per];
    int local = 0;
#pragma unroll
    for (int k = 0; k < per; k++) {
        int idx = start + k;
        int v = 0;
        if (idx < NN) {
            v = g_cnt[idx];
            g_dis[idx] = rsqrtf(g_deg[idx] + 1.0f);
        }
        vals[k] = v; local += v;
    }
    int x = local;
#pragma unroll
    for (int off = 1; off < 32; off <<= 1) {
        int y = __shfl_up_sync(0xffffffffu, x, off);
        if (lane >= off) x += y;
    }
    if (lane == 31) ssum[wid] = x;
    __syncthreads();
    if (wid == 0) {
        int v = ssum[lane];
#pragma unroll
        for (int off = 1; off < 32; off <<= 1) {
            int y = __shfl_up_sync(0xffffffffu, v, off);
            if (lane >= off) v += y;
        }
        ssum[lane] = v;
    }
    __syncthreads();
    int run = (wid > 0 ? ssum[wid - 1] : 0) + x - local;
#pragma unroll
    for (int k = 0; k < per; k++) {
        int idx = start + k;
        if (idx < NN) g_rowptr[idx] = run;
        run += vals[k];
    }
    if (tid == 1023) g_rowptr[NN] = run;
}

__global__ void k_scatter(const int* __restrict__ ei, const float* __restrict__ ew) {
    int e = blockIdx.x * blockDim.x + threadIdx.x;
    if (e >= EE) return;
    int srcn = ei[e];
    int d = ei[EE + e];
    int pos = atomicAdd(&g_fill[d], 1);
    int idx = g_rowptr[d] + pos;
    g_csrc[idx] = srcn;
    g_cnorm[idx] = g_dis[srcn] * ew[e] * g_dis[d];
}

// ======================= layer 1: conv + IN + relu only (mm composed away) =======================
// warp per node; lane owns co pair (2l,2l+1); fp32 staged inputs (aligned + shifted copy)
// smem: wsA [32][128] 16KB | wsB [32][64] 8KB | region L1N*896 floats 28KB => 52KB
#define L1N 8
__global__ void __launch_bounds__(32 * L1N, 3)
k_layer1(const float* __restrict__ x, const float* __restrict__ w1,
         const float* __restrict__ gamma, const float* __restrict__ beta) {
    extern __shared__ float sm[];
    float* wsA = sm;
    float* wsB = wsA + 32 * 128;
    float* regAll = wsB + 32 * 64;

    int tid = threadIdx.x;
    const int NT = 32 * L1N;
    for (int i = tid; i < 32 * 64; i += NT) {
        int ci = i >> 6, co = i & 63;
        int l = co >> 1, odd = co & 1;
        const float* wp = w1 + co * 96 + ci * 3;
        wsA[ci * 128 + l * 4 + odd] = wp[0];
        wsA[ci * 128 + l * 4 + 2 + odd] = wp[1];
        wsB[ci * 64 + l * 2 + odd] = wp[2];
    }
    int local = tid >> 5;
    int lane = tid & 31;
    int n = blockIdx.x * L1N + local;
    float* region = regAll + local * 896;   // xa [32][16] | xb +512 [32][12]
    __syncthreads();

    {
        const float* xn = x + (size_t)n * 32 + lane;
        float xv[TT];
#pragma unroll
        for (int t = 0; t < TT; t++) xv[t] = xn[(size_t)t * NN * 32];
        float4* xa4 = reinterpret_cast<float4*>(region + lane * 16);
        xa4[0] = make_float4(0.f, xv[0], xv[1], xv[2]);
        xa4[1] = make_float4(xv[3], xv[4], xv[5], xv[6]);
        xa4[2] = make_float4(xv[7], xv[8], xv[9], xv[10]);
        xa4[3] = make_float4(xv[11], 0.f, 0.f, 0.f);
        float4* xb4 = reinterpret_cast<float4*>(region + 512 + lane * 12);
        xb4[0] = make_float4(xv[0], xv[1], xv[2], xv[3]);
        xb4[1] = make_float4(xv[4], xv[5], xv[6], xv[7]);
        xb4[2] = make_float4(xv[8], xv[9], xv[10], xv[11]);
    }
    __syncwarp();

    u64 accA[6], accB[6];
#pragma unroll
    for (int p = 0; p < 6; p++) { accA[p] = splat2(0.f); accB[p] = splat2(0.f); }
    const float4* wsA4 = reinterpret_cast<const float4*>(wsA) + lane;
    const float2* wsB2 = reinterpret_cast<const float2*>(wsB) + lane;
    for (int ci = 0; ci < 32; ci++) {
        const float4* xaP = reinterpret_cast<const float4*>(region + ci * 16);
        const float4* xbP = reinterpret_cast<const float4*>(region + 512 + ci * 12);
        float4 A0 = xaP[0], A1 = xaP[1], A2 = xaP[2], A3 = xaP[3];
        float4 B0 = xbP[0], B1 = xbP[1], B2 = xbP[2];
        u64 pa[7] = {pack2(A0.x, A0.y), pack2(A0.z, A0.w), pack2(A1.x, A1.y), pack2(A1.z, A1.w),
                     pack2(A2.x, A2.y), pack2(A2.z, A2.w), pack2(A3.x, A3.y)};
        u64 pb[6] = {pack2(B0.x, B0.y), pack2(B0.z, B0.w), pack2(B1.x, B1.y),
                     pack2(B1.z, B1.w), pack2(B2.x, B2.y), pack2(B2.z, B2.w)};
        float4 wa = wsA4[ci * 32];
        float2 wb = wsB2[ci * 32];
        u64 W0a = splat2(wa.x), W0b = splat2(wa.y);
        u64 W1a = splat2(wa.z), W1b = splat2(wa.w);
        u64 W2a = splat2(wb.x), W2b = splat2(wb.y);
#pragma unroll
        for (int p = 0; p < 6; p++) {
            fma2(accA[p], W0a, pa[p]);
            fma2(accB[p], W0b, pa[p]);
            fma2(accA[p], W1a, pb[p]);
            fma2(accB[p], W1b, pb[p]);
            fma2(accA[p], W2a, pa[p + 1]);
            fma2(accB[p], W2b, pa[p + 1]);
        }
    }

    // IN + relu (conv bias constant over t -> cancels in IN), write h fp16 interleaved
    {
        float2 gg = *reinterpret_cast<const float2*>(gamma + 2 * lane);
        float2 be = *reinterpret_cast<const float2*>(beta + 2 * lane);
        float aA[TT], aB[TT];
#pragma unroll
        for (int p = 0; p < 6; p++) {
            float2 fa = unpack2(accA[p]);
            float2 fb = unpack2(accB[p]);
            aA[2 * p] = fa.x; aA[2 * p + 1] = fa.y;
            aB[2 * p] = fb.x; aB[2 * p + 1] = fb.y;
        }
        float muA = 0.f, muB = 0.f;
#pragma unroll
        for (int t = 0; t < TT; t++) { muA += aA[t]; muB += aB[t]; }
        muA *= (1.0f / TT); muB *= (1.0f / TT);
        float vA = 0.f, vB = 0.f;
#pragma unroll
        for (int t = 0; t < TT; t++) {
            float dA = aA[t] - muA, dB = aB[t] - muB;
            vA += dA * dA; vB += dB * dB;
        }
        float scA = rsqrtf(vA * (1.0f / TT) + 1e-5f) * gg.x;
        float scB = rsqrtf(vB * (1.0f / TT) + 1e-5f) * gg.y;
        __half2* outp = reinterpret_cast<__half2*>(g_h1h);
#pragma unroll
        for (int t = 0; t < TT; t++) {
            float xv = (aA[t] - muA) * scA + be.x;
            float yv = (aB[t] - muB) * scB + be.y;
            xv = xv > 0.f ? xv : 0.f;
            yv = yv > 0.f ? yv : 0.f;
            outp[((size_t)t * NN + n) * 32 + lane] = __floats2half2_rn(xv, yv);
        }
    }
}

// ---------------- layer 1 aggregation: gathers h, no bias (folded into layer2) ----------------
__global__ void k_agg1() {
    int gwid = (blockIdx.x * blockDim.x + threadIdx.x) >> 5;
    int lane = threadIdx.x & 31;
    if (gwid >= 2 * NN) return;
    int n = gwid >> 1;
    int t0 = (gwid & 1) * 6;
    int rs = g_rowptr[n], re = g_rowptr[n + 1];
    const __half2* base = reinterpret_cast<const __half2*>(g_h1h) + (size_t)t0 * NN * 32 + lane;
    float a[12];
#pragma unroll
    for (int i = 0; i < 12; i++) a[i] = 0.f;
    int sN = 0; float wN = 0.f;
    if (rs < re) { sN = __ldg(&g_csrc[rs]); wN = __ldg(&g_cnorm[rs]); }
    for (int i = rs; i < re; i++) {
        int s = sN; float w = wN;
        if (i + 1 < re) { sN = __ldg(&g_csrc[i + 1]); wN = __ldg(&g_cnorm[i + 1]); }
        const __half2* p = base + (size_t)s * 32;
#pragma unroll
        for (int t = 0; t < 6; t++) {
            float2 f = __half22float2(__ldg(p + (size_t)t * NN * 32));
            a[2 * t]     += w * f.x;
            a[2 * t + 1] += w * f.y;
        }
    }
    float d = g_dis[n];
    float d2 = d * d;
    const __half2* pn = base + (size_t)n * 32;
    __half2* outh = reinterpret_cast<__half2*>(g_agg1h) + (size_t)t0 * NN * 32 + (size_t)n * 32 + lane;
#pragma unroll
    for (int t = 0; t < 6; t++) {
        float2 f = __half22float2(pn[(size_t)t * NN * 32]);
        float r0 = a[2 * t]     + d2 * f.x;
        float r1 = a[2 * t + 1] + d2 * f.y;
        outh[(size_t)t * NN * 32] = __floats2half2_rn(r0, r1);
    }
}

// ======================= layer 2: composed conv + boundary bias + IN + relu + Tmean + @gcn_w2 ====
// smem: wsA [64][128] 32KB | wsB [64][64] 16KB | region L2N*1792 floats 56KB => 104KB
#define L2N 8
__global__ void __launch_bounds__(32 * L2N, 2)
k_layer2(const float* __restrict__ gamma, const float* __restrict__ beta,
         const float* __restrict__ gw) {
    extern __shared__ float sm[];
    float* wsA = sm;
    float* wsB = wsA + 64 * 128;
    float* regAll = wsB + 64 * 64;

    int tid = threadIdx.x;
    const int NT = 32 * L2N;
    for (int i = tid; i < 64 * 64; i += NT) {
        int ci = i >> 6, co = i & 63;
        int l = co >> 1, odd = co & 1;
        const float* wp = g_w2c + co * 192 + ci * 3;
        wsA[ci * 128 + l * 4 + odd] = wp[0];
        wsA[ci * 128 + l * 4 + 2 + odd] = wp[1];
        wsB[ci * 64 + l * 2 + odd] = wp[2];
    }
    int local = tid >> 5;
    int lane = tid & 31;
    int n = blockIdx.x * L2N + local;
    float* region = regAll + local * 1792;   // xa [64][16] | xb +1024 [64][12]
    __syncthreads();

    // stage: lane loads half2 pair = channels (2l, 2l+1)
    {
        const __half2* src = reinterpret_cast<const __half2*>(g_agg1h) + (size_t)n * 32 + lane;
        float xv0[TT], xv1[TT];
#pragma unroll
        for (int t = 0; t < TT; t++) {
            float2 f = __half22float2(src[(size_t)t * NN * 32]);
            xv0[t] = f.x; xv1[t] = f.y;
        }
        int ci0 = 2 * lane;
#pragma unroll
        for (int half = 0; half < 2; half++) {
            const float* xv = half ? xv1 : xv0;
            int ci = ci0 + half;
            float4* xa4 = reinterpret_cast<float4*>(region + ci * 16);
            xa4[0] = make_float4(0.f, xv[0], xv[1], xv[2]);
            xa4[1] = make_float4(xv[3], xv[4], xv[5], xv[6]);
            xa4[2] = make_float4(xv[7], xv[8], xv[9], xv[10]);
            xa4[3] = make_float4(xv[11], 0.f, 0.f, 0.f);
            float4* xb4 = reinterpret_cast<float4*>(region + 1024 + ci * 12);
            xb4[0] = make_float4(xv[0], xv[1], xv[2], xv[3]);
            xb4[1] = make_float4(xv[4], xv[5], xv[6], xv[7]);
            xb4[2] = make_float4(xv[8], xv[9], xv[10], xv[11]);
        }
    }
    __syncwarp();

    u64 accA[6], accB[6];
#pragma unroll
    for (int p = 0; p < 6; p++) { accA[p] = splat2(0.f); accB[p] = splat2(0.f); }
    const float4* wsA4 = reinterpret_cast<const float4*>(wsA) + lane;
    const float2* wsB2 = reinterpret_cast<const float2*>(wsB) + lane;
    for (int ci = 0; ci < 64; ci++) {
        const float4* xaP = reinterpret_cast<const float4*>(region + ci * 16);
        const float4* xbP = reinterpret_cast<const float4*>(region + 1024 + ci * 12);
        float4 A0 = xaP[0], A1 = xaP[1], A2 = xaP[2], A3 = xaP[3];
        float4 B0 = xbP[0], B1 = xbP[1], B2 = xbP[2];
        u64 pa[7] = {pack2(A0.x, A0.y), pack2(A0.z, A0.w), pack2(A1.x, A1.y), pack2(A1.z, A1.w),
                     pack2(A2.x, A2.y), pack2(A2.z, A2.w), pack2(A3.x, A3.y)};
        u64 pb[6] = {pack2(B0.x, B0.y), pack2(B0.z, B0.w), pack2(B1.x, B1.y),
                     pack2(B1.z, B1.w), pack2(B2.x, B2.y), pack2(B2.z, B2.w)};
        float4 wa = wsA4[ci * 32];
        float2 wb = wsB2[ci * 32];
        u64 W0a = splat2(wa.x), W0b = splat2(wa.y);
        u64 W1a = splat2(wa.z), W1b = splat2(wa.w);
        u64 W2a = splat2(wb.x), W2b = splat2(wb.y);
#pragma unroll
        for (int p = 0; p < 6; p++) {
            fma2(accA[p], W0a, pa[p]);
            fma2(accB[p], W0b, pa[p]);
            fma2(accA[p], W1a, pb[p]);
            fma2(accB[p], W1b, pb[p]);
            fma2(accA[p], W2a, pa[p + 1]);
            fma2(accB[p], W2b, pa[p + 1]);
        }
    }
    __syncwarp();

    // boundary bias corrections + IN + relu + T-mean; mean h -> region[0..63]
    {
        float2 gg = *reinterpret_cast<const float2*>(gamma + 2 * lane);
        float2 be = *reinterpret_cast<const float2*>(beta + 2 * lane);
        float2 s0 = *reinterpret_cast<const float2*>(g_S0 + 2 * lane);
        float2 s2 = *reinterpret_cast<const float2*>(g_S2 + 2 * lane);
        float aA[TT], aB[TT];
#pragma unroll
        for (int p = 0; p < 6; p++) {
            float2 fa = unpack2(accA[p]);
            float2 fb = unpack2(accB[p]);
            aA[2 * p] = fa.x; aA[2 * p + 1] = fa.y;
            aB[2 * p] = fb.x; aB[2 * p + 1] = fb.y;
        }
        // at t=0 the k=0 tap read zero-pad instead of bias-carrying input: subtract S0
        // at t=11 the k=2 tap: subtract S2   (all constant-in-t bias terms cancel in IN)
        aA[0] -= s0.x; aB[0] -= s0.y;
        aA[11] -= s2.x; aB[11] -= s2.y;
        float muA = 0.f, muB = 0.f;
#pragma unroll
        for (int t = 0; t < TT; t++) { muA += aA[t]; muB += aB[t]; }
        muA *= (1.0f / TT); muB *= (1.0f / TT);
        float vA = 0.f, vB = 0.f;
#pragma unroll
        for (int t = 0; t < TT; t++) {
            float dA = aA[t] - muA, dB = aB[t] - muB;
            vA += dA * dA; vB += dB * dB;
        }
        float scA = rsqrtf(vA * (1.0f / TT) + 1e-5f) * gg.x;
        float scB = rsqrtf(vB * (1.0f / TT) + 1e-5f) * gg.y;
        float sA = 0.f, sB = 0.f;
#pragma unroll
        for (int t = 0; t < TT; t++) {
            float x0 = (aA[t] - muA) * scA + be.x;
            float y0 = (aB[t] - muB) * scB + be.y;
            sA += (x0 > 0.f ? x0 : 0.f);
            sB += (y0 > 0.f ? y0 : 0.f);
        }
        *reinterpret_cast<float2*>(region + 2 * lane) = make_float2(sA * (1.0f / TT), sB * (1.0f / TT));
    }
    __syncwarp();
    {
        const float4* hl4 = reinterpret_cast<const float4*>(region);
        const float2* gp = reinterpret_cast<const float2*>(gw) + lane;
        u64 oacc = splat2(0.f);
        for (int c4 = 0; c4 < 16; c4++) {
            float4 hc = hl4[c4];
            int c = c4 * 4;
            float2 g0 = __ldg(gp + (c + 0) * 32);
            float2 g1 = __ldg(gp + (c + 1) * 32);
            float2 g2 = __ldg(gp + (c + 2) * 32);
            float2 g3 = __ldg(gp + (c + 3) * 32);
            fma2(oacc, splat2(hc.x), pack2(g0.x, g0.y));
            fma2(oacc, splat2(hc.y), pack2(g1.x, g1.y));
            fma2(oacc, splat2(hc.z), pack2(g2.x, g2.y));
            fma2(oacc, splat2(hc.w), pack2(g3.x, g3.y));
        }
        float2 o = unpack2(oacc);
        *reinterpret_cast<float2*>(g_xs2 + (size_t)n * 64 + 2 * lane) = o;
    }
}

// ---------------- layer 2 aggregation + output linear + scratch re-zero ----------------
__global__ void k_agg2_out(const float* __restrict__ gb, const float* __restrict__ ow,
                           const float* __restrict__ ob, float* __restrict__ out) {
    __shared__ float ows[64 * 32];
    __shared__ float am[8][64];
    int tid = threadIdx.x;
    if (tid < 8) {
        int idx = blockIdx.x * 8 + tid;
        if (idx < NN) { g_deg[idx] = 0.f; g_cnt[idx] = 0; g_fill[idx] = 0; }
    }
    for (int i = tid; i < 64 * 32; i += 256) ows[i] = ow[i];
    __syncthreads();
    int wslot = tid >> 5;
    int lane = tid & 31;
    int n = blockIdx.x * 8 + wslot;
    if (n >= NN) return;
    int rs = g_rowptr[n], re = g_rowptr[n + 1];
    float a0 = 0.f, a1 = 0.f;
    int sN = 0; float wN = 0.f;
    if (rs < re) { sN = __ldg(&g_csrc[rs]); wN = __ldg(&g_cnorm[rs]); }
    for (int i = rs; i < re; i++) {
        int s = sN; float w = wN;
        if (i + 1 < re) { sN = __ldg(&g_csrc[i + 1]); wN = __ldg(&g_cnorm[i + 1]); }
        const float* p = g_xs2 + (size_t)s * 64;
        a0 += w * __ldg(p + lane);
        a1 += w * __ldg(p + lane + 32);
    }
    float d = g_dis[n];
    float d2 = d * d;
    const float* pn = g_xs2 + (size_t)n * 64;
    a0 += d2 * pn[lane] + gb[lane];
    a1 += d2 * pn[lane + 32] + gb[lane + 32];
    am[wslot][lane] = a0;
    am[wslot][lane + 32] = a1;
    __syncwarp();
    float s = ob[lane];
    const float* amr = am[wslot];
#pragma unroll 8
    for (int c = 0; c < 64; c++) s += amr[c] * ows[c * 32 + lane];
    out[(size_t)n * 32 + lane] = s;
}

// ---------------- launch ----------------
extern "C" void kernel_launch(void* const* d_in, const int* in_sizes, int n_in,
                              void* d_out, int out_size) {
    const float* x    = (const float*)d_in[0];
    const int*   ei   = (const int*)d_in[1];
    const float* ew   = (const float*)d_in[2];
    const float* cw1  = (const float*)d_in[3];
    const float* ga1  = (const float*)d_in[5];
    const float* be1  = (const float*)d_in[6];
    const float* gw1  = (const float*)d_in[7];
    const float* gb1  = (const float*)d_in[8];
    const float* cw2  = (const float*)d_in[9];
    const float* ga2  = (const float*)d_in[11];
    const float* be2  = (const float*)d_in[12];
    const float* gw2  = (const float*)d_in[13];
    const float* gb2  = (const float*)d_in[14];
    const float* ow   = (const float*)d_in[15];
    const float* ob   = (const float*)d_in[16];
    float* out = (float*)d_out;

    const int smem1 = (32 * 128 + 32 * 64 + L1N * 896) * 4;    // 52KB
    const int smem2 = (64 * 128 + 64 * 64 + L2N * 1792) * 4;   // 104KB
    static bool attr_set = false;
    if (!attr_set) {
        cudaFuncSetAttribute(k_layer1, cudaFuncAttributeMaxDynamicSharedMemorySize, smem1);
        cudaFuncSetAttribute(k_layer2, cudaFuncAttributeMaxDynamicSharedMemorySize, smem2);
        attr_set = true;
    }

    // k_layer1 kept at launch slot 4 for positional ncu capture
    k_compose<<<17, 256>>>(cw2, gw1, gb1);
    k_edge_hist<<<(EE + 255) / 256, 256>>>(ei, ew);
    k_scandis<<<1, 1024>>>();
    k_layer1<<<(NN + L1N - 1) / L1N, 32 * L1N, smem1>>>(x, cw1, ga1, be1);
    k_scatter<<<(EE + 255) / 256, 256>>>(ei, ew);
    k_agg1<<<(2 * NN * 32 + 255) / 256, 256>>>();
    k_layer2<<<(NN + L2N - 1) / L2N, 32 * L2N, smem2>>>(ga2, be2, gw2);
    k_agg2_out<<<(NN + 7) / 8, 256>>>(gb2, ow, ob, out);
}

// round 8
// speedup vs baseline: 2.9450x; 1.6093x over previous
#include <cuda_runtime.h>
#include <cuda_fp16.h>
#include <cuda_bf16.h>
#include <cstdint>

#define TT 12
#define NN 10000
#define EE 160000

typedef unsigned long long u64;

__device__ __forceinline__ u64 splat2(float v) {
    u64 r; asm("mov.b64 %0,{%1,%1};" : "=l"(r) : "f"(v)); return r;
}
__device__ __forceinline__ u64 pack2(float lo, float hi) {
    u64 r; asm("mov.b64 %0,{%1,%2};" : "=l"(r) : "f"(lo), "f"(hi)); return r;
}
__device__ __forceinline__ void fma2(u64& acc, u64 a, u64 b) {
    asm("fma.rn.f32x2 %0,%1,%2,%0;" : "+l"(acc) : "l"(a), "l"(b));
}
__device__ __forceinline__ float2 unpack2(u64 v) {
    float2 f; asm("mov.b64 {%0,%1},%2;" : "=f"(f.x), "=f"(f.y) : "l"(v)); return f;
}

// ---------------- device scratch ----------------
__device__ __half  g_h1h[TT * NN * 64];    // layer1 h (post IN+relu), fp16 co-pair interleaved
__device__ __half  g_agg1h[TT * NN * 64];  // aggregated h, fp16 same layout
__device__ float   g_xs2[NN * 64];
__device__ __half  g_w2h[64 * 192];        // composed conv2 weights fp16, [co][K], K = tap*64+ci
__device__ float   g_S0[64];               // boundary bias corrections
__device__ float   g_S2[64];
__device__ float   g_deg[NN];              // zero-init at load; re-zeroed by k_agg2_out
__device__ float   g_dis[NN];
__device__ int     g_cnt[NN];
__device__ int     g_fill[NN];
__device__ int     g_rowptr[NN + 1];
__device__ int     g_csrc[EE];
__device__ float   g_cnorm[EE];

// ---------------- weight composition: W2' = w2 ∘ gcn_w1 (fp16, tap-major K), S0/S2 from gb1 ----
__global__ void k_compose(const float* __restrict__ w2, const float* __restrict__ gw1,
                          const float* __restrict__ gb1) {
    int idx = blockIdx.x * blockDim.x + threadIdx.x;
    if (idx < 4096) {
        int co = idx >> 6, c = idx & 63;
        const float* w2r = w2 + co * 192;      // [d][3]
        const float* g1r = gw1 + c * 64;       // [d]
        float s0 = 0.f, s1 = 0.f, s2 = 0.f;
        for (int d = 0; d < 64; d++) {
            float g = g1r[d];
            s0 += w2r[d * 3 + 0] * g;
            s1 += w2r[d * 3 + 1] * g;
            s2 += w2r[d * 3 + 2] * g;
        }
        g_w2h[co * 192 +   0 + c] = __float2half_rn(s0);
        g_w2h[co * 192 +  64 + c] = __float2half_rn(s1);
        g_w2h[co * 192 + 128 + c] = __float2half_rn(s2);
    }
    if (idx >= 4096 && idx < 4096 + 128) {
        int j = idx - 4096;
        int co = j & 63, which = j >> 6;
        const float* w2r = w2 + co * 192;
        float s = 0.f;
        int k = which ? 2 : 0;
        for (int d = 0; d < 64; d++) s += w2r[d * 3 + k] * gb1[d];
        if (which) g_S2[co] = s; else g_S0[co] = s;
    }
}

// ---------------- graph preprocessing ----------------
__global__ void k_edge_hist(const int* __restrict__ ei, const float* __restrict__ ew) {
    int e = blockIdx.x * blockDim.x + threadIdx.x;
    if (e >= EE) return;
    int d = ei[EE + e];
    atomicAdd(&g_deg[d], ew[e]);
    atomicAdd(&g_cnt[d], 1);
}

__global__ void k_scandis() {
    __shared__ int ssum[32];
    int tid = threadIdx.x;
    int lane = tid & 31;
    int wid = tid >> 5;
    const int per = 10;
    int start = tid * per;
    int vals[per];
    int local = 0;
#pragma unroll
    for (int k = 0; k < per; k++) {
        int idx = start + k;
        int v = 0;
        if (idx < NN) {
            v = g_cnt[idx];
            g_dis[idx] = rsqrtf(g_deg[idx] + 1.0f);
        }
        vals[k] = v; local += v;
    }
    int x = local;
#pragma unroll
    for (int off = 1; off < 32; off <<= 1) {
        int y = __shfl_up_sync(0xffffffffu, x, off);
        if (lane >= off) x += y;
    }
    if (lane == 31) ssum[wid] = x;
    __syncthreads();
    if (wid == 0) {
        int v = ssum[lane];
#pragma unroll
        for (int off = 1; off < 32; off <<= 1) {
            int y = __shfl_up_sync(0xffffffffu, v, off);
            if (lane >= off) v += y;
        }
        ssum[lane] = v;
    }
    __syncthreads();
    int run = (wid > 0 ? ssum[wid - 1] : 0) + x - local;
#pragma unroll
    for (int k = 0; k < per; k++) {
        int idx = start + k;
        if (idx < NN) g_rowptr[idx] = run;
        run += vals[k];
    }
    if (tid == 1023) g_rowptr[NN] = run;
}

__global__ void k_scatter(const int* __restrict__ ei, const float* __restrict__ ew) {
    int e = blockIdx.x * blockDim.x + threadIdx.x;
    if (e >= EE) return;
    int srcn = ei[e];
    int d = ei[EE + e];
    int pos = atomicAdd(&g_fill[d], 1);
    int idx = g_rowptr[d] + pos;
    g_csrc[idx] = srcn;
    g_cnorm[idx] = g_dis[srcn] * ew[e] * g_dis[d];
}

// ======================= layer 1: conv + IN + relu (unchanged FFMA2) =======================
#define L1N 8
__global__ void __launch_bounds__(32 * L1N, 3)
k_layer1(const float* __restrict__ x, const float* __restrict__ w1,
         const float* __restrict__ gamma, const float* __restrict__ beta) {
    extern __shared__ float sm[];
    float* wsA = sm;
    float* wsB = wsA + 32 * 128;
    float* regAll = wsB + 32 * 64;

    int tid = threadIdx.x;
    const int NT = 32 * L1N;
    for (int i = tid; i < 32 * 64; i += NT) {
        int ci = i >> 6, co = i & 63;
        int l = co >> 1, odd = co & 1;
        const float* wp = w1 + co * 96 + ci * 3;
        wsA[ci * 128 + l * 4 + odd] = wp[0];
        wsA[ci * 128 + l * 4 + 2 + odd] = wp[1];
        wsB[ci * 64 + l * 2 + odd] = wp[2];
    }
    int local = tid >> 5;
    int lane = tid & 31;
    int n = blockIdx.x * L1N + local;
    float* region = regAll + local * 896;
    __syncthreads();

    {
        const float* xn = x + (size_t)n * 32 + lane;
        float xv[TT];
#pragma unroll
        for (int t = 0; t < TT; t++) xv[t] = xn[(size_t)t * NN * 32];
        float4* xa4 = reinterpret_cast<float4*>(region + lane * 16);
        xa4[0] = make_float4(0.f, xv[0], xv[1], xv[2]);
        xa4[1] = make_float4(xv[3], xv[4], xv[5], xv[6]);
        xa4[2] = make_float4(xv[7], xv[8], xv[9], xv[10]);
        xa4[3] = make_float4(xv[11], 0.f, 0.f, 0.f);
        float4* xb4 = reinterpret_cast<float4*>(region + 512 + lane * 12);
        xb4[0] = make_float4(xv[0], xv[1], xv[2], xv[3]);
        xb4[1] = make_float4(xv[4], xv[5], xv[6], xv[7]);
        xb4[2] = make_float4(xv[8], xv[9], xv[10], xv[11]);
    }
    __syncwarp();

    u64 accA[6], accB[6];
#pragma unroll
    for (int p = 0; p < 6; p++) { accA[p] = splat2(0.f); accB[p] = splat2(0.f); }
    const float4* wsA4 = reinterpret_cast<const float4*>(wsA) + lane;
    const float2* wsB2 = reinterpret_cast<const float2*>(wsB) + lane;
    for (int ci = 0; ci < 32; ci++) {
        const float4* xaP = reinterpret_cast<const float4*>(region + ci * 16);
        const float4* xbP = reinterpret_cast<const float4*>(region + 512 + ci * 12);
        float4 A0 = xaP[0], A1 = xaP[1], A2 = xaP[2], A3 = xaP[3];
        float4 B0 = xbP[0], B1 = xbP[1], B2 = xbP[2];
        u64 pa[7] = {pack2(A0.x, A0.y), pack2(A0.z, A0.w), pack2(A1.x, A1.y), pack2(A1.z, A1.w),
                     pack2(A2.x, A2.y), pack2(A2.z, A2.w), pack2(A3.x, A3.y)};
        u64 pb[6] = {pack2(B0.x, B0.y), pack2(B0.z, B0.w), pack2(B1.x, B1.y),
                     pack2(B1.z, B1.w), pack2(B2.x, B2.y), pack2(B2.z, B2.w)};
        float4 wa = wsA4[ci * 32];
        float2 wb = wsB2[ci * 32];
        u64 W0a = splat2(wa.x), W0b = splat2(wa.y);
        u64 W1a = splat2(wa.z), W1b = splat2(wa.w);
        u64 W2a = splat2(wb.x), W2b = splat2(wb.y);
#pragma unroll
        for (int p = 0; p < 6; p++) {
            fma2(accA[p], W0a, pa[p]);
            fma2(accB[p], W0b, pa[p]);
            fma2(accA[p], W1a, pb[p]);
            fma2(accB[p], W1b, pb[p]);
            fma2(accA[p], W2a, pa[p + 1]);
            fma2(accB[p], W2b, pa[p + 1]);
        }
    }

    {
        float2 gg = *reinterpret_cast<const float2*>(gamma + 2 * lane);
        float2 be = *reinterpret_cast<const float2*>(beta + 2 * lane);
        float aA[TT], aB[TT];
#pragma unroll
        for (int p = 0; p < 6; p++) {
            float2 fa = unpack2(accA[p]);
            float2 fb = unpack2(accB[p]);
            aA[2 * p] = fa.x; aA[2 * p + 1] = fa.y;
            aB[2 * p] = fb.x; aB[2 * p + 1] = fb.y;
        }
        float muA = 0.f, muB = 0.f;
#pragma unroll
        for (int t = 0; t < TT; t++) { muA += aA[t]; muB += aB[t]; }
        muA *= (1.0f / TT); muB *= (1.0f / TT);
        float vA = 0.f, vB = 0.f;
#pragma unroll
        for (int t = 0; t < TT; t++) {
            float dA = aA[t] - muA, dB = aB[t] - muB;
            vA += dA * dA; vB += dB * dB;
        }
        float scA = rsqrtf(vA * (1.0f / TT) + 1e-5f) * gg.x;
        float scB = rsqrtf(vB * (1.0f / TT) + 1e-5f) * gg.y;
        __half2* outp = reinterpret_cast<__half2*>(g_h1h);
#pragma unroll
        for (int t = 0; t < TT; t++) {
            float xv = (aA[t] - muA) * scA + be.x;
            float yv = (aB[t] - muB) * scB + be.y;
            xv = xv > 0.f ? xv : 0.f;
            yv = yv > 0.f ? yv : 0.f;
            outp[((size_t)t * NN + n) * 32 + lane] = __floats2half2_rn(xv, yv);
        }
    }
}

// ---------------- layer 1 aggregation ----------------
__global__ void k_agg1() {
    int gwid = (blockIdx.x * blockDim.x + threadIdx.x) >> 5;
    int lane = threadIdx.x & 31;
    if (gwid >= 2 * NN) return;
    int n = gwid >> 1;
    int t0 = (gwid & 1) * 6;
    int rs = g_rowptr[n], re = g_rowptr[n + 1];
    const __half2* base = reinterpret_cast<const __half2*>(g_h1h) + (size_t)t0 * NN * 32 + lane;
    float a[12];
#pragma unroll
    for (int i = 0; i < 12; i++) a[i] = 0.f;
    int sN = 0; float wN = 0.f;
    if (rs < re) { sN = __ldg(&g_csrc[rs]); wN = __ldg(&g_cnorm[rs]); }
    for (int i = rs; i < re; i++) {
        int s = sN; float w = wN;
        if (i + 1 < re) { sN = __ldg(&g_csrc[i + 1]); wN = __ldg(&g_cnorm[i + 1]); }
        const __half2* p = base + (size_t)s * 32;
#pragma unroll
        for (int t = 0; t < 6; t++) {
            float2 f = __half22float2(__ldg(p + (size_t)t * NN * 32));
            a[2 * t]     += w * f.x;
            a[2 * t + 1] += w * f.y;
        }
    }
    float d = g_dis[n];
    float d2 = d * d;
    const __half2* pn = base + (size_t)n * 32;
    __half2* outh = reinterpret_cast<__half2*>(g_agg1h) + (size_t)t0 * NN * 32 + (size_t)n * 32 + lane;
#pragma unroll
    for (int t = 0; t < 6; t++) {
        float2 f = __half22float2(pn[(size_t)t * NN * 32]);
        float r0 = a[2 * t]     + d2 * f.x;
        float r1 = a[2 * t + 1] + d2 * f.y;
        outh[(size_t)t * NN * 32] = __floats2half2_rn(r0, r1);
    }
}

// ======================= layer 2: tensor-core MMA conv + IN + relu + Tmean + @gcn_w2 ========
// warp per node. D[64co x 16t] = A[64 x 192] @ B[192 x 16] via m16n8k16, K tap-major.
// smem: params 256f (1KB) | aw half[64][200] (25.6KB) | xrow u32[L2N][14][36] (16.1KB) | hbar (2KB)
#define L2N 8
__global__ void __launch_bounds__(32 * L2N, 3)
k_layer2(const float* __restrict__ gamma, const float* __restrict__ beta,
         const float* __restrict__ gw) {
    extern __shared__ float sm[];
    float* gms = sm;             // 64
    float* bes = gms + 64;       // 64
    float* s0s = bes + 64;       // 64
    float* s2s = s0s + 64;       // 64
    unsigned int* aw = reinterpret_cast<unsigned int*>(s2s + 64);   // [64][100] u32 (200 halves/row)
    unsigned int* xr = aw + 64 * 100;                                // L2N * 14*36
    float* hbar = reinterpret_cast<float*>(xr + L2N * 14 * 36);      // L2N * 64

    int tid = threadIdx.x;
    const int NT = 32 * L2N;
    for (int i = tid; i < 64; i += NT) {
        gms[i] = gamma[i]; bes[i] = beta[i]; s0s[i] = g_S0[i]; s2s[i] = g_S2[i];
    }
    const unsigned int* wsrc = reinterpret_cast<const unsigned int*>(g_w2h);
    for (int i = tid; i < 64 * 96; i += NT) {
        int co = i / 96, k2 = i % 96;
        aw[co * 100 + k2] = wsrc[i];
    }
    int local = tid >> 5;
    int lane = tid & 31;
    int gid = lane >> 2;     // groupID
    int tig = lane & 3;      // thread-in-group
    int n = blockIdx.x * L2N + local;
    unsigned int* xrow = xr + local * (14 * 36);

    // stage x: xrow[tp][l] = half2(agg ch 2l,2l+1) at t = tp-1; tp=0,13 zero pads
    {
        const __half2* src = reinterpret_cast<const __half2*>(g_agg1h) + (size_t)n * 32 + lane;
        xrow[0 * 36 + lane] = 0u;
        xrow[13 * 36 + lane] = 0u;
#pragma unroll
        for (int t = 0; t < TT; t++) {
            __half2 v = src[(size_t)t * NN * 32];
            xrow[(t + 1) * 36 + lane] = *reinterpret_cast<unsigned int*>(&v);
        }
    }
    __syncthreads();

    float d0[4][4], d1[4][4];
#pragma unroll
    for (int m = 0; m < 4; m++)
#pragma unroll
        for (int r = 0; r < 4; r++) { d0[m][r] = 0.f; d1[m][r] = 0.f; }

#pragma unroll
    for (int kt = 0; kt < 12; kt++) {
        int tap = kt >> 2;
        int l0 = (kt & 3) * 8;
        int tp0 = gid + tap;                        // <= 9
        int tp1 = gid + 8 + tap; if (tp1 > 13) tp1 = 13;
        unsigned int b00 = xrow[tp0 * 36 + l0 + tig];
        unsigned int b01 = xrow[tp0 * 36 + l0 + tig + 4];
        unsigned int b10 = xrow[tp1 * 36 + l0 + tig];
        unsigned int b11 = xrow[tp1 * 36 + l0 + tig + 4];
#pragma unroll
        for (int mt = 0; mt < 4; mt++) {
            const unsigned int* ap = aw + (mt * 16 + gid) * 100 + kt * 8 + tig;
            unsigned int a0 = ap[0];
            unsigned int a1 = ap[8 * 100];
            unsigned int a2 = ap[4];
            unsigned int a3 = ap[8 * 100 + 4];
            asm volatile("mma.sync.aligned.m16n8k16.row.col.f32.f16.f16.f32 "
                "{%0,%1,%2,%3}, {%4,%5,%6,%7}, {%8,%9}, {%0,%1,%2,%3};"
                : "+f"(d0[mt][0]), "+f"(d0[mt][1]), "+f"(d0[mt][2]), "+f"(d0[mt][3])
                : "r"(a0), "r"(a1), "r"(a2), "r"(a3), "r"(b00), "r"(b01));
            asm volatile("mma.sync.aligned.m16n8k16.row.col.f32.f16.f16.f32 "
                "{%0,%1,%2,%3}, {%4,%5,%6,%7}, {%8,%9}, {%0,%1,%2,%3};"
                : "+f"(d1[mt][0]), "+f"(d1[mt][1]), "+f"(d1[mt][2]), "+f"(d1[mt][3])
                : "r"(a0), "r"(a1), "r"(a2), "r"(a3), "r"(b10), "r"(b11));
        }
    }

    // epilogue: per (mt, row half) => one co; lane holds t = {2tig, 2tig+1, 8+2tig, 9+2tig}
    // (t >= 12 masked). IN stats via 4-lane shfl reductions.
#pragma unroll
    for (int mt = 0; mt < 4; mt++) {
#pragma unroll
        for (int part = 0; part < 2; part++) {
            int co = mt * 16 + gid + part * 8;
            float v0 = part ? d0[mt][2] : d0[mt][0];   // t = 2 tig
            float v1 = part ? d0[mt][3] : d0[mt][1];   // t = 2 tig + 1
            float v2 = part ? d1[mt][2] : d1[mt][0];   // t = 8 + 2 tig
            float v3 = part ? d1[mt][3] : d1[mt][1];   // t = 9 + 2 tig
            if (tig == 0) v0 -= s0s[co];               // t = 0 boundary correction
            if (tig == 1) v3 -= s2s[co];               // t = 11 boundary correction
            bool val2 = tig < 2;
            float s = v0 + v1 + (val2 ? v2 + v3 : 0.f);
            s += __shfl_xor_sync(0xffffffffu, s, 1);
            s += __shfl_xor_sync(0xffffffffu, s, 2);
            float mu = s * (1.0f / 12.0f);
            float e0 = v0 - mu, e1 = v1 - mu, e2 = v2 - mu, e3 = v3 - mu;
            float q = e0 * e0 + e1 * e1 + (val2 ? e2 * e2 + e3 * e3 : 0.f);
            q += __shfl_xor_sync(0xffffffffu, q, 1);
            q += __shfl_xor_sync(0xffffffffu, q, 2);
            float sc = rsqrtf(q * (1.0f / 12.0f) + 1e-5f) * gms[co];
            float bt = bes[co];
            float r = fmaxf(e0 * sc + bt, 0.f) + fmaxf(e1 * sc + bt, 0.f)
                    + (val2 ? fmaxf(e2 * sc + bt, 0.f) + fmaxf(e3 * sc + bt, 0.f) : 0.f);
            r += __shfl_xor_sync(0xffffffffu, r, 1);
            r += __shfl_xor_sync(0xffffffffu, r, 2);
            if (tig == 0) hbar[local * 64 + co] = r * (1.0f / 12.0f);
        }
    }
    __syncwarp();

    // mean(h) @ gcn_w2 (g via LDG)
    {
        const float4* hl4 = reinterpret_cast<const float4*>(hbar + local * 64);
        const float2* gp = reinterpret_cast<const float2*>(gw) + lane;
        u64 oacc = splat2(0.f);
        for (int c4 = 0; c4 < 16; c4++) {
            float4 hc = hl4[c4];
            int c = c4 * 4;
            float2 g0 = __ldg(gp + (c + 0) * 32);
            float2 g1 = __ldg(gp + (c + 1) * 32);
            float2 g2 = __ldg(gp + (c + 2) * 32);
            float2 g3 = __ldg(gp + (c + 3) * 32);
            fma2(oacc, splat2(hc.x), pack2(g0.x, g0.y));
            fma2(oacc, splat2(hc.y), pack2(g1.x, g1.y));
            fma2(oacc, splat2(hc.z), pack2(g2.x, g2.y));
            fma2(oacc, splat2(hc.w), pack2(g3.x, g3.y));
        }
        float2 o = unpack2(oacc);
        *reinterpret_cast<float2*>(g_xs2 + (size_t)n * 64 + 2 * lane) = o;
    }
}

// ---------------- layer 2 aggregation + output linear + scratch re-zero ----------------
__global__ void k_agg2_out(const float* __restrict__ gb, const float* __restrict__ ow,
                           const float* __restrict__ ob, float* __restrict__ out) {
    __shared__ float ows[64 * 32];
    __shared__ float am[8][64];
    int tid = threadIdx.x;
    if (tid < 8) {
        int idx = blockIdx.x * 8 + tid;
        if (idx < NN) { g_deg[idx] = 0.f; g_cnt[idx] = 0; g_fill[idx] = 0; }
    }
    for (int i = tid; i < 64 * 32; i += 256) ows[i] = ow[i];
    __syncthreads();
    int wslot = tid >> 5;
    int lane = tid & 31;
    int n = blockIdx.x * 8 + wslot;
    if (n >= NN) return;
    int rs = g_rowptr[n], re = g_rowptr[n + 1];
    float a0 = 0.f, a1 = 0.f;
    int sN = 0; float wN = 0.f;
    if (rs < re) { sN = __ldg(&g_csrc[rs]); wN = __ldg(&g_cnorm[rs]); }
    for (int i = rs; i < re; i++) {
        int s = sN; float w = wN;
        if (i + 1 < re) { sN = __ldg(&g_csrc[i + 1]); wN = __ldg(&g_cnorm[i + 1]); }
        const float* p = g_xs2 + (size_t)s * 64;
        a0 += w * __ldg(p + lane);
        a1 += w * __ldg(p + lane + 32);
    }
    float d = g_dis[n];
    float d2 = d * d;
    const float* pn = g_xs2 + (size_t)n * 64;
    a0 += d2 * pn[lane] + gb[lane];
    a1 += d2 * pn[lane + 32] + gb[lane + 32];
    am[wslot][lane] = a0;
    am[wslot][lane + 32] = a1;
    __syncwarp();
    float s = ob[lane];
    const float* amr = am[wslot];
#pragma unroll 8
    for (int c = 0; c < 64; c++) s += amr[c] * ows[c * 32 + lane];
    out[(size_t)n * 32 + lane] = s;
}

// ---------------- launch ----------------
extern "C" void kernel_launch(void* const* d_in, const int* in_sizes, int n_in,
                              void* d_out, int out_size) {
    const float* x    = (const float*)d_in[0];
    const int*   ei   = (const int*)d_in[1];
    const float* ew   = (const float*)d_in[2];
    const float* cw1  = (const float*)d_in[3];
    const float* ga1  = (const float*)d_in[5];
    const float* be1  = (const float*)d_in[6];
    const float* gw1  = (const float*)d_in[7];
    const float* gb1  = (const float*)d_in[8];
    const float* cw2  = (const float*)d_in[9];
    const float* ga2  = (const float*)d_in[11];
    const float* be2  = (const float*)d_in[12];
    const float* gw2  = (const float*)d_in[13];
    const float* gb2  = (const float*)d_in[14];
    const float* ow   = (const float*)d_in[15];
    const float* ob   = (const float*)d_in[16];
    float* out = (float*)d_out;

    const int smem1 = (32 * 128 + 32 * 64 + L1N * 896) * 4;                       // 52KB
    const int smem2 = (256 + 64 * 100 + L2N * 14 * 36 + L2N * 64) * 4;            // ~44.8KB
    static bool attr_set = false;
    if (!attr_set) {
        cudaFuncSetAttribute(k_layer1, cudaFuncAttributeMaxDynamicSharedMemorySize, smem1);
        cudaFuncSetAttribute(k_layer2, cudaFuncAttributeMaxDynamicSharedMemorySize, smem2);
        attr_set = true;
    }

    // k_layer1 kept at launch slot 4 for positional ncu capture (unchanged control)
    k_compose<<<17, 256>>>(cw2, gw1, gb1);
    k_edge_hist<<<(EE + 255) / 256, 256>>>(ei, ew);
    k_scandis<<<1, 1024>>>();
    k_layer1<<<(NN + L1N - 1) / L1N, 32 * L1N, smem1>>>(x, cw1, ga1, be1);
    k_scatter<<<(EE + 255) / 256, 256>>>(ei, ew);
    k_agg1<<<(2 * NN * 32 + 255) / 256, 256>>>();
    k_layer2<<<(NN + L2N - 1) / L2N, 32 * L2N, smem2>>>(ga2, be2, gw2);
    k_agg2_out<<<(NN + 7) / 8, 256>>>(gb2, ow, ob, out);
}

// round 9
// speedup vs baseline: 3.9354x; 1.3363x over previous
#include <cuda_runtime.h>
#include <cuda_fp16.h>
#include <cuda_bf16.h>
#include <cstdint>

#define TT 12
#define NN 10000
#define EE 160000

typedef unsigned long long u64;

__device__ __forceinline__ u64 splat2(float v) {
    u64 r; asm("mov.b64 %0,{%1,%1};" : "=l"(r) : "f"(v)); return r;
}
__device__ __forceinline__ u64 pack2(float lo, float hi) {
    u64 r; asm("mov.b64 %0,{%1,%2};" : "=l"(r) : "f"(lo), "f"(hi)); return r;
}
__device__ __forceinline__ void fma2(u64& acc, u64 a, u64 b) {
    asm("fma.rn.f32x2 %0,%1,%2,%0;" : "+l"(acc) : "l"(a), "l"(b));
}
__device__ __forceinline__ float2 unpack2(u64 v) {
    float2 f; asm("mov.b64 {%0,%1},%2;" : "=f"(f.x), "=f"(f.y) : "l"(v)); return f;
}

// ---------------- device scratch ----------------
__device__ __half  g_h1h[TT * NN * 64];    // layer1 h (post IN+relu), fp16 co-pair interleaved
__device__ __half  g_agg1h[TT * NN * 64];  // aggregated h, fp16 same layout
__device__ float   g_xs2[NN * 64];
__device__ __half  g_w1h[64 * 96];         // conv1 weights fp16, [co][K], K = tap*32+ci
__device__ __half  g_w2h[64 * 192];        // composed conv2 weights fp16, [co][K], K = tap*64+ci
__device__ float   g_S0[64];
__device__ float   g_S2[64];
__device__ float   g_deg[NN];              // zero-init at load; re-zeroed by k_agg2_out
__device__ float   g_dis[NN];
__device__ int     g_cnt[NN];
__device__ int     g_fill[NN];
__device__ int     g_rowptr[NN + 1];
__device__ int     g_csrc[EE];
__device__ float   g_cnorm[EE];

// ---------------- weight prep: W2' = w2 ∘ gcn_w1 (fp16), w1 fp16 pack, S0/S2 from gb1 ----
__global__ void k_compose(const float* __restrict__ w2, const float* __restrict__ gw1,
                          const float* __restrict__ gb1, const float* __restrict__ w1) {
    int idx = blockIdx.x * blockDim.x + threadIdx.x;
    if (idx < 4096) {
        int co = idx >> 6, c = idx & 63;
        const float* w2r = w2 + co * 192;
        const float* g1r = gw1 + c * 64;
        float s0 = 0.f, s1 = 0.f, s2 = 0.f;
        for (int d = 0; d < 64; d++) {
            float g = g1r[d];
            s0 += w2r[d * 3 + 0] * g;
            s1 += w2r[d * 3 + 1] * g;
            s2 += w2r[d * 3 + 2] * g;
        }
        g_w2h[co * 192 +   0 + c] = __float2half_rn(s0);
        g_w2h[co * 192 +  64 + c] = __float2half_rn(s1);
        g_w2h[co * 192 + 128 + c] = __float2half_rn(s2);
    } else if (idx < 4096 + 128) {
        int j = idx - 4096;
        int co = j & 63, which = j >> 6;
        const float* w2r = w2 + co * 192;
        float s = 0.f;
        int k = which ? 2 : 0;
        for (int d = 0; d < 64; d++) s += w2r[d * 3 + k] * gb1[d];
        if (which) g_S2[co] = s; else g_S0[co] = s;
    } else if (idx >= 4224 && idx < 4224 + 6144) {
        int j = idx - 4224;                    // w1: [co][ci][3] -> g_w1h[co][k*32+ci]
        int co = j / 96, rem = j % 96;
        int ci = rem / 3, k = rem % 3;
        g_w1h[co * 96 + k * 32 + ci] = __float2half_rn(w1[j]);
    }
}

// ---------------- graph preprocessing ----------------
__global__ void k_edge_hist(const int* __restrict__ ei, const float* __restrict__ ew) {
    int e = blockIdx.x * blockDim.x + threadIdx.x;
    if (e >= EE) return;
    int d = ei[EE + e];
    atomicAdd(&g_deg[d], ew[e]);
    atomicAdd(&g_cnt[d], 1);
}

__global__ void k_scandis() {
    __shared__ int ssum[32];
    int tid = threadIdx.x;
    int lane = tid & 31;
    int wid = tid >> 5;
    const int per = 10;
    int start = tid * per;
    int vals[per];
    int local = 0;
#pragma unroll
    for (int k = 0; k < per; k++) {
        int idx = start + k;
        int v = 0;
        if (idx < NN) {
            v = g_cnt[idx];
            g_dis[idx] = rsqrtf(g_deg[idx] + 1.0f);
        }
        vals[k] = v; local += v;
    }
    int x = local;
#pragma unroll
    for (int off = 1; off < 32; off <<= 1) {
        int y = __shfl_up_sync(0xffffffffu, x, off);
        if (lane >= off) x += y;
    }
    if (lane == 31) ssum[wid] = x;
    __syncthreads();
    if (wid == 0) {
        int v = ssum[lane];
#pragma unroll
        for (int off = 1; off < 32; off <<= 1) {
            int y = __shfl_up_sync(0xffffffffu, v, off);
            if (lane >= off) v += y;
        }
        ssum[lane] = v;
    }
    __syncthreads();
    int run = (wid > 0 ? ssum[wid - 1] : 0) + x - local;
#pragma unroll
    for (int k = 0; k < per; k++) {
        int idx = start + k;
        if (idx < NN) g_rowptr[idx] = run;
        run += vals[k];
    }
    if (tid == 1023) g_rowptr[NN] = run;
}

__global__ void k_scatter(const int* __restrict__ ei, const float* __restrict__ ew) {
    int e = blockIdx.x * blockDim.x + threadIdx.x;
    if (e >= EE) return;
    int srcn = ei[e];
    int d = ei[EE + e];
    int pos = atomicAdd(&g_fill[d], 1);
    int idx = g_rowptr[d] + pos;
    g_csrc[idx] = srcn;
    g_cnorm[idx] = g_dis[srcn] * ew[e] * g_dis[d];
}

// ======================= layer 1: tensor-core MMA conv + IN + relu =======================
// warp per node. D[64co x 16t] = A[64 x 96] @ B[96 x 16], K tap-major (tap*32+ci).
// smem: params 128f | aw u32[64][52] 13.3KB | xr u32[L1N][14][20] 9KB | hstage half[L1N][12][64] 12.3KB
#define L1N 8
__global__ void __launch_bounds__(32 * L1N, 3)
k_layer1(const float* __restrict__ x, const float* __restrict__ gamma,
         const float* __restrict__ beta) {
    extern __shared__ float sm[];
    float* gms = sm;                                             // 64
    float* bes = gms + 64;                                       // 64
    unsigned int* aw = reinterpret_cast<unsigned int*>(bes + 64);  // [64][52]
    unsigned int* xr = aw + 64 * 52;                               // L1N * 14*20
    __half* hst = reinterpret_cast<__half*>(xr + L1N * 14 * 20);   // L1N * 12*64

    int tid = threadIdx.x;
    const int NT = 32 * L1N;
    for (int i = tid; i < 64; i += NT) { gms[i] = gamma[i]; bes[i] = beta[i]; }
    const unsigned int* wsrc = reinterpret_cast<const unsigned int*>(g_w1h);
    for (int i = tid; i < 64 * 48; i += NT) {
        int co = i / 48, k2 = i % 48;
        aw[co * 52 + k2] = wsrc[i];
    }
    int local = tid >> 5;
    int lane = tid & 31;
    int gid = lane >> 2;
    int tig = lane & 3;
    int n = blockIdx.x * L1N + local;
    unsigned int* xrow = xr + local * (14 * 20);
    __half* hstage = hst + local * (12 * 64);

    // stage x fp32 -> half2 ch pairs; rows tp = t+1, pads at 0 and 13
    {
        int pair = lane & 15;
        int th = lane >> 4;   // t half: 0 -> t 0..5, 1 -> t 6..11
        if (lane < 16) { xrow[0 * 20 + lane] = 0u; xrow[13 * 20 + lane] = 0u; }
#pragma unroll
        for (int tt = 0; tt < 6; tt++) {
            int t = th * 6 + tt;
            float2 f = __ldg(reinterpret_cast<const float2*>(x + ((size_t)t * NN + n) * 32) + pair);
            __half2 h = __floats2half2_rn(f.x, f.y);
            xrow[(t + 1) * 20 + pair] = *reinterpret_cast<unsigned int*>(&h);
        }
    }
    __syncthreads();

    float d0[4][4], d1[4][4];
#pragma unroll
    for (int m = 0; m < 4; m++)
#pragma unroll
        for (int r = 0; r < 4; r++) { d0[m][r] = 0.f; d1[m][r] = 0.f; }

#pragma unroll
    for (int kt = 0; kt < 6; kt++) {
        int tap = kt >> 1;
        int l0 = (kt & 1) * 8;
        int tp0 = gid + tap;
        int tp1 = gid + 8 + tap; if (tp1 > 13) tp1 = 13;
        unsigned int b00 = xrow[tp0 * 20 + l0 + tig];
        unsigned int b01 = xrow[tp0 * 20 + l0 + tig + 4];
        unsigned int b10 = xrow[tp1 * 20 + l0 + tig];
        unsigned int b11 = xrow[tp1 * 20 + l0 + tig + 4];
#pragma unroll
        for (int mt = 0; mt < 4; mt++) {
            const unsigned int* ap = aw + (mt * 16 + gid) * 52 + kt * 8 + tig;
            unsigned int a0 = ap[0];
            unsigned int a1 = ap[8 * 52];
            unsigned int a2 = ap[4];
            unsigned int a3 = ap[8 * 52 + 4];
            asm volatile("mma.sync.aligned.m16n8k16.row.col.f32.f16.f16.f32 "
                "{%0,%1,%2,%3}, {%4,%5,%6,%7}, {%8,%9}, {%0,%1,%2,%3};"
                : "+f"(d0[mt][0]), "+f"(d0[mt][1]), "+f"(d0[mt][2]), "+f"(d0[mt][3])
                : "r"(a0), "r"(a1), "r"(a2), "r"(a3), "r"(b00), "r"(b01));
            asm volatile("mma.sync.aligned.m16n8k16.row.col.f32.f16.f16.f32 "
                "{%0,%1,%2,%3}, {%4,%5,%6,%7}, {%8,%9}, {%0,%1,%2,%3};"
                : "+f"(d1[mt][0]), "+f"(d1[mt][1]), "+f"(d1[mt][2]), "+f"(d1[mt][3])
                : "r"(a0), "r"(a1), "r"(a2), "r"(a3), "r"(b10), "r"(b11));
        }
    }

    // epilogue: IN + relu per co (4-lane shfl stats), stage h half [t][64co]
#pragma unroll
    for (int mt = 0; mt < 4; mt++) {
#pragma unroll
        for (int part = 0; part < 2; part++) {
            int co = mt * 16 + gid + part * 8;
            float v0 = part ? d0[mt][2] : d0[mt][0];   // t = 2 tig
            float v1 = part ? d0[mt][3] : d0[mt][1];   // t = 2 tig + 1
            float v2 = part ? d1[mt][2] : d1[mt][0];   // t = 8 + 2 tig
            float v3 = part ? d1[mt][3] : d1[mt][1];   // t = 9 + 2 tig
            bool val2 = tig < 2;
            float s = v0 + v1 + (val2 ? v2 + v3 : 0.f);
            s += __shfl_xor_sync(0xffffffffu, s, 1);
            s += __shfl_xor_sync(0xffffffffu, s, 2);
            float mu = s * (1.0f / 12.0f);
            float e0 = v0 - mu, e1 = v1 - mu, e2 = v2 - mu, e3 = v3 - mu;
            float q = e0 * e0 + e1 * e1 + (val2 ? e2 * e2 + e3 * e3 : 0.f);
            q += __shfl_xor_sync(0xffffffffu, q, 1);
            q += __shfl_xor_sync(0xffffffffu, q, 2);
            float sc = rsqrtf(q * (1.0f / 12.0f) + 1e-5f) * gms[co];
            float bt = bes[co];
            hstage[(2 * tig) * 64 + co]     = __float2half_rn(fmaxf(e0 * sc + bt, 0.f));
            hstage[(2 * tig + 1) * 64 + co] = __float2half_rn(fmaxf(e1 * sc + bt, 0.f));
            if (val2) {
                hstage[(8 + 2 * tig) * 64 + co] = __float2half_rn(fmaxf(e2 * sc + bt, 0.f));
                hstage[(9 + 2 * tig) * 64 + co] = __float2half_rn(fmaxf(e3 * sc + bt, 0.f));
            }
        }
    }
    __syncwarp();
    {
        const unsigned int* hsu = reinterpret_cast<const unsigned int*>(hstage);
        __half2* outp = reinterpret_cast<__half2*>(g_h1h);
#pragma unroll
        for (int t = 0; t < TT; t++) {
            unsigned int v = hsu[t * 32 + lane];
            outp[((size_t)t * NN + n) * 32 + lane] = *reinterpret_cast<const __half2*>(&v);
        }
    }
}

// ---------------- layer 1 aggregation ----------------
__global__ void k_agg1() {
    int gwid = (blockIdx.x * blockDim.x + threadIdx.x) >> 5;
    int lane = threadIdx.x & 31;
    if (gwid >= 2 * NN) return;
    int n = gwid >> 1;
    int t0 = (gwid & 1) * 6;
    int rs = g_rowptr[n], re = g_rowptr[n + 1];
    const __half2* base = reinterpret_cast<const __half2*>(g_h1h) + (size_t)t0 * NN * 32 + lane;
    float a[12];
#pragma unroll
    for (int i = 0; i < 12; i++) a[i] = 0.f;
    int sN = 0; float wN = 0.f;
    if (rs < re) { sN = __ldg(&g_csrc[rs]); wN = __ldg(&g_cnorm[rs]); }
    for (int i = rs; i < re; i++) {
        int s = sN; float w = wN;
        if (i + 1 < re) { sN = __ldg(&g_csrc[i + 1]); wN = __ldg(&g_cnorm[i + 1]); }
        const __half2* p = base + (size_t)s * 32;
#pragma unroll
        for (int t = 0; t < 6; t++) {
            float2 f = __half22float2(__ldg(p + (size_t)t * NN * 32));
            a[2 * t]     += w * f.x;
            a[2 * t + 1] += w * f.y;
        }
    }
    float d = g_dis[n];
    float d2 = d * d;
    const __half2* pn = base + (size_t)n * 32;
    __half2* outh = reinterpret_cast<__half2*>(g_agg1h) + (size_t)t0 * NN * 32 + (size_t)n * 32 + lane;
#pragma unroll
    for (int t = 0; t < 6; t++) {
        float2 f = __half22float2(pn[(size_t)t * NN * 32]);
        float r0 = a[2 * t]     + d2 * f.x;
        float r1 = a[2 * t + 1] + d2 * f.y;
        outh[(size_t)t * NN * 32] = __floats2half2_rn(r0, r1);
    }
}

// ======================= layer 2: tensor-core MMA conv + IN + relu + Tmean + @gcn_w2 ========
#define L2N 8
__global__ void __launch_bounds__(32 * L2N, 3)
k_layer2(const float* __restrict__ gamma, const float* __restrict__ beta,
         const float* __restrict__ gw) {
    extern __shared__ float sm[];
    float* gms = sm;
    float* bes = gms + 64;
    float* s0s = bes + 64;
    float* s2s = s0s + 64;
    unsigned int* aw = reinterpret_cast<unsigned int*>(s2s + 64);
    unsigned int* xr = aw + 64 * 100;
    float* hbar = reinterpret_cast<float*>(xr + L2N * 14 * 36);

    int tid = threadIdx.x;
    const int NT = 32 * L2N;
    for (int i = tid; i < 64; i += NT) {
        gms[i] = gamma[i]; bes[i] = beta[i]; s0s[i] = g_S0[i]; s2s[i] = g_S2[i];
    }
    const unsigned int* wsrc = reinterpret_cast<const unsigned int*>(g_w2h);
    for (int i = tid; i < 64 * 96; i += NT) {
        int co = i / 96, k2 = i % 96;
        aw[co * 100 + k2] = wsrc[i];
    }
    int local = tid >> 5;
    int lane = tid & 31;
    int gid = lane >> 2;
    int tig = lane & 3;
    int n = blockIdx.x * L2N + local;
    unsigned int* xrow = xr + local * (14 * 36);

    {
        const __half2* src = reinterpret_cast<const __half2*>(g_agg1h) + (size_t)n * 32 + lane;
        xrow[0 * 36 + lane] = 0u;
        xrow[13 * 36 + lane] = 0u;
#pragma unroll
        for (int t = 0; t < TT; t++) {
            __half2 v = src[(size_t)t * NN * 32];
            xrow[(t + 1) * 36 + lane] = *reinterpret_cast<unsigned int*>(&v);
        }
    }
    __syncthreads();

    float d0[4][4], d1[4][4];
#pragma unroll
    for (int m = 0; m < 4; m++)
#pragma unroll
        for (int r = 0; r < 4; r++) { d0[m][r] = 0.f; d1[m][r] = 0.f; }

#pragma unroll
    for (int kt = 0; kt < 12; kt++) {
        int tap = kt >> 2;
        int l0 = (kt & 3) * 8;
        int tp0 = gid + tap;
        int tp1 = gid + 8 + tap; if (tp1 > 13) tp1 = 13;
        unsigned int b00 = xrow[tp0 * 36 + l0 + tig];
        unsigned int b01 = xrow[tp0 * 36 + l0 + tig + 4];
        unsigned int b10 = xrow[tp1 * 36 + l0 + tig];
        unsigned int b11 = xrow[tp1 * 36 + l0 + tig + 4];
#pragma unroll
        for (int mt = 0; mt < 4; mt++) {
            const unsigned int* ap = aw + (mt * 16 + gid) * 100 + kt * 8 + tig;
            unsigned int a0 = ap[0];
            unsigned int a1 = ap[8 * 100];
            unsigned int a2 = ap[4];
            unsigned int a3 = ap[8 * 100 + 4];
            asm volatile("mma.sync.aligned.m16n8k16.row.col.f32.f16.f16.f32 "
                "{%0,%1,%2,%3}, {%4,%5,%6,%7}, {%8,%9}, {%0,%1,%2,%3};"
                : "+f"(d0[mt][0]), "+f"(d0[mt][1]), "+f"(d0[mt][2]), "+f"(d0[mt][3])
                : "r"(a0), "r"(a1), "r"(a2), "r"(a3), "r"(b00), "r"(b01));
            asm volatile("mma.sync.aligned.m16n8k16.row.col.f32.f16.f16.f32 "
                "{%0,%1,%2,%3}, {%4,%5,%6,%7}, {%8,%9}, {%0,%1,%2,%3};"
                : "+f"(d1[mt][0]), "+f"(d1[mt][1]), "+f"(d1[mt][2]), "+f"(d1[mt][3])
                : "r"(a0), "r"(a1), "r"(a2), "r"(a3), "r"(b10), "r"(b11));
        }
    }

#pragma unroll
    for (int mt = 0; mt < 4; mt++) {
#pragma unroll
        for (int part = 0; part < 2; part++) {
            int co = mt * 16 + gid + part * 8;
            float v0 = part ? d0[mt][2] : d0[mt][0];
            float v1 = part ? d0[mt][3] : d0[mt][1];
            float v2 = part ? d1[mt][2] : d1[mt][0];
            float v3 = part ? d1[mt][3] : d1[mt][1];
            if (tig == 0) v0 -= s0s[co];
            if (tig == 1) v3 -= s2s[co];
            bool val2 = tig < 2;
            float s = v0 + v1 + (val2 ? v2 + v3 : 0.f);
            s += __shfl_xor_sync(0xffffffffu, s, 1);
            s += __shfl_xor_sync(0xffffffffu, s, 2);
            float mu = s * (1.0f / 12.0f);
            float e0 = v0 - mu, e1 = v1 - mu, e2 = v2 - mu, e3 = v3 - mu;
            float q = e0 * e0 + e1 * e1 + (val2 ? e2 * e2 + e3 * e3 : 0.f);
            q += __shfl_xor_sync(0xffffffffu, q, 1);
            q += __shfl_xor_sync(0xffffffffu, q, 2);
            float sc = rsqrtf(q * (1.0f / 12.0f) + 1e-5f) * gms[co];
            float bt = bes[co];
            float r = fmaxf(e0 * sc + bt, 0.f) + fmaxf(e1 * sc + bt, 0.f)
                    + (val2 ? fmaxf(e2 * sc + bt, 0.f) + fmaxf(e3 * sc + bt, 0.f) : 0.f);
            r += __shfl_xor_sync(0xffffffffu, r, 1);
            r += __shfl_xor_sync(0xffffffffu, r, 2);
            if (tig == 0) hbar[local * 64 + co] = r * (1.0f / 12.0f);
        }
    }
    __syncwarp();

    {
        const float4* hl4 = reinterpret_cast<const float4*>(hbar + local * 64);
        const float2* gp = reinterpret_cast<const float2*>(gw) + lane;
        u64 oacc = splat2(0.f);
        for (int c4 = 0; c4 < 16; c4++) {
            float4 hc = hl4[c4];
            int c = c4 * 4;
            float2 g0 = __ldg(gp + (c + 0) * 32);
            float2 g1 = __ldg(gp + (c + 1) * 32);
            float2 g2 = __ldg(gp + (c + 2) * 32);
            float2 g3 = __ldg(gp + (c + 3) * 32);
            fma2(oacc, splat2(hc.x), pack2(g0.x, g0.y));
            fma2(oacc, splat2(hc.y), pack2(g1.x, g1.y));
            fma2(oacc, splat2(hc.z), pack2(g2.x, g2.y));
            fma2(oacc, splat2(hc.w), pack2(g3.x, g3.y));
        }
        float2 o = unpack2(oacc);
        *reinterpret_cast<float2*>(g_xs2 + (size_t)n * 64 + 2 * lane) = o;
    }
}

// ---------------- layer 2 aggregation + output linear + scratch re-zero ----------------
__global__ void k_agg2_out(const float* __restrict__ gb, const float* __restrict__ ow,
                           const float* __restrict__ ob, float* __restrict__ out) {
    __shared__ float ows[64 * 32];
    __shared__ float am[8][64];
    int tid = threadIdx.x;
    if (tid < 8) {
        int idx = blockIdx.x * 8 + tid;
        if (idx < NN) { g_deg[idx] = 0.f; g_cnt[idx] = 0; g_fill[idx] = 0; }
    }
    for (int i = tid; i < 64 * 32; i += 256) ows[i] = ow[i];
    __syncthreads();
    int wslot = tid >> 5;
    int lane = tid & 31;
    int n = blockIdx.x * 8 + wslot;
    if (n >= NN) return;
    int rs = g_rowptr[n], re = g_rowptr[n + 1];
    float a0 = 0.f, a1 = 0.f;
    int sN = 0; float wN = 0.f;
    if (rs < re) { sN = __ldg(&g_csrc[rs]); wN = __ldg(&g_cnorm[rs]); }
    for (int i = rs; i < re; i++) {
        int s = sN; float w = wN;
        if (i + 1 < re) { sN = __ldg(&g_csrc[i + 1]); wN = __ldg(&g_cnorm[i + 1]); }
        const float* p = g_xs2 + (size_t)s * 64;
        a0 += w * __ldg(p + lane);
        a1 += w * __ldg(p + lane + 32);
    }
    float d = g_dis[n];
    float d2 = d * d;
    const float* pn = g_xs2 + (size_t)n * 64;
    a0 += d2 * pn[lane] + gb[lane];
    a1 += d2 * pn[lane + 32] + gb[lane + 32];
    am[wslot][lane] = a0;
    am[wslot][lane + 32] = a1;
    __syncwarp();
    float s = ob[lane];
    const float* amr = am[wslot];
#pragma unroll 8
    for (int c = 0; c < 64; c++) s += amr[c] * ows[c * 32 + lane];
    out[(size_t)n * 32 + lane] = s;
}

// ---------------- launch ----------------
extern "C" void kernel_launch(void* const* d_in, const int* in_sizes, int n_in,
                              void* d_out, int out_size) {
    const float* x    = (const float*)d_in[0];
    const int*   ei   = (const int*)d_in[1];
    const float* ew   = (const float*)d_in[2];
    const float* cw1  = (const float*)d_in[3];
    const float* ga1  = (const float*)d_in[5];
    const float* be1  = (const float*)d_in[6];
    const float* gw1  = (const float*)d_in[7];
    const float* gb1  = (const float*)d_in[8];
    const float* cw2  = (const float*)d_in[9];
    const float* ga2  = (const float*)d_in[11];
    const float* be2  = (const float*)d_in[12];
    const float* gw2  = (const float*)d_in[13];
    const float* gb2  = (const float*)d_in[14];
    const float* ow   = (const float*)d_in[15];
    const float* ob   = (const float*)d_in[16];
    float* out = (float*)d_out;

    const int smem1 = (128 + 64 * 52 + L1N * 14 * 20 + L1N * 12 * 32) * 4;   // ~34.3KB
    const int smem2 = (256 + 64 * 100 + L2N * 14 * 36 + L2N * 64) * 4;       // ~44.8KB
    static bool attr_set = false;
    if (!attr_set) {
        cudaFuncSetAttribute(k_layer1, cudaFuncAttributeMaxDynamicSharedMemorySize, smem1);
        cudaFuncSetAttribute(k_layer2, cudaFuncAttributeMaxDynamicSharedMemorySize, smem2);
        attr_set = true;
    }

    // k_layer1 kept at launch slot 4 for positional ncu capture
    k_compose<<<41, 256>>>(cw2, gw1, gb1, cw1);
    k_edge_hist<<<(EE + 255) / 256, 256>>>(ei, ew);
    k_scandis<<<1, 1024>>>();
    k_layer1<<<(NN + L1N - 1) / L1N, 32 * L1N, smem1>>>(x, ga1, be1);
    k_scatter<<<(EE + 255) / 256, 256>>>(ei, ew);
    k_agg1<<<(2 * NN * 32 + 255) / 256, 256>>>();
    k_layer2<<<(NN + L2N - 1) / L2N, 32 * L2N, smem2>>>(ga2, be2, gw2);
    k_agg2_out<<<(NN + 7) / 8, 256>>>(gb2, ow, ob, out);
}

// round 10
// speedup vs baseline: 4.1476x; 1.0539x over previous
#include <cuda_runtime.h>
#include <cuda_fp16.h>
#include <cuda_bf16.h>
#include <cstdint>

#define TT 12
#define NN 10000
#define EE 160000

typedef unsigned long long u64;

__device__ __forceinline__ u64 splat2(float v) {
    u64 r; asm("mov.b64 %0,{%1,%1};" : "=l"(r) : "f"(v)); return r;
}
__device__ __forceinline__ u64 pack2(float lo, float hi) {
    u64 r; asm("mov.b64 %0,{%1,%2};" : "=l"(r) : "f"(lo), "f"(hi)); return r;
}
__device__ __forceinline__ void fma2(u64& acc, u64 a, u64 b) {
    asm("fma.rn.f32x2 %0,%1,%2,%0;" : "+l"(acc) : "l"(a), "l"(b));
}
__device__ __forceinline__ float2 unpack2(u64 v) {
    float2 f; asm("mov.b64 {%0,%1},%2;" : "=f"(f.x), "=f"(f.y) : "l"(v)); return f;
}

// ---------------- device scratch ----------------
__device__ __half  g_h1h[TT * NN * 64];    // layer1 h (post IN+relu), fp16 co-pair interleaved
__device__ __half  g_agg1h[TT * NN * 64];  // aggregated h, fp16 same layout
__device__ float   g_xs2[NN * 64];
__device__ __half  g_w1h[64 * 96];         // conv1 weights fp16, [co][K], K = tap*32+ci
__device__ __half  g_w2h[64 * 192];        // composed conv2 weights fp16, [co][K], K = tap*64+ci
__device__ float   g_S0[64];
__device__ float   g_S2[64];
__device__ u64     g_hist[NN];             // cnt in bits[40..], deg fixed-point 2^-24 in bits[0..40)
__device__ float   g_dis[NN];
__device__ int     g_fill[NN];
__device__ int     g_rowptr[NN + 1];
__device__ int     g_csrc[EE];
__device__ float   g_cnorm[EE];

#define FIXP 16777216.0f   // 2^24

// ======== fused: edge histogram (packed u64 atomic) + weight prep ========
// blocks [0,625): hist over edges; blocks [625,666): compose W2'=w2∘gw1, S0/S2, w1 fp16 pack
__global__ void k_histcompose(const int* __restrict__ ei, const float* __restrict__ ew,
                              const float* __restrict__ w2, const float* __restrict__ gw1,
                              const float* __restrict__ gb1, const float* __restrict__ w1) {
    if (blockIdx.x < 625) {
        int e = blockIdx.x * 256 + threadIdx.x;
        if (e >= EE) return;
        int d = ei[EE + e];
        u64 v = ((u64)1 << 40) | (u64)(ew[e] * FIXP);
        atomicAdd(&g_hist[d], v);
        return;
    }
    int idx = (blockIdx.x - 625) * 256 + threadIdx.x;
    if (idx < 4096) {
        int co = idx >> 6, c = idx & 63;
        const float* w2r = w2 + co * 192;
        const float* g1r = gw1 + c * 64;
        float s0 = 0.f, s1 = 0.f, s2 = 0.f;
        for (int d = 0; d < 64; d++) {
            float g = g1r[d];
            s0 += w2r[d * 3 + 0] * g;
            s1 += w2r[d * 3 + 1] * g;
            s2 += w2r[d * 3 + 2] * g;
        }
        g_w2h[co * 192 +   0 + c] = __float2half_rn(s0);
        g_w2h[co * 192 +  64 + c] = __float2half_rn(s1);
        g_w2h[co * 192 + 128 + c] = __float2half_rn(s2);
    } else if (idx < 4096 + 128) {
        int j = idx - 4096;
        int co = j & 63, which = j >> 6;
        const float* w2r = w2 + co * 192;
        float s = 0.f;
        int k = which ? 2 : 0;
        for (int d = 0; d < 64; d++) s += w2r[d * 3 + k] * gb1[d];
        if (which) g_S2[co] = s; else g_S0[co] = s;
    } else if (idx >= 4224 && idx < 4224 + 6144) {
        int j = idx - 4224;                    // w1: [co][ci][3] -> g_w1h[co][k*32+ci]
        int co = j / 96, rem = j % 96;
        int ci = rem / 3, k = rem % 3;
        g_w1h[co * 96 + k * 32 + ci] = __float2half_rn(w1[j]);
    }
}

// ---------------- scan + dis (decodes packed hist) ----------------
__global__ void k_scandis() {
    __shared__ int ssum[32];
    int tid = threadIdx.x;
    int lane = tid & 31;
    int wid = tid >> 5;
    const int per = 10;
    int start = tid * per;
    int vals[per];
    int local = 0;
#pragma unroll
    for (int k = 0; k < per; k++) {
        int idx = start + k;
        int v = 0;
        if (idx < NN) {
            u64 h = g_hist[idx];
            v = (int)(h >> 40);
            float deg = (float)(h & 0xFFFFFFFFFFull) * (1.0f / FIXP);
            g_dis[idx] = rsqrtf(deg + 1.0f);
        }
        vals[k] = v; local += v;
    }
    int x = local;
#pragma unroll
    for (int off = 1; off < 32; off <<= 1) {
        int y = __shfl_up_sync(0xffffffffu, x, off);
        if (lane >= off) x += y;
    }
    if (lane == 31) ssum[wid] = x;
    __syncthreads();
    if (wid == 0) {
        int v = ssum[lane];
#pragma unroll
        for (int off = 1; off < 32; off <<= 1) {
            int y = __shfl_up_sync(0xffffffffu, v, off);
            if (lane >= off) v += y;
        }
        ssum[lane] = v;
    }
    __syncthreads();
    int run = (wid > 0 ? ssum[wid - 1] : 0) + x - local;
#pragma unroll
    for (int k = 0; k < per; k++) {
        int idx = start + k;
        if (idx < NN) g_rowptr[idx] = run;
        run += vals[k];
    }
    if (tid == 1023) g_rowptr[NN] = run;
}

// ======================= fused: layer 1 (MMA conv + IN + relu) + CSR scatter =======================
// blocks [0,1250): layer1 (warp per node); blocks [1250,1875): edge scatter
#define L1N 8
__global__ void __launch_bounds__(32 * L1N, 3)
k_l1scat(const float* __restrict__ x, const float* __restrict__ gamma,
         const float* __restrict__ beta, const int* __restrict__ ei,
         const float* __restrict__ ew) {
    if (blockIdx.x >= 1250) {
        // ---- scatter ----
        int e = (blockIdx.x - 1250) * 256 + threadIdx.x;
        if (e >= EE) return;
        int srcn = ei[e];
        int d = ei[EE + e];
        int pos = atomicAdd(&g_fill[d], 1);
        int idx = g_rowptr[d] + pos;
        g_csrc[idx] = srcn;
        g_cnorm[idx] = g_dis[srcn] * ew[e] * g_dis[d];
        return;
    }
    // ---- layer 1 ----
    extern __shared__ float sm[];
    float* gms = sm;                                             // 64
    float* bes = gms + 64;                                       // 64
    unsigned int* aw = reinterpret_cast<unsigned int*>(bes + 64);  // [64][52]
    unsigned int* xr = aw + 64 * 52;                               // L1N * 14*20
    __half* hst = reinterpret_cast<__half*>(xr + L1N * 14 * 20);   // L1N * 12*64

    int tid = threadIdx.x;
    const int NT = 32 * L1N;
    for (int i = tid; i < 64; i += NT) { gms[i] = gamma[i]; bes[i] = beta[i]; }
    const unsigned int* wsrc = reinterpret_cast<const unsigned int*>(g_w1h);
    for (int i = tid; i < 64 * 48; i += NT) {
        int co = i / 48, k2 = i % 48;
        aw[co * 52 + k2] = wsrc[i];
    }
    int local = tid >> 5;
    int lane = tid & 31;
    int gid = lane >> 2;
    int tig = lane & 3;
    int n = blockIdx.x * L1N + local;
    unsigned int* xrow = xr + local * (14 * 20);
    __half* hstage = hst + local * (12 * 64);

    {
        int pair = lane & 15;
        int th = lane >> 4;
        if (lane < 16) { xrow[0 * 20 + lane] = 0u; xrow[13 * 20 + lane] = 0u; }
#pragma unroll
        for (int tt = 0; tt < 6; tt++) {
            int t = th * 6 + tt;
            float2 f = __ldg(reinterpret_cast<const float2*>(x + ((size_t)t * NN + n) * 32) + pair);
            __half2 h = __floats2half2_rn(f.x, f.y);
            xrow[(t + 1) * 20 + pair] = *reinterpret_cast<unsigned int*>(&h);
        }
    }
    __syncthreads();

    float d0[4][4], d1[4][4];
#pragma unroll
    for (int m = 0; m < 4; m++)
#pragma unroll
        for (int r = 0; r < 4; r++) { d0[m][r] = 0.f; d1[m][r] = 0.f; }

#pragma unroll
    for (int kt = 0; kt < 6; kt++) {
        int tap = kt >> 1;
        int l0 = (kt & 1) * 8;
        int tp0 = gid + tap;
        int tp1 = gid + 8 + tap; if (tp1 > 13) tp1 = 13;
        unsigned int b00 = xrow[tp0 * 20 + l0 + tig];
        unsigned int b01 = xrow[tp0 * 20 + l0 + tig + 4];
        unsigned int b10 = xrow[tp1 * 20 + l0 + tig];
        unsigned int b11 = xrow[tp1 * 20 + l0 + tig + 4];
#pragma unroll
        for (int mt = 0; mt < 4; mt++) {
            const unsigned int* ap = aw + (mt * 16 + gid) * 52 + kt * 8 + tig;
            unsigned int a0 = ap[0];
            unsigned int a1 = ap[8 * 52];
            unsigned int a2 = ap[4];
            unsigned int a3 = ap[8 * 52 + 4];
            asm volatile("mma.sync.aligned.m16n8k16.row.col.f32.f16.f16.f32 "
                "{%0,%1,%2,%3}, {%4,%5,%6,%7}, {%8,%9}, {%0,%1,%2,%3};"
                : "+f"(d0[mt][0]), "+f"(d0[mt][1]), "+f"(d0[mt][2]), "+f"(d0[mt][3])
                : "r"(a0), "r"(a1), "r"(a2), "r"(a3), "r"(b00), "r"(b01));
            asm volatile("mma.sync.aligned.m16n8k16.row.col.f32.f16.f16.f32 "
                "{%0,%1,%2,%3}, {%4,%5,%6,%7}, {%8,%9}, {%0,%1,%2,%3};"
                : "+f"(d1[mt][0]), "+f"(d1[mt][1]), "+f"(d1[mt][2]), "+f"(d1[mt][3])
                : "r"(a0), "r"(a1), "r"(a2), "r"(a3), "r"(b10), "r"(b11));
        }
    }

#pragma unroll
    for (int mt = 0; mt < 4; mt++) {
#pragma unroll
        for (int part = 0; part < 2; part++) {
            int co = mt * 16 + gid + part * 8;
            float v0 = part ? d0[mt][2] : d0[mt][0];
            float v1 = part ? d0[mt][3] : d0[mt][1];
            float v2 = part ? d1[mt][2] : d1[mt][0];
            float v3 = part ? d1[mt][3] : d1[mt][1];
            bool val2 = tig < 2;
            float s = v0 + v1 + (val2 ? v2 + v3 : 0.f);
            s += __shfl_xor_sync(0xffffffffu, s, 1);
            s += __shfl_xor_sync(0xffffffffu, s, 2);
            float mu = s * (1.0f / 12.0f);
            float e0 = v0 - mu, e1 = v1 - mu, e2 = v2 - mu, e3 = v3 - mu;
            float q = e0 * e0 + e1 * e1 + (val2 ? e2 * e2 + e3 * e3 : 0.f);
            q += __shfl_xor_sync(0xffffffffu, q, 1);
            q += __shfl_xor_sync(0xffffffffu, q, 2);
            float sc = rsqrtf(q * (1.0f / 12.0f) + 1e-5f) * gms[co];
            float bt = bes[co];
            hstage[(2 * tig) * 64 + co]     = __float2half_rn(fmaxf(e0 * sc + bt, 0.f));
            hstage[(2 * tig + 1) * 64 + co] = __float2half_rn(fmaxf(e1 * sc + bt, 0.f));
            if (val2) {
                hstage[(8 + 2 * tig) * 64 + co] = __float2half_rn(fmaxf(e2 * sc + bt, 0.f));
                hstage[(9 + 2 * tig) * 64 + co] = __float2half_rn(fmaxf(e3 * sc + bt, 0.f));
            }
        }
    }
    __syncwarp();
    {
        const unsigned int* hsu = reinterpret_cast<const unsigned int*>(hstage);
        __half2* outp = reinterpret_cast<__half2*>(g_h1h);
#pragma unroll
        for (int t = 0; t < TT; t++) {
            unsigned int v = hsu[t * 32 + lane];
            outp[((size_t)t * NN + n) * 32 + lane] = *reinterpret_cast<const __half2*>(&v);
        }
    }
}

// ---------------- layer 1 aggregation ----------------
__global__ void k_agg1() {
    int gwid = (blockIdx.x * blockDim.x + threadIdx.x) >> 5;
    int lane = threadIdx.x & 31;
    if (gwid >= 2 * NN) return;
    int n = gwid >> 1;
    int t0 = (gwid & 1) * 6;
    int rs = g_rowptr[n], re = g_rowptr[n + 1];
    const __half2* base = reinterpret_cast<const __half2*>(g_h1h) + (size_t)t0 * NN * 32 + lane;
    float a[12];
#pragma unroll
    for (int i = 0; i < 12; i++) a[i] = 0.f;
    int sN = 0; float wN = 0.f;
    if (rs < re) { sN = __ldg(&g_csrc[rs]); wN = __ldg(&g_cnorm[rs]); }
    for (int i = rs; i < re; i++) {
        int s = sN; float w = wN;
        if (i + 1 < re) { sN = __ldg(&g_csrc[i + 1]); wN = __ldg(&g_cnorm[i + 1]); }
        const __half2* p = base + (size_t)s * 32;
#pragma unroll
        for (int t = 0; t < 6; t++) {
            float2 f = __half22float2(__ldg(p + (size_t)t * NN * 32));
            a[2 * t]     += w * f.x;
            a[2 * t + 1] += w * f.y;
        }
    }
    float d = g_dis[n];
    float d2 = d * d;
    const __half2* pn = base + (size_t)n * 32;
    __half2* outh = reinterpret_cast<__half2*>(g_agg1h) + (size_t)t0 * NN * 32 + (size_t)n * 32 + lane;
#pragma unroll
    for (int t = 0; t < 6; t++) {
        float2 f = __half22float2(pn[(size_t)t * NN * 32]);
        float r0 = a[2 * t]     + d2 * f.x;
        float r1 = a[2 * t + 1] + d2 * f.y;
        outh[(size_t)t * NN * 32] = __floats2half2_rn(r0, r1);
    }
}

// ======================= layer 2: MMA conv + IN + relu + Tmean + @gcn_w2 ========
#define L2N 8
__global__ void __launch_bounds__(32 * L2N, 3)
k_layer2(const float* __restrict__ gamma, const float* __restrict__ beta,
         const float* __restrict__ gw) {
    extern __shared__ float sm[];
    float* gms = sm;
    float* bes = gms + 64;
    float* s0s = bes + 64;
    float* s2s = s0s + 64;
    unsigned int* aw = reinterpret_cast<unsigned int*>(s2s + 64);
    unsigned int* xr = aw + 64 * 100;
    float* hbar = reinterpret_cast<float*>(xr + L2N * 14 * 36);

    int tid = threadIdx.x;
    const int NT = 32 * L2N;
    for (int i = tid; i < 64; i += NT) {
        gms[i] = gamma[i]; bes[i] = beta[i]; s0s[i] = g_S0[i]; s2s[i] = g_S2[i];
    }
    const unsigned int* wsrc = reinterpret_cast<const unsigned int*>(g_w2h);
    for (int i = tid; i < 64 * 96; i += NT) {
        int co = i / 96, k2 = i % 96;
        aw[co * 100 + k2] = wsrc[i];
    }
    int local = tid >> 5;
    int lane = tid & 31;
    int gid = lane >> 2;
    int tig = lane & 3;
    int n = blockIdx.x * L2N + local;
    unsigned int* xrow = xr + local * (14 * 36);

    {
        const __half2* src = reinterpret_cast<const __half2*>(g_agg1h) + (size_t)n * 32 + lane;
        xrow[0 * 36 + lane] = 0u;
        xrow[13 * 36 + lane] = 0u;
#pragma unroll
        for (int t = 0; t < TT; t++) {
            __half2 v = src[(size_t)t * NN * 32];
            xrow[(t + 1) * 36 + lane] = *reinterpret_cast<unsigned int*>(&v);
        }
    }
    __syncthreads();

    float d0[4][4], d1[4][4];
#pragma unroll
    for (int m = 0; m < 4; m++)
#pragma unroll
        for (int r = 0; r < 4; r++) { d0[m][r] = 0.f; d1[m][r] = 0.f; }

#pragma unroll
    for (int kt = 0; kt < 12; kt++) {
        int tap = kt >> 2;
        int l0 = (kt & 3) * 8;
        int tp0 = gid + tap;
        int tp1 = gid + 8 + tap; if (tp1 > 13) tp1 = 13;
        unsigned int b00 = xrow[tp0 * 36 + l0 + tig];
        unsigned int b01 = xrow[tp0 * 36 + l0 + tig + 4];
        unsigned int b10 = xrow[tp1 * 36 + l0 + tig];
        unsigned int b11 = xrow[tp1 * 36 + l0 + tig + 4];
#pragma unroll
        for (int mt = 0; mt < 4; mt++) {
            const unsigned int* ap = aw + (mt * 16 + gid) * 100 + kt * 8 + tig;
            unsigned int a0 = ap[0];
            unsigned int a1 = ap[8 * 100];
            unsigned int a2 = ap[4];
            unsigned int a3 = ap[8 * 100 + 4];
            asm volatile("mma.sync.aligned.m16n8k16.row.col.f32.f16.f16.f32 "
                "{%0,%1,%2,%3}, {%4,%5,%6,%7}, {%8,%9}, {%0,%1,%2,%3};"
                : "+f"(d0[mt][0]), "+f"(d0[mt][1]), "+f"(d0[mt][2]), "+f"(d0[mt][3])
                : "r"(a0), "r"(a1), "r"(a2), "r"(a3), "r"(b00), "r"(b01));
            asm volatile("mma.sync.aligned.m16n8k16.row.col.f32.f16.f16.f32 "
                "{%0,%1,%2,%3}, {%4,%5,%6,%7}, {%8,%9}, {%0,%1,%2,%3};"
                : "+f"(d1[mt][0]), "+f"(d1[mt][1]), "+f"(d1[mt][2]), "+f"(d1[mt][3])
                : "r"(a0), "r"(a1), "r"(a2), "r"(a3), "r"(b10), "r"(b11));
        }
    }

#pragma unroll
    for (int mt = 0; mt < 4; mt++) {
#pragma unroll
        for (int part = 0; part < 2; part++) {
            int co = mt * 16 + gid + part * 8;
            float v0 = part ? d0[mt][2] : d0[mt][0];
            float v1 = part ? d0[mt][3] : d0[mt][1];
            float v2 = part ? d1[mt][2] : d1[mt][0];
            float v3 = part ? d1[mt][3] : d1[mt][1];
            if (tig == 0) v0 -= s0s[co];
            if (tig == 1) v3 -= s2s[co];
            bool val2 = tig < 2;
            float s = v0 + v1 + (val2 ? v2 + v3 : 0.f);
            s += __shfl_xor_sync(0xffffffffu, s, 1);
            s += __shfl_xor_sync(0xffffffffu, s, 2);
            float mu = s * (1.0f / 12.0f);
            float e0 = v0 - mu, e1 = v1 - mu, e2 = v2 - mu, e3 = v3 - mu;
            float q = e0 * e0 + e1 * e1 + (val2 ? e2 * e2 + e3 * e3 : 0.f);
            q += __shfl_xor_sync(0xffffffffu, q, 1);
            q += __shfl_xor_sync(0xffffffffu, q, 2);
            float sc = rsqrtf(q * (1.0f / 12.0f) + 1e-5f) * gms[co];
            float bt = bes[co];
            float r = fmaxf(e0 * sc + bt, 0.f) + fmaxf(e1 * sc + bt, 0.f)
                    + (val2 ? fmaxf(e2 * sc + bt, 0.f) + fmaxf(e3 * sc + bt, 0.f) : 0.f);
            r += __shfl_xor_sync(0xffffffffu, r, 1);
            r += __shfl_xor_sync(0xffffffffu, r, 2);
            if (tig == 0) hbar[local * 64 + co] = r * (1.0f / 12.0f);
        }
    }
    __syncwarp();

    {
        const float4* hl4 = reinterpret_cast<const float4*>(hbar + local * 64);
        const float2* gp = reinterpret_cast<const float2*>(gw) + lane;
        u64 oacc = splat2(0.f);
        for (int c4 = 0; c4 < 16; c4++) {
            float4 hc = hl4[c4];
            int c = c4 * 4;
            float2 g0 = __ldg(gp + (c + 0) * 32);
            float2 g1 = __ldg(gp + (c + 1) * 32);
            float2 g2 = __ldg(gp + (c + 2) * 32);
            float2 g3 = __ldg(gp + (c + 3) * 32);
            fma2(oacc, splat2(hc.x), pack2(g0.x, g0.y));
            fma2(oacc, splat2(hc.y), pack2(g1.x, g1.y));
            fma2(oacc, splat2(hc.z), pack2(g2.x, g2.y));
            fma2(oacc, splat2(hc.w), pack2(g3.x, g3.y));
        }
        float2 o = unpack2(oacc);
        *reinterpret_cast<float2*>(g_xs2 + (size_t)n * 64 + 2 * lane) = o;
    }
}

// ---------------- layer 2 aggregation + output linear + scratch re-zero ----------------
__global__ void k_agg2_out(const float* __restrict__ gb, const float* __restrict__ ow,
                           const float* __restrict__ ob, float* __restrict__ out) {
    __shared__ float ows[64 * 32];
    __shared__ float am[8][64];
    int tid = threadIdx.x;
    if (tid < 8) {
        int idx = blockIdx.x * 8 + tid;
        if (idx < NN) { g_hist[idx] = 0ull; g_fill[idx] = 0; }
    }
    for (int i = tid; i < 64 * 32; i += 256) ows[i] = ow[i];
    __syncthreads();
    int wslot = tid >> 5;
    int lane = tid & 31;
    int n = blockIdx.x * 8 + wslot;
    if (n >= NN) return;
    int rs = g_rowptr[n], re = g_rowptr[n + 1];
    float a0 = 0.f, a1 = 0.f;
    int sN = 0; float wN = 0.f;
    if (rs < re) { sN = __ldg(&g_csrc[rs]); wN = __ldg(&g_cnorm[rs]); }
    for (int i = rs; i < re; i++) {
        int s = sN; float w = wN;
        if (i + 1 < re) { sN = __ldg(&g_csrc[i + 1]); wN = __ldg(&g_cnorm[i + 1]); }
        const float* p = g_xs2 + (size_t)s * 64;
        a0 += w * __ldg(p + lane);
        a1 += w * __ldg(p + lane + 32);
    }
    float d = g_dis[n];
    float d2 = d * d;
    const float* pn = g_xs2 + (size_t)n * 64;
    a0 += d2 * pn[lane] + gb[lane];
    a1 += d2 * pn[lane + 32] + gb[lane + 32];
    am[wslot][lane] = a0;
    am[wslot][lane + 32] = a1;
    __syncwarp();
    float s = ob[lane];
    const float* amr = am[wslot];
#pragma unroll 8
    for (int c = 0; c < 64; c++) s += amr[c] * ows[c * 32 + lane];
    out[(size_t)n * 32 + lane] = s;
}

// ---------------- launch ----------------
extern "C" void kernel_launch(void* const* d_in, const int* in_sizes, int n_in,
                              void* d_out, int out_size) {
    const float* x    = (const float*)d_in[0];
    const int*   ei   = (const int*)d_in[1];
    const float* ew   = (const float*)d_in[2];
    const float* cw1  = (const float*)d_in[3];
    const float* ga1  = (const float*)d_in[5];
    const float* be1  = (const float*)d_in[6];
    const float* gw1  = (const float*)d_in[7];
    const float* gb1  = (const float*)d_in[8];
    const float* cw2  = (const float*)d_in[9];
    const float* ga2  = (const float*)d_in[11];
    const float* be2  = (const float*)d_in[12];
    const float* gw2  = (const float*)d_in[13];
    const float* gb2  = (const float*)d_in[14];
    const float* ow   = (const float*)d_in[15];
    const float* ob   = (const float*)d_in[16];
    float* out = (float*)d_out;

    const int smem1 = (128 + 64 * 52 + L1N * 14 * 20 + L1N * 12 * 32) * 4;   // ~34.3KB
    const int smem2 = (256 + 64 * 100 + L2N * 14 * 36 + L2N * 64) * 4;       // ~44.8KB
    static bool attr_set = false;
    if (!attr_set) {
        cudaFuncSetAttribute(k_l1scat, cudaFuncAttributeMaxDynamicSharedMemorySize, smem1);
        cudaFuncSetAttribute(k_layer2, cudaFuncAttributeMaxDynamicSharedMemorySize, smem2);
        attr_set = true;
    }

    // 6 launches; k_agg1 at profile slot 4
    k_histcompose<<<625 + 41, 256>>>(ei, ew, cw2, gw1, gb1, cw1);
    k_scandis<<<1, 1024>>>();
    k_l1scat<<<1250 + 625, 256, smem1>>>(x, ga1, be1, ei, ew);
    k_agg1<<<(2 * NN * 32 + 255) / 256, 256>>>();
    k_layer2<<<(NN + L2N - 1) / L2N, 32 * L2N, smem2>>>(ga2, be2, gw2);
    k_agg2_out<<<(NN + 7) / 8, 256>>>(gb2, ow, ob, out);
}

// round 11
// speedup vs baseline: 4.7332x; 1.1412x over previous
#include <cuda_runtime.h>
#include <cuda_fp16.h>
#include <cuda_bf16.h>
#include <cstdint>

#define TT 12
#define NN 10000
#define EE 160000
#define CAP 96   // padded CSR row capacity (deg ~ Poisson(16); P(>96) ~ 1e-40)

typedef unsigned long long u64;

__device__ __forceinline__ u64 splat2(float v) {
    u64 r; asm("mov.b64 %0,{%1,%1};" : "=l"(r) : "f"(v)); return r;
}
__device__ __forceinline__ u64 pack2(float lo, float hi) {
    u64 r; asm("mov.b64 %0,{%1,%2};" : "=l"(r) : "f"(lo), "f"(hi)); return r;
}
__device__ __forceinline__ void fma2(u64& acc, u64 a, u64 b) {
    asm("fma.rn.f32x2 %0,%1,%2,%0;" : "+l"(acc) : "l"(a), "l"(b));
}
__device__ __forceinline__ float2 unpack2(u64 v) {
    float2 f; asm("mov.b64 {%0,%1},%2;" : "=f"(f.x), "=f"(f.y) : "l"(v)); return f;
}

// ---------------- device scratch ----------------
__device__ __half  g_h1h[TT * NN * 64];    // layer1 h (post IN+relu), fp16 co-pair interleaved
__device__ float   g_xs2[NN * 64];
__device__ __half  g_w1h[64 * 96];         // conv1 weights fp16, [co][K], K = tap*32+ci
__device__ __half  g_w2h[64 * 192];        // composed conv2 weights fp16, [co][K], K = tap*64+ci
__device__ float   g_S0[64];
__device__ float   g_S2[64];
__device__ u64     g_hist[NN];             // cnt in bits[40..], deg fixed-point 2^-24 in [0..40)
__device__ int     g_fill[NN];
__device__ int     g_csrc[NN * CAP];       // padded CSR
__device__ float   g_cnorm[NN * CAP];

#define FIXP 16777216.0f   // 2^24
#define FIXM 0xFFFFFFFFFFull

// ---------------- edge histogram (packed u64 atomic) ----------------
__global__ void k_hist(const int* __restrict__ ei, const float* __restrict__ ew) {
    int e = blockIdx.x * blockDim.x + threadIdx.x;
    if (e >= EE) return;
    int d = ei[EE + e];
    u64 v = ((u64)1 << 40) | (u64)(ew[e] * FIXP);
    atomicAdd(&g_hist[d], v);
}

// ---------------- weight prep: W2' = w2 ∘ gcn_w1 (fp16), w1 fp16 pack, S0/S2 from gb1 ----
__global__ void k_compose(const float* __restrict__ w2, const float* __restrict__ gw1,
                          const float* __restrict__ gb1, const float* __restrict__ w1) {
    int idx = blockIdx.x * blockDim.x + threadIdx.x;
    if (idx < 4096) {
        int co = idx >> 6, c = idx & 63;
        const float* w2r = w2 + co * 192;
        const float* g1r = gw1 + c * 64;
        float s0 = 0.f, s1 = 0.f, s2 = 0.f;
        for (int d = 0; d < 64; d++) {
            float g = g1r[d];
            s0 += w2r[d * 3 + 0] * g;
            s1 += w2r[d * 3 + 1] * g;
            s2 += w2r[d * 3 + 2] * g;
        }
        g_w2h[co * 192 +   0 + c] = __float2half_rn(s0);
        g_w2h[co * 192 +  64 + c] = __float2half_rn(s1);
        g_w2h[co * 192 + 128 + c] = __float2half_rn(s2);
    } else if (idx < 4096 + 128) {
        int j = idx - 4096;
        int co = j & 63, which = j >> 6;
        const float* w2r = w2 + co * 192;
        float s = 0.f;
        int k = which ? 2 : 0;
        for (int d = 0; d < 64; d++) s += w2r[d * 3 + k] * gb1[d];
        if (which) g_S2[co] = s; else g_S0[co] = s;
    } else if (idx >= 4224 && idx < 4224 + 6144) {
        int j = idx - 4224;
        int co = j / 96, rem = j % 96;
        int ci = rem / 3, k = rem % 3;
        g_w1h[co * 96 + k * 32 + ci] = __float2half_rn(w1[j]);
    }
}

// ======================= fused: layer 1 (MMA conv + IN + relu) + padded-CSR scatter ========
// blocks [0,1250): layer1 (warp per node); blocks [1250,1875): edge scatter (dis decoded on-fly)
#define L1N 8
__global__ void __launch_bounds__(32 * L1N, 3)
k_l1scat(const float* __restrict__ x, const float* __restrict__ gamma,
         const float* __restrict__ beta, const int* __restrict__ ei,
         const float* __restrict__ ew) {
    if (blockIdx.x >= 1250) {
        int e = (blockIdx.x - 1250) * 256 + threadIdx.x;
        if (e >= EE) return;
        int srcn = ei[e];
        int d = ei[EE + e];
        u64 hs = __ldg(&g_hist[srcn]);
        u64 hd = __ldg(&g_hist[d]);
        float dis_s = rsqrtf((float)(hs & FIXM) * (1.0f / FIXP) + 1.0f);
        float dis_d = rsqrtf((float)(hd & FIXM) * (1.0f / FIXP) + 1.0f);
        int pos = atomicAdd(&g_fill[d], 1);
        int idx = d * CAP + pos;
        g_csrc[idx] = srcn;
        g_cnorm[idx] = dis_s * ew[e] * dis_d;
        return;
    }
    // ---- layer 1 ----
    extern __shared__ float sm[];
    float* gms = sm;
    float* bes = gms + 64;
    unsigned int* aw = reinterpret_cast<unsigned int*>(bes + 64);  // [64][52]
    unsigned int* xr = aw + 64 * 52;                               // L1N * 14*20
    __half* hst = reinterpret_cast<__half*>(xr + L1N * 14 * 20);   // L1N * 12*64

    int tid = threadIdx.x;
    const int NT = 32 * L1N;
    for (int i = tid; i < 64; i += NT) { gms[i] = gamma[i]; bes[i] = beta[i]; }
    const unsigned int* wsrc = reinterpret_cast<const unsigned int*>(g_w1h);
    for (int i = tid; i < 64 * 48; i += NT) {
        int co = i / 48, k2 = i % 48;
        aw[co * 52 + k2] = wsrc[i];
    }
    int local = tid >> 5;
    int lane = tid & 31;
    int gid = lane >> 2;
    int tig = lane & 3;
    int n = blockIdx.x * L1N + local;
    unsigned int* xrow = xr + local * (14 * 20);
    __half* hstage = hst + local * (12 * 64);

    {
        int pair = lane & 15;
        int th = lane >> 4;
        if (lane < 16) { xrow[0 * 20 + lane] = 0u; xrow[13 * 20 + lane] = 0u; }
#pragma unroll
        for (int tt = 0; tt < 6; tt++) {
            int t = th * 6 + tt;
            float2 f = __ldg(reinterpret_cast<const float2*>(x + ((size_t)t * NN + n) * 32) + pair);
            __half2 h = __floats2half2_rn(f.x, f.y);
            xrow[(t + 1) * 20 + pair] = *reinterpret_cast<unsigned int*>(&h);
        }
    }
    __syncthreads();

    float d0[4][4], d1[4][4];
#pragma unroll
    for (int m = 0; m < 4; m++)
#pragma unroll
        for (int r = 0; r < 4; r++) { d0[m][r] = 0.f; d1[m][r] = 0.f; }

#pragma unroll
    for (int kt = 0; kt < 6; kt++) {
        int tap = kt >> 1;
        int l0 = (kt & 1) * 8;
        int tp0 = gid + tap;
        int tp1 = gid + 8 + tap; if (tp1 > 13) tp1 = 13;
        unsigned int b00 = xrow[tp0 * 20 + l0 + tig];
        unsigned int b01 = xrow[tp0 * 20 + l0 + tig + 4];
        unsigned int b10 = xrow[tp1 * 20 + l0 + tig];
        unsigned int b11 = xrow[tp1 * 20 + l0 + tig + 4];
#pragma unroll
        for (int mt = 0; mt < 4; mt++) {
            const unsigned int* ap = aw + (mt * 16 + gid) * 52 + kt * 8 + tig;
            unsigned int a0 = ap[0];
            unsigned int a1 = ap[8 * 52];
            unsigned int a2 = ap[4];
            unsigned int a3 = ap[8 * 52 + 4];
            asm volatile("mma.sync.aligned.m16n8k16.row.col.f32.f16.f16.f32 "
                "{%0,%1,%2,%3}, {%4,%5,%6,%7}, {%8,%9}, {%0,%1,%2,%3};"
                : "+f"(d0[mt][0]), "+f"(d0[mt][1]), "+f"(d0[mt][2]), "+f"(d0[mt][3])
                : "r"(a0), "r"(a1), "r"(a2), "r"(a3), "r"(b00), "r"(b01));
            asm volatile("mma.sync.aligned.m16n8k16.row.col.f32.f16.f16.f32 "
                "{%0,%1,%2,%3}, {%4,%5,%6,%7}, {%8,%9}, {%0,%1,%2,%3};"
                : "+f"(d1[mt][0]), "+f"(d1[mt][1]), "+f"(d1[mt][2]), "+f"(d1[mt][3])
                : "r"(a0), "r"(a1), "r"(a2), "r"(a3), "r"(b10), "r"(b11));
        }
    }

#pragma unroll
    for (int mt = 0; mt < 4; mt++) {
#pragma unroll
        for (int part = 0; part < 2; part++) {
            int co = mt * 16 + gid + part * 8;
            float v0 = part ? d0[mt][2] : d0[mt][0];
            float v1 = part ? d0[mt][3] : d0[mt][1];
            float v2 = part ? d1[mt][2] : d1[mt][0];
            float v3 = part ? d1[mt][3] : d1[mt][1];
            bool val2 = tig < 2;
            float s = v0 + v1 + (val2 ? v2 + v3 : 0.f);
            s += __shfl_xor_sync(0xffffffffu, s, 1);
            s += __shfl_xor_sync(0xffffffffu, s, 2);
            float mu = s * (1.0f / 12.0f);
            float e0 = v0 - mu, e1 = v1 - mu, e2 = v2 - mu, e3 = v3 - mu;
            float q = e0 * e0 + e1 * e1 + (val2 ? e2 * e2 + e3 * e3 : 0.f);
            q += __shfl_xor_sync(0xffffffffu, q, 1);
            q += __shfl_xor_sync(0xffffffffu, q, 2);
            float sc = rsqrtf(q * (1.0f / 12.0f) + 1e-5f) * gms[co];
            float bt = bes[co];
            hstage[(2 * tig) * 64 + co]     = __float2half_rn(fmaxf(e0 * sc + bt, 0.f));
            hstage[(2 * tig + 1) * 64 + co] = __float2half_rn(fmaxf(e1 * sc + bt, 0.f));
            if (val2) {
                hstage[(8 + 2 * tig) * 64 + co] = __float2half_rn(fmaxf(e2 * sc + bt, 0.f));
                hstage[(9 + 2 * tig) * 64 + co] = __float2half_rn(fmaxf(e3 * sc + bt, 0.f));
            }
        }
    }
    __syncwarp();
    {
        const unsigned int* hsu = reinterpret_cast<const unsigned int*>(hstage);
        __half2* outp = reinterpret_cast<__half2*>(g_h1h);
#pragma unroll
        for (int t = 0; t < TT; t++) {
            unsigned int v = hsu[t * 32 + lane];
            outp[((size_t)t * NN + n) * 32 + lane] = *reinterpret_cast<const __half2*>(&v);
        }
    }
}

// ======================= fused: GCN aggregation + layer2 MMA conv + IN + relu + Tmean + @gcn_w2
#define L2N 8
__global__ void __launch_bounds__(32 * L2N, 3)
k_l2fused(const float* __restrict__ gamma, const float* __restrict__ beta,
          const float* __restrict__ gw) {
    extern __shared__ float sm[];
    float* gms = sm;
    float* bes = gms + 64;
    float* s0s = bes + 64;
    float* s2s = s0s + 64;
    unsigned int* aw = reinterpret_cast<unsigned int*>(s2s + 64);  // [64][100]
    unsigned int* xr = aw + 64 * 100;                              // L2N * 14*36
    float* hbar = reinterpret_cast<float*>(xr + L2N * 14 * 36);

    int tid = threadIdx.x;
    const int NT = 32 * L2N;
    for (int i = tid; i < 64; i += NT) {
        gms[i] = gamma[i]; bes[i] = beta[i]; s0s[i] = g_S0[i]; s2s[i] = g_S2[i];
    }
    const unsigned int* wsrc = reinterpret_cast<const unsigned int*>(g_w2h);
    for (int i = tid; i < 64 * 96; i += NT) {
        int co = i / 96, k2 = i % 96;
        aw[co * 100 + k2] = wsrc[i];
    }
    __syncthreads();   // weights visible; everything below is warp-private

    int local = tid >> 5;
    int lane = tid & 31;
    int gid = lane >> 2;
    int tig = lane & 3;
    int n = blockIdx.x * L2N + local;
    unsigned int* xrow = xr + local * (14 * 36);

    // ---- in-warp GCN aggregation straight into xrow ----
    {
        u64 h = __ldg(&g_hist[n]);
        int cnt = (int)(h >> 40);
        float deg = (float)(h & FIXM) * (1.0f / FIXP);
        float dd2 = 1.0f / (deg + 1.0f);    // dis^2
        const __half2* base = reinterpret_cast<const __half2*>(g_h1h) + lane;
        float a[2 * TT];
#pragma unroll
        for (int i = 0; i < 2 * TT; i++) a[i] = 0.f;
        const int* csr = g_csrc + n * CAP;
        const float* cnm = g_cnorm + n * CAP;
        int sN = 0; float wN = 0.f;
        if (cnt > 0) { sN = __ldg(csr); wN = __ldg(cnm); }
        for (int i = 0; i < cnt; i++) {
            int s = sN; float w = wN;
            if (i + 1 < cnt) { sN = __ldg(csr + i + 1); wN = __ldg(cnm + i + 1); }
            const __half2* p = base + (size_t)s * 32;
#pragma unroll
            for (int t = 0; t < TT; t++) {
                float2 f = __half22float2(__ldg(p + (size_t)t * NN * 32));
                a[2 * t]     += w * f.x;
                a[2 * t + 1] += w * f.y;
            }
        }
        const __half2* pn = base + (size_t)n * 32;
        xrow[0 * 36 + lane] = 0u;
        xrow[13 * 36 + lane] = 0u;
#pragma unroll
        for (int t = 0; t < TT; t++) {
            float2 f = __half22float2(pn[(size_t)t * NN * 32]);
            __half2 v = __floats2half2_rn(a[2 * t] + dd2 * f.x, a[2 * t + 1] + dd2 * f.y);
            xrow[(t + 1) * 36 + lane] = *reinterpret_cast<unsigned int*>(&v);
        }
    }
    __syncwarp();

    float d0[4][4], d1[4][4];
#pragma unroll
    for (int m = 0; m < 4; m++)
#pragma unroll
        for (int r = 0; r < 4; r++) { d0[m][r] = 0.f; d1[m][r] = 0.f; }

#pragma unroll
    for (int kt = 0; kt < 12; kt++) {
        int tap = kt >> 2;
        int l0 = (kt & 3) * 8;
        int tp0 = gid + tap;
        int tp1 = gid + 8 + tap; if (tp1 > 13) tp1 = 13;
        unsigned int b00 = xrow[tp0 * 36 + l0 + tig];
        unsigned int b01 = xrow[tp0 * 36 + l0 + tig + 4];
        unsigned int b10 = xrow[tp1 * 36 + l0 + tig];
        unsigned int b11 = xrow[tp1 * 36 + l0 + tig + 4];
#pragma unroll
        for (int mt = 0; mt < 4; mt++) {
            const unsigned int* ap = aw + (mt * 16 + gid) * 100 + kt * 8 + tig;
            unsigned int a0 = ap[0];
            unsigned int a1 = ap[8 * 100];
            unsigned int a2 = ap[4];
            unsigned int a3 = ap[8 * 100 + 4];
            asm volatile("mma.sync.aligned.m16n8k16.row.col.f32.f16.f16.f32 "
                "{%0,%1,%2,%3}, {%4,%5,%6,%7}, {%8,%9}, {%0,%1,%2,%3};"
                : "+f"(d0[mt][0]), "+f"(d0[mt][1]), "+f"(d0[mt][2]), "+f"(d0[mt][3])
                : "r"(a0), "r"(a1), "r"(a2), "r"(a3), "r"(b00), "r"(b01));
            asm volatile("mma.sync.aligned.m16n8k16.row.col.f32.f16.f16.f32 "
                "{%0,%1,%2,%3}, {%4,%5,%6,%7}, {%8,%9}, {%0,%1,%2,%3};"
                : "+f"(d1[mt][0]), "+f"(d1[mt][1]), "+f"(d1[mt][2]), "+f"(d1[mt][3])
                : "r"(a0), "r"(a1), "r"(a2), "r"(a3), "r"(b10), "r"(b11));
        }
    }

#pragma unroll
    for (int mt = 0; mt < 4; mt++) {
#pragma unroll
        for (int part = 0; part < 2; part++) {
            int co = mt * 16 + gid + part * 8;
            float v0 = part ? d0[mt][2] : d0[mt][0];
            float v1 = part ? d0[mt][3] : d0[mt][1];
            float v2 = part ? d1[mt][2] : d1[mt][0];
            float v3 = part ? d1[mt][3] : d1[mt][1];
            if (tig == 0) v0 -= s0s[co];
            if (tig == 1) v3 -= s2s[co];
            bool val2 = tig < 2;
            float s = v0 + v1 + (val2 ? v2 + v3 : 0.f);
            s += __shfl_xor_sync(0xffffffffu, s, 1);
            s += __shfl_xor_sync(0xffffffffu, s, 2);
            float mu = s * (1.0f / 12.0f);
            float e0 = v0 - mu, e1 = v1 - mu, e2 = v2 - mu, e3 = v3 - mu;
            float q = e0 * e0 + e1 * e1 + (val2 ? e2 * e2 + e3 * e3 : 0.f);
            q += __shfl_xor_sync(0xffffffffu, q, 1);
            q += __shfl_xor_sync(0xffffffffu, q, 2);
            float sc = rsqrtf(q * (1.0f / 12.0f) + 1e-5f) * gms[co];
            float bt = bes[co];
            float r = fmaxf(e0 * sc + bt, 0.f) + fmaxf(e1 * sc + bt, 0.f)
                    + (val2 ? fmaxf(e2 * sc + bt, 0.f) + fmaxf(e3 * sc + bt, 0.f) : 0.f);
            r += __shfl_xor_sync(0xffffffffu, r, 1);
            r += __shfl_xor_sync(0xffffffffu, r, 2);
            if (tig == 0) hbar[local * 64 + co] = r * (1.0f / 12.0f);
        }
    }
    __syncwarp();

    {
        const float4* hl4 = reinterpret_cast<const float4*>(hbar + local * 64);
        const float2* gp = reinterpret_cast<const float2*>(gw) + lane;
        u64 oacc = splat2(0.f);
        for (int c4 = 0; c4 < 16; c4++) {
            float4 hc = hl4[c4];
            int c = c4 * 4;
            float2 g0 = __ldg(gp + (c + 0) * 32);
            float2 g1 = __ldg(gp + (c + 1) * 32);
            float2 g2 = __ldg(gp + (c + 2) * 32);
            float2 g3 = __ldg(gp + (c + 3) * 32);
            fma2(oacc, splat2(hc.x), pack2(g0.x, g0.y));
            fma2(oacc, splat2(hc.y), pack2(g1.x, g1.y));
            fma2(oacc, splat2(hc.z), pack2(g2.x, g2.y));
            fma2(oacc, splat2(hc.w), pack2(g3.x, g3.y));
        }
        float2 o = unpack2(oacc);
        *reinterpret_cast<float2*>(g_xs2 + (size_t)n * 64 + 2 * lane) = o;
    }
}

// ---------------- layer 2 aggregation + output linear + scratch re-zero ----------------
__global__ void k_agg2_out(const float* __restrict__ gb, const float* __restrict__ ow,
                           const float* __restrict__ ob, float* __restrict__ out) {
    __shared__ float ows[64 * 32];
    __shared__ float am[8][64];
    int tid = threadIdx.x;
    for (int i = tid; i < 64 * 32; i += 256) ows[i] = ow[i];
    __syncthreads();
    int wslot = tid >> 5;
    int lane = tid & 31;
    int n = blockIdx.x * 8 + wslot;
    if (n >= NN) return;
    u64 h = __ldg(&g_hist[n]);
    int cnt = (int)(h >> 40);
    float deg = (float)(h & FIXM) * (1.0f / FIXP);
    float d2 = 1.0f / (deg + 1.0f);
    // re-zero scratch for next replay (own node only; after read)
    if (lane == 0) { g_hist[n] = 0ull; g_fill[n] = 0; }
    const int* csr = g_csrc + n * CAP;
    const float* cnm = g_cnorm + n * CAP;
    float a0 = 0.f, a1 = 0.f;
    int sN = 0; float wN = 0.f;
    if (cnt > 0) { sN = __ldg(csr); wN = __ldg(cnm); }
    for (int i = 0; i < cnt; i++) {
        int s = sN; float w = wN;
        if (i + 1 < cnt) { sN = __ldg(csr + i + 1); wN = __ldg(cnm + i + 1); }
        const float* p = g_xs2 + (size_t)s * 64;
        a0 += w * __ldg(p + lane);
        a1 += w * __ldg(p + lane + 32);
    }
    const float* pn = g_xs2 + (size_t)n * 64;
    a0 += d2 * pn[lane] + gb[lane];
    a1 += d2 * pn[lane + 32] + gb[lane + 32];
    am[wslot][lane] = a0;
    am[wslot][lane + 32] = a1;
    __syncwarp();
    float s = ob[lane];
    const float* amr = am[wslot];
#pragma unroll 8
    for (int c = 0; c < 64; c++) s += amr[c] * ows[c * 32 + lane];
    out[(size_t)n * 32 + lane] = s;
}

// ---------------- launch ----------------
extern "C" void kernel_launch(void* const* d_in, const int* in_sizes, int n_in,
                              void* d_out, int out_size) {
    const float* x    = (const float*)d_in[0];
    const int*   ei   = (const int*)d_in[1];
    const float* ew   = (const float*)d_in[2];
    const float* cw1  = (const float*)d_in[3];
    const float* ga1  = (const float*)d_in[5];
    const float* be1  = (const float*)d_in[6];
    const float* gw1  = (const float*)d_in[7];
    const float* gb1  = (const float*)d_in[8];
    const float* cw2  = (const float*)d_in[9];
    const float* ga2  = (const float*)d_in[11];
    const float* be2  = (const float*)d_in[12];
    const float* gw2  = (const float*)d_in[13];
    const float* gb2  = (const float*)d_in[14];
    const float* ow   = (const float*)d_in[15];
    const float* ob   = (const float*)d_in[16];
    float* out = (float*)d_out;

    const int smem1 = (128 + 64 * 52 + 8 * 14 * 20 + 8 * 12 * 32) * 4;   // ~34.3KB
    const int smem2 = (256 + 64 * 100 + L2N * 14 * 36 + L2N * 64) * 4;   // ~44.8KB
    static bool attr_set = false;
    if (!attr_set) {
        cudaFuncSetAttribute(k_l1scat, cudaFuncAttributeMaxDynamicSharedMemorySize, smem1);
        cudaFuncSetAttribute(k_l2fused, cudaFuncAttributeMaxDynamicSharedMemorySize, smem2);
        attr_set = true;
    }

    // 5 launches; k_l2fused at profile slot 4
    k_hist<<<(EE + 255) / 256, 256>>>(ei, ew);
    k_compose<<<41, 256>>>(cw2, gw1, gb1, cw1);
    k_l1scat<<<1250 + 625, 256, smem1>>>(x, ga1, be1, ei, ew);
    k_l2fused<<<(NN + L2N - 1) / L2N, 32 * L2N, smem2>>>(ga2, be2, gw2);
    k_agg2_out<<<(NN + 7) / 8, 256>>>(gb2, ow, ob, out);
}